// round 1
// baseline (speedup 1.0000x reference)
#include <cuda_runtime.h>
#include <math.h>

#define N_TOK 1024
#define DMODEL 2048
#define NH 8
#define NKV 2
#define HDIM 256
#define FFDIM 4096
#define HPL 256
#define NLAYER 7
#define STARTL 8
#define TOTAL_LAYERS 30
#define EPSF 1e-6f

// ---------------- scratch (single device global, no allocation) ----------------
#define SZ_HS     ((size_t)N_TOK * DMODEL)          // 2,097,152
#define SZ_QRAW   ((size_t)N_TOK * NH * HDIM)       // 2,097,152
#define SZ_KRAW   ((size_t)N_TOK * NKV * HDIM)      //   524,288
#define SZ_SCORE  ((size_t)NH * N_TOK * N_TOK)      // 8,388,608
#define SZ_FF     ((size_t)N_TOK * FFDIM)           // 4,194,304
#define SZ_PL     ((size_t)N_TOK * HPL)             //   262,144
#define KVNHD     ((size_t)NKV * N_TOK * HDIM)      //   524,288

#define OFF_HS     ((size_t)0)
#define OFF_H      (OFF_HS + SZ_HS)
#define OFF_QRAW   (OFF_H + SZ_HS)
#define OFF_QT     (OFF_QRAW + SZ_QRAW)
#define OFF_KRAW   (OFF_QT + SZ_QRAW)
#define OFF_VRAW   (OFF_KRAW + SZ_KRAW)
#define OFF_SCORE  (OFF_VRAW + SZ_KRAW)
#define OFF_AO     (OFF_SCORE + SZ_SCORE)
#define OFF_TMP    (OFF_AO + SZ_QRAW)
#define OFF_G      (OFF_TMP + SZ_HS)
#define OFF_U      (OFF_G + SZ_FF)
#define OFF_PLB    (OFF_U + SZ_FF)
#define SCRATCH_TOTAL (OFF_PLB + SZ_PL)

__device__ float g_scratch[SCRATCH_TOTAL];

// ---------------- block reductions (256 threads = 8 warps) ----------------
__device__ __forceinline__ float blockReduceSum256(float v) {
    __shared__ float sh[8];
    __shared__ float res;
    int lane = threadIdx.x & 31;
    int wid = threadIdx.x >> 5;
    #pragma unroll
    for (int o = 16; o > 0; o >>= 1) v += __shfl_xor_sync(0xffffffffu, v, o);
    if (lane == 0) sh[wid] = v;
    __syncthreads();
    if (wid == 0) {
        float x = (lane < 8) ? sh[lane] : 0.f;
        #pragma unroll
        for (int o = 4; o > 0; o >>= 1) x += __shfl_xor_sync(0xffffffffu, x, o);
        if (lane == 0) res = x;
    }
    __syncthreads();
    return res;
}

__device__ __forceinline__ float blockReduceMax256(float v) {
    __shared__ float sh[8];
    __shared__ float res;
    int lane = threadIdx.x & 31;
    int wid = threadIdx.x >> 5;
    #pragma unroll
    for (int o = 16; o > 0; o >>= 1) v = fmaxf(v, __shfl_xor_sync(0xffffffffu, v, o));
    if (lane == 0) sh[wid] = v;
    __syncthreads();
    if (wid == 0) {
        float x = (lane < 8) ? sh[lane] : -INFINITY;
        #pragma unroll
        for (int o = 4; o > 0; o >>= 1) x = fmaxf(x, __shfl_xor_sync(0xffffffffu, x, o));
        if (lane == 0) res = x;
    }
    __syncthreads();
    return res;
}

__device__ __forceinline__ float gelu_tanh(float x) {
    float t = tanhf(0.7978845608028654f * (x + 0.044715f * x * x * x));
    return 0.5f * x * (1.f + t);
}

// ---------------- norms ----------------
// y = x * rsqrt(mean(x^2)+eps) * (1+w)    (one block per row, 256 threads)
__global__ void rmsnorm_kernel(const float* __restrict__ x, const float* __restrict__ w,
                               float* __restrict__ y, int cols) {
    int row = blockIdx.x;
    const float* xr = x + (size_t)row * cols;
    float ss = 0.f;
    for (int c = threadIdx.x; c < cols; c += 256) { float v = xr[c]; ss += v * v; }
    ss = blockReduceSum256(ss);
    float inv = rsqrtf(ss / (float)cols + EPSF);
    float* yr = y + (size_t)row * cols;
    for (int c = threadIdx.x; c < cols; c += 256)
        yr[c] = xr[c] * inv * (1.f + w[c]);
}

// hs = (hs + x * rsqrt(mean(x^2)+eps) * (1+w)) * scale
__global__ void add_rms_kernel(float* __restrict__ hs, const float* __restrict__ x,
                               const float* __restrict__ w,
                               const float* __restrict__ scale_ptr, int cols) {
    int row = blockIdx.x;
    const float* xr = x + (size_t)row * cols;
    float ss = 0.f;
    for (int c = threadIdx.x; c < cols; c += 256) { float v = xr[c]; ss += v * v; }
    ss = blockReduceSum256(ss);
    float inv = rsqrtf(ss / (float)cols + EPSF);
    float sc = scale_ptr ? *scale_ptr : 1.f;
    float* hr = hs + (size_t)row * cols;
    for (int c = threadIdx.x; c < cols; c += 256)
        hr[c] = (hr[c] + xr[c] * inv * (1.f + w[c])) * sc;
}

// ---------------- qk-norm + rope  (grid: (N, nh), block: 256 = HDIM) ----------------
// in : x   (N, nh, HDIM)
// out: y   (nh, N, HDIM)
__global__ void rope_norm_kernel(const float* __restrict__ x, const float* __restrict__ w,
                                 const float* __restrict__ cost, const float* __restrict__ sint,
                                 float* __restrict__ y, int nh) {
    int n = blockIdx.x, h = blockIdx.y, d = threadIdx.x;
    __shared__ float sx[HDIM];
    float v = x[((size_t)n * nh + h) * HDIM + d];
    float ss = blockReduceSum256(v * v);
    float inv = rsqrtf(ss / (float)HDIM + EPSF);
    float xn = v * inv * (1.f + w[d]);
    sx[d] = xn;
    __syncthreads();
    float rh = (d < HDIM / 2) ? -sx[d + HDIM / 2] : sx[d - HDIM / 2];
    y[((size_t)h * N_TOK + n) * HDIM + d] =
        xn * cost[(size_t)n * HDIM + d] + rh * sint[(size_t)n * HDIM + d];
}

// v_norm (no weight): out (nh, N, HDIM)
__global__ void vnorm_kernel(const float* __restrict__ x, float* __restrict__ y, int nh) {
    int n = blockIdx.x, h = blockIdx.y, d = threadIdx.x;
    float v = x[((size_t)n * nh + h) * HDIM + d];
    float ss = blockReduceSum256(v * v);
    y[((size_t)h * N_TOK + n) * HDIM + d] = v * rsqrtf(ss / (float)HDIM + EPSF);
}

// ---------------- softmax over rows of 1024 ----------------
__global__ void softmax_kernel(float* __restrict__ p) {
    float* row = p + (size_t)blockIdx.x * N_TOK;
    int base = threadIdx.x * 4;
    float4 r4 = *reinterpret_cast<float4*>(row + base);
    float v0 = r4.x, v1 = r4.y, v2 = r4.z, v3 = r4.w;
    float m = fmaxf(fmaxf(v0, v1), fmaxf(v2, v3));
    m = blockReduceMax256(m);
    v0 = expf(v0 - m); v1 = expf(v1 - m); v2 = expf(v2 - m); v3 = expf(v3 - m);
    float s = blockReduceSum256(v0 + v1 + v2 + v3);
    float invs = 1.f / s;
    float4 o4; o4.x = v0 * invs; o4.y = v1 * invs; o4.z = v2 * invs; o4.w = v3 * invs;
    *reinterpret_cast<float4*>(row + base) = o4;
}

// ---------------- elementwise ----------------
__global__ void gelu_mul_kernel(float* __restrict__ g, const float* __restrict__ u, int n) {
    int i = blockIdx.x * blockDim.x + threadIdx.x;
    if (i < n) g[i] = gelu_tanh(g[i]) * u[i];
}

__global__ void gelu_sl_kernel(float* __restrict__ g, const float* __restrict__ plc, int li) {
    int i = blockIdx.x * blockDim.x + threadIdx.x;
    if (i < N_TOK * HPL) {
        int n = i >> 8, j = i & 255;
        g[i] = gelu_tanh(g[i]) * plc[(size_t)n * (TOTAL_LAYERS * HPL) + (size_t)li * HPL + j];
    }
}

// ---------------- GEMM: C[bz](rows x M) = A[bz](rows x K) * B[bz>>bshift] ----------------
// BT=true : B is (M, K), K-contiguous (NT gemm: C[r,c] = sum_k A[r,k]*B[c,k])
// BT=false: B is (K, M) with row stride ldb (NN: C[r,c] = sum_k A[r,k]*B[k,c])
// A row stride == K. C element: C[bz*sC + r*ldc + c]. MASK: add maskAdd[r*N_TOK+c].
template <bool BT, bool MASK>
__global__ void __launch_bounds__(256)
gemm_kernel(const float* __restrict__ A, const float* __restrict__ B, float* __restrict__ C,
            int K, int ldb, int ldc,
            long long sA, long long sB, long long sC, int bshift,
            const float* __restrict__ maskAdd) {
    __shared__ float As[8][128];
    __shared__ float Bs[8][132];
    const int tid = threadIdx.x;
    const int bz = blockIdx.z;
    const float* Ab = A + (size_t)bz * sA + (size_t)blockIdx.y * 128 * K;
    const float* Bb = B + (size_t)(bz >> bshift) * sB;
    float* Cb = C + (size_t)bz * sC;

    const int ar = tid >> 1;
    const int ak = (tid & 1) << 2;
    const int bk = tid >> 5;
    const int bc = (tid & 31) << 2;
    const int ty = tid >> 4, tx = tid & 15;

    float acc[8][8];
    #pragma unroll
    for (int i = 0; i < 8; i++)
        #pragma unroll
        for (int j = 0; j < 8; j++) acc[i][j] = 0.f;

    for (int kb = 0; kb < K; kb += 8) {
        float4 a4 = *reinterpret_cast<const float4*>(Ab + (size_t)ar * K + kb + ak);
        As[ak + 0][ar] = a4.x; As[ak + 1][ar] = a4.y;
        As[ak + 2][ar] = a4.z; As[ak + 3][ar] = a4.w;
        if (BT) {
            const float4 b4 = *reinterpret_cast<const float4*>(
                Bb + ((size_t)blockIdx.x * 128 + ar) * K + kb + ak);
            Bs[ak + 0][ar] = b4.x; Bs[ak + 1][ar] = b4.y;
            Bs[ak + 2][ar] = b4.z; Bs[ak + 3][ar] = b4.w;
        } else {
            const float4 b4 = *reinterpret_cast<const float4*>(
                Bb + (size_t)(kb + bk) * ldb + (size_t)blockIdx.x * 128 + bc);
            *reinterpret_cast<float4*>(&Bs[bk][bc]) = b4;
        }
        __syncthreads();
        #pragma unroll
        for (int k = 0; k < 8; k++) {
            float a[8], b[8];
            *reinterpret_cast<float4*>(&a[0]) = *reinterpret_cast<const float4*>(&As[k][ty * 8]);
            *reinterpret_cast<float4*>(&a[4]) = *reinterpret_cast<const float4*>(&As[k][ty * 8 + 4]);
            *reinterpret_cast<float4*>(&b[0]) = *reinterpret_cast<const float4*>(&Bs[k][tx * 8]);
            *reinterpret_cast<float4*>(&b[4]) = *reinterpret_cast<const float4*>(&Bs[k][tx * 8 + 4]);
            #pragma unroll
            for (int i = 0; i < 8; i++)
                #pragma unroll
                for (int j = 0; j < 8; j++) acc[i][j] += a[i] * b[j];
        }
        __syncthreads();
    }

    const int row0 = blockIdx.y * 128 + ty * 8;
    const int col0 = blockIdx.x * 128 + tx * 8;
    #pragma unroll
    for (int i = 0; i < 8; i++) {
        #pragma unroll
        for (int j = 0; j < 8; j++) {
            float v = acc[i][j];
            if (MASK) v += maskAdd[(size_t)(row0 + i) * N_TOK + (col0 + j)];
            Cb[(size_t)(row0 + i) * ldc + col0 + j] = v;
        }
    }
}

// plain NT gemm: C (rows x M) = A (rows x K) @ W(M x K)^T
static inline void launch_gemm_nt(const float* A, const float* W, float* C,
                                  int rows, int M, int K) {
    dim3 grid(M / 128, rows / 128, 1);
    gemm_kernel<true, false><<<grid, 256>>>(A, W, C, K, 0, M, 0, 0, 0, 0, nullptr);
}

// ---------------- driver ----------------
extern "C" void kernel_launch(void* const* d_in, const int* in_sizes, int n_in,
                              void* d_out, int out_size) {
    const float* hidden = (const float*)d_in[0];
    const float* plc    = (const float*)d_in[1];
    const float* mask   = (const float*)d_in[2];
    const float* cos_s  = (const float*)d_in[3];
    const float* sin_s  = (const float*)d_in[4];
    const float* cos_f  = (const float*)d_in[5];
    const float* sin_f  = (const float*)d_in[6];
    const float* Wq     = (const float*)d_in[7];
    const float* Wk     = (const float*)d_in[8];
    const float* Wv     = (const float*)d_in[9];
    const float* Wo     = (const float*)d_in[10];
    const float* Wg     = (const float*)d_in[11];
    const float* Wu     = (const float*)d_in[12];
    const float* Wd     = (const float*)d_in[13];
    const float* Wplg   = (const float*)d_in[14];
    const float* Wplp   = (const float*)d_in[15];
    const float* ln_in  = (const float*)d_in[16];
    const float* ln_pa  = (const float*)d_in[17];
    const float* ln_pf  = (const float*)d_in[18];
    const float* ln_ff  = (const float*)d_in[19];
    const float* ln_pl  = (const float*)d_in[20];
    const float* qn_w   = (const float*)d_in[21];
    const float* kn_w   = (const float*)d_in[22];
    const float* lscale = (const float*)d_in[23];

    float* scratch = nullptr;
    cudaGetSymbolAddress((void**)&scratch, g_scratch);

    float* hs     = scratch + OFF_HS;
    float* hbuf   = scratch + OFF_H;
    float* qraw   = scratch + OFF_QRAW;
    float* qt     = scratch + OFF_QT;
    float* kraw   = scratch + OFF_KRAW;
    float* vraw   = scratch + OFF_VRAW;
    float* scores = scratch + OFF_SCORE;
    float* ao     = scratch + OFF_AO;
    float* tmp    = scratch + OFF_TMP;
    float* gbuf   = scratch + OFF_G;
    float* ubuf   = scratch + OFF_U;
    float* plbuf  = scratch + OFF_PLB;
    float* out    = (float*)d_out;

    cudaMemcpyAsync(hs, hidden, SZ_HS * sizeof(float), cudaMemcpyDeviceToDevice, 0);

    for (int i = 0; i < NLAYER; i++) {
        const int li = STARTL + i;
        const bool full = ((li + 1) % 5) == 0;
        const float* cost = full ? cos_f : cos_s;
        const float* sint = full ? sin_f : sin_s;
        float* Kout = out + SZ_HS + (size_t)i * 2 * KVNHD;
        float* Vout = Kout + KVNHD;

        // pre-attention norm
        rmsnorm_kernel<<<N_TOK, 256>>>(hs, ln_in + (size_t)i * DMODEL, hbuf, DMODEL);

        // qkv projections
        launch_gemm_nt(hbuf, Wq + (size_t)i * NH * HDIM * DMODEL,  qraw, N_TOK, NH * HDIM,  DMODEL);
        launch_gemm_nt(hbuf, Wk + (size_t)i * NKV * HDIM * DMODEL, kraw, N_TOK, NKV * HDIM, DMODEL);
        launch_gemm_nt(hbuf, Wv + (size_t)i * NKV * HDIM * DMODEL, vraw, N_TOK, NKV * HDIM, DMODEL);

        // qk-norm + rope (q -> qt (H,N,HD); k -> d_out K cache (KV,N,HD)); v-norm -> V cache
        rope_norm_kernel<<<dim3(N_TOK, NH),  256>>>(qraw, qn_w + (size_t)i * HDIM, cost, sint, qt,   NH);
        rope_norm_kernel<<<dim3(N_TOK, NKV), 256>>>(kraw, kn_w + (size_t)i * HDIM, cost, sint, Kout, NKV);
        vnorm_kernel    <<<dim3(N_TOK, NKV), 256>>>(vraw, Vout, NKV);

        // attention: scores = q @ K^T + mask (batched over 8 heads, kv = head>>2)
        gemm_kernel<true, true><<<dim3(N_TOK / 128, N_TOK / 128, NH), 256>>>(
            qt, Kout, scores, HDIM, 0, N_TOK,
            (long long)N_TOK * HDIM, (long long)N_TOK * HDIM,
            (long long)N_TOK * N_TOK, 2, mask);
        softmax_kernel<<<NH * N_TOK, 256>>>(scores);
        // ao(n, h*HD+d) = P @ V
        gemm_kernel<false, false><<<dim3(HDIM / 128, N_TOK / 128, NH), 256>>>(
            scores, Vout, ao, N_TOK, HDIM, NH * HDIM,
            (long long)N_TOK * N_TOK, (long long)N_TOK * HDIM,
            (long long)HDIM, 2, nullptr);

        // output projection + post-attn norm + residual
        launch_gemm_nt(ao, Wo + (size_t)i * DMODEL * NH * HDIM, tmp, N_TOK, DMODEL, NH * HDIM);
        add_rms_kernel<<<N_TOK, 256>>>(hs, tmp, ln_pa + (size_t)i * DMODEL, nullptr, DMODEL);

        // MLP
        rmsnorm_kernel<<<N_TOK, 256>>>(hs, ln_pf + (size_t)i * DMODEL, hbuf, DMODEL);
        launch_gemm_nt(hbuf, Wg + (size_t)i * FFDIM * DMODEL, gbuf, N_TOK, FFDIM, DMODEL);
        launch_gemm_nt(hbuf, Wu + (size_t)i * FFDIM * DMODEL, ubuf, N_TOK, FFDIM, DMODEL);
        gelu_mul_kernel<<<(N_TOK * FFDIM + 255) / 256, 256>>>(gbuf, ubuf, N_TOK * FFDIM);
        launch_gemm_nt(gbuf, Wd + (size_t)i * DMODEL * FFDIM, tmp, N_TOK, DMODEL, FFDIM);
        add_rms_kernel<<<N_TOK, 256>>>(hs, tmp, ln_ff + (size_t)i * DMODEL, nullptr, DMODEL);

        // per-layer gating
        launch_gemm_nt(hs, Wplg + (size_t)i * HPL * DMODEL, plbuf, N_TOK, HPL, DMODEL);
        gelu_sl_kernel<<<(N_TOK * HPL + 255) / 256, 256>>>(plbuf, plc, li);
        launch_gemm_nt(plbuf, Wplp + (size_t)i * DMODEL * HPL, tmp, N_TOK, DMODEL, HPL);
        add_rms_kernel<<<N_TOK, 256>>>(hs, tmp, ln_pl + (size_t)i * DMODEL, lscale + i, DMODEL);
    }

    cudaMemcpyAsync(out, hs, SZ_HS * sizeof(float), cudaMemcpyDeviceToDevice, 0);
}

// round 7
// speedup vs baseline: 1.2090x; 1.2090x over previous
#include <cuda_runtime.h>
#include <cuda_bf16.h>
#include <math.h>
#include <stdint.h>

#define N_TOK 1024
#define DMODEL 2048
#define NH 8
#define NKV 2
#define HDIM 256
#define FFDIM 4096
#define HPL 256
#define NLAYER 7
#define STARTL 8
#define TOTAL_LAYERS 30
#define EPSF 1e-6f

typedef __nv_bfloat16 bf16;

// ======================= scratch layout (bytes) =======================
#define E_WG  ((size_t)NLAYER * FFDIM * DMODEL)   // 58,720,256 elements (same for Wu, Wd)

#define OFF_WG3   ((size_t)0)
#define OFF_WU3   (OFF_WG3 + 6 * E_WG)
#define OFF_WD3   (OFF_WU3 + 6 * E_WG)
// fp32 activation buffers (round-1 set)
#define OFF_HS    (OFF_WD3 + 6 * E_WG)
#define OFF_H     (OFF_HS   + 4ull * N_TOK * DMODEL)
#define OFF_QRAW  (OFF_H    + 4ull * N_TOK * DMODEL)
#define OFF_QT    (OFF_QRAW + 4ull * N_TOK * NH * HDIM)
#define OFF_KRAW  (OFF_QT   + 4ull * N_TOK * NH * HDIM)
#define OFF_VRAW  (OFF_KRAW + 4ull * N_TOK * NKV * HDIM)
#define OFF_SC    (OFF_VRAW + 4ull * N_TOK * NKV * HDIM)
#define OFF_AO    (OFF_SC   + 4ull * NH * N_TOK * N_TOK)
#define OFF_TMP   (OFF_AO   + 4ull * N_TOK * NH * HDIM)
#define OFF_G     (OFF_TMP  + 4ull * N_TOK * DMODEL)
#define OFF_U     (OFF_G    + 4ull * N_TOK * FFDIM)
#define OFF_PL    (OFF_U    + 4ull * N_TOK * FFDIM)
// bf16 3-plane split activations (6 bytes per element)
#define OFF_H2    (OFF_PL   + 4ull * N_TOK * HPL)
#define OFF_M2    (OFF_H2   + 6ull * N_TOK * DMODEL)
#define TOTAL_SCR (OFF_M2   + 6ull * N_TOK * FFDIM)

__device__ __align__(1024) char g_scr[TOTAL_SCR];

// ======================= block reductions (round-1, verbatim) =======================
__device__ __forceinline__ float blockReduceSum256(float v) {
    __shared__ float sh[8]; __shared__ float res;
    int lane = threadIdx.x & 31, wid = threadIdx.x >> 5;
    #pragma unroll
    for (int o = 16; o > 0; o >>= 1) v += __shfl_xor_sync(0xffffffffu, v, o);
    if (lane == 0) sh[wid] = v;
    __syncthreads();
    if (wid == 0) {
        float x = (lane < 8) ? sh[lane] : 0.f;
        #pragma unroll
        for (int o = 4; o > 0; o >>= 1) x += __shfl_xor_sync(0xffffffffu, x, o);
        if (lane == 0) res = x;
    }
    __syncthreads();
    return res;
}
__device__ __forceinline__ float blockReduceMax256(float v) {
    __shared__ float sh[8]; __shared__ float res;
    int lane = threadIdx.x & 31, wid = threadIdx.x >> 5;
    #pragma unroll
    for (int o = 16; o > 0; o >>= 1) v = fmaxf(v, __shfl_xor_sync(0xffffffffu, v, o));
    if (lane == 0) sh[wid] = v;
    __syncthreads();
    if (wid == 0) {
        float x = (lane < 8) ? sh[lane] : -INFINITY;
        #pragma unroll
        for (int o = 4; o > 0; o >>= 1) x = fmaxf(x, __shfl_xor_sync(0xffffffffu, x, o));
        if (lane == 0) res = x;
    }
    __syncthreads();
    return res;
}
__device__ __forceinline__ float gelu_tanh(float x) {
    float t = tanhf(0.7978845608028654f * (x + 0.044715f * x * x * x));
    return 0.5f * x * (1.f + t);
}

// ======================= round-1 fp32 kernels (verbatim) =======================
__global__ void rmsnorm_kernel(const float* __restrict__ x, const float* __restrict__ w,
                               float* __restrict__ y, int cols) {
    int row = blockIdx.x;
    const float* xr = x + (size_t)row * cols;
    float ss = 0.f;
    for (int c = threadIdx.x; c < cols; c += 256) { float v = xr[c]; ss += v * v; }
    ss = blockReduceSum256(ss);
    float inv = rsqrtf(ss / (float)cols + EPSF);
    float* yr = y + (size_t)row * cols;
    for (int c = threadIdx.x; c < cols; c += 256)
        yr[c] = xr[c] * inv * (1.f + w[c]);
}

__global__ void add_rms_kernel(float* __restrict__ hs, const float* __restrict__ x,
                               const float* __restrict__ w,
                               const float* __restrict__ scale_ptr, int cols) {
    int row = blockIdx.x;
    const float* xr = x + (size_t)row * cols;
    float ss = 0.f;
    for (int c = threadIdx.x; c < cols; c += 256) { float v = xr[c]; ss += v * v; }
    ss = blockReduceSum256(ss);
    float inv = rsqrtf(ss / (float)cols + EPSF);
    float sc = scale_ptr ? *scale_ptr : 1.f;
    float* hr = hs + (size_t)row * cols;
    for (int c = threadIdx.x; c < cols; c += 256)
        hr[c] = (hr[c] + xr[c] * inv * (1.f + w[c])) * sc;
}

__global__ void rope_norm_kernel(const float* __restrict__ x, const float* __restrict__ w,
                                 const float* __restrict__ cost, const float* __restrict__ sint,
                                 float* __restrict__ y, int nh) {
    int n = blockIdx.x, h = blockIdx.y, d = threadIdx.x;
    __shared__ float sx[HDIM];
    float v = x[((size_t)n * nh + h) * HDIM + d];
    float ss = blockReduceSum256(v * v);
    float inv = rsqrtf(ss / (float)HDIM + EPSF);
    float xn = v * inv * (1.f + w[d]);
    sx[d] = xn;
    __syncthreads();
    float rh = (d < HDIM / 2) ? -sx[d + HDIM / 2] : sx[d - HDIM / 2];
    y[((size_t)h * N_TOK + n) * HDIM + d] =
        xn * cost[(size_t)n * HDIM + d] + rh * sint[(size_t)n * HDIM + d];
}

__global__ void vnorm_kernel(const float* __restrict__ x, float* __restrict__ y, int nh) {
    int n = blockIdx.x, h = blockIdx.y, d = threadIdx.x;
    float v = x[((size_t)n * nh + h) * HDIM + d];
    float ss = blockReduceSum256(v * v);
    y[((size_t)h * N_TOK + n) * HDIM + d] = v * rsqrtf(ss / (float)HDIM + EPSF);
}

__global__ void softmax_kernel(float* __restrict__ p) {
    float* row = p + (size_t)blockIdx.x * N_TOK;
    int base = threadIdx.x * 4;
    float4 r4 = *reinterpret_cast<float4*>(row + base);
    float v0 = r4.x, v1 = r4.y, v2 = r4.z, v3 = r4.w;
    float m = fmaxf(fmaxf(v0, v1), fmaxf(v2, v3));
    m = blockReduceMax256(m);
    v0 = expf(v0 - m); v1 = expf(v1 - m); v2 = expf(v2 - m); v3 = expf(v3 - m);
    float s = blockReduceSum256(v0 + v1 + v2 + v3);
    float invs = 1.f / s;
    float4 o4; o4.x = v0 * invs; o4.y = v1 * invs; o4.z = v2 * invs; o4.w = v3 * invs;
    *reinterpret_cast<float4*>(row + base) = o4;
}

__global__ void gelu_sl_kernel(float* __restrict__ g, const float* __restrict__ plc, int li) {
    int i = blockIdx.x * blockDim.x + threadIdx.x;
    if (i < N_TOK * HPL) {
        int n = i >> 8, j = i & 255;
        g[i] = gelu_tanh(g[i]) * plc[(size_t)n * (TOTAL_LAYERS * HPL) + (size_t)li * HPL + j];
    }
}

// ======================= round-1 SIMT fp32 GEMM (verbatim) =======================
template <bool BT, bool MASK>
__global__ void __launch_bounds__(256)
gemm_kernel(const float* __restrict__ A, const float* __restrict__ B, float* __restrict__ C,
            int K, int ldb, int ldc,
            long long sA, long long sB, long long sC, int bshift,
            const float* __restrict__ maskAdd) {
    __shared__ float As[8][128];
    __shared__ float Bs[8][132];
    const int tid = threadIdx.x;
    const int bz = blockIdx.z;
    const float* Ab = A + (size_t)bz * sA + (size_t)blockIdx.y * 128 * K;
    const float* Bb = B + (size_t)(bz >> bshift) * sB;
    float* Cb = C + (size_t)bz * sC;

    const int ar = tid >> 1;
    const int ak = (tid & 1) << 2;
    const int bk = tid >> 5;
    const int bc = (tid & 31) << 2;
    const int ty = tid >> 4, tx = tid & 15;

    float acc[8][8];
    #pragma unroll
    for (int i = 0; i < 8; i++)
        #pragma unroll
        for (int j = 0; j < 8; j++) acc[i][j] = 0.f;

    for (int kb = 0; kb < K; kb += 8) {
        float4 a4 = *reinterpret_cast<const float4*>(Ab + (size_t)ar * K + kb + ak);
        As[ak + 0][ar] = a4.x; As[ak + 1][ar] = a4.y;
        As[ak + 2][ar] = a4.z; As[ak + 3][ar] = a4.w;
        if (BT) {
            const float4 b4 = *reinterpret_cast<const float4*>(
                Bb + ((size_t)blockIdx.x * 128 + ar) * K + kb + ak);
            Bs[ak + 0][ar] = b4.x; Bs[ak + 1][ar] = b4.y;
            Bs[ak + 2][ar] = b4.z; Bs[ak + 3][ar] = b4.w;
        } else {
            const float4 b4 = *reinterpret_cast<const float4*>(
                Bb + (size_t)(kb + bk) * ldb + (size_t)blockIdx.x * 128 + bc);
            *reinterpret_cast<float4*>(&Bs[bk][bc]) = b4;
        }
        __syncthreads();
        #pragma unroll
        for (int k = 0; k < 8; k++) {
            float a[8], b[8];
            *reinterpret_cast<float4*>(&a[0]) = *reinterpret_cast<const float4*>(&As[k][ty * 8]);
            *reinterpret_cast<float4*>(&a[4]) = *reinterpret_cast<const float4*>(&As[k][ty * 8 + 4]);
            *reinterpret_cast<float4*>(&b[0]) = *reinterpret_cast<const float4*>(&Bs[k][tx * 8]);
            *reinterpret_cast<float4*>(&b[4]) = *reinterpret_cast<const float4*>(&Bs[k][tx * 8 + 4]);
            #pragma unroll
            for (int i = 0; i < 8; i++)
                #pragma unroll
                for (int j = 0; j < 8; j++) acc[i][j] += a[i] * b[j];
        }
        __syncthreads();
    }

    const int row0 = blockIdx.y * 128 + ty * 8;
    const int col0 = blockIdx.x * 128 + tx * 8;
    #pragma unroll
    for (int i = 0; i < 8; i++) {
        #pragma unroll
        for (int j = 0; j < 8; j++) {
            float v = acc[i][j];
            if (MASK) v += maskAdd[(size_t)(row0 + i) * N_TOK + (col0 + j)];
            Cb[(size_t)(row0 + i) * ldc + col0 + j] = v;
        }
    }
}

static inline void launch_gemm_nt(const float* A, const float* W, float* C,
                                  int rows, int M, int K) {
    dim3 grid(M / 128, rows / 128, 1);
    gemm_kernel<true, false><<<grid, 256>>>(A, W, C, K, 0, M, 0, 0, 0, 0, nullptr);
}

// ======================= bf16x3 mma machinery (round-6 core, FFN only) =======================
__device__ __forceinline__ uint32_t smem_u32(const void* p) {
    uint32_t a;
    asm("{ .reg .u64 t; cvta.to.shared.u64 t, %1; cvt.u32.u64 %0, t; }" : "=r"(a) : "l"(p));
    return a;
}
__device__ __forceinline__ void cp16(uint32_t dst, const void* src) {
    asm volatile("cp.async.cg.shared.global [%0], [%1], 16;" :: "r"(dst), "l"(src) : "memory");
}
__device__ __forceinline__ void ldsm4(uint32_t* r, uint32_t addr) {
    asm volatile("ldmatrix.sync.aligned.m8n8.x4.shared.b16 {%0,%1,%2,%3}, [%4];"
                 : "=r"(r[0]), "=r"(r[1]), "=r"(r[2]), "=r"(r[3]) : "r"(addr));
}
__device__ __forceinline__ void mma_bf16(float* d, const uint32_t* a, const uint32_t* b) {
    asm volatile(
        "mma.sync.aligned.m16n8k16.row.col.f32.bf16.bf16.f32 "
        "{%0,%1,%2,%3}, {%4,%5,%6,%7}, {%8,%9}, {%0,%1,%2,%3};"
        : "+f"(d[0]), "+f"(d[1]), "+f"(d[2]), "+f"(d[3])
        : "r"(a[0]), "r"(a[1]), "r"(a[2]), "r"(a[3]), "r"(b[0]), "r"(b[1]));
}
__device__ __forceinline__ void split3(float v, bf16& h, bf16& m, bf16& l) {
    h = __float2bfloat16_rn(v);
    float r = v - __bfloat162float(h);
    m = __float2bfloat16_rn(r);
    l = __float2bfloat16_rn(r - __bfloat162float(m));
}

#define TROWB 80
#define TILE_BYTES (128 * TROWB)
#define STG_BYTES  (6 * TILE_BYTES)
#define GSMEM      (2 * STG_BYTES)

// C(1024 x M) = A(1024 x K) @ B(M x K)^T ; A,B bf16 3-plane (strides eA/eB), fp32 out.
__global__ void __launch_bounds__(256, 1)
mma_gemm(const bf16* __restrict__ A3, const bf16* __restrict__ B3,
         long long eA, long long eB,
         float* __restrict__ Cf, int K, int ldc) {
    extern __shared__ char smem[];
    const uint32_t sb = smem_u32(smem);
    const int tid = threadIdx.x;
    const int row0 = blockIdx.y * 128;
    const int col0 = blockIdx.x * 128;

    const bf16* srcs[6];
    #pragma unroll
    for (int p = 0; p < 3; p++) {
        srcs[p]     = A3 + (size_t)p * eA + (size_t)row0 * K;
        srcs[3 + p] = B3 + (size_t)p * eB + (size_t)col0 * K;
    }

    const int lane = tid & 31, wid = tid >> 5;
    const int wm = wid & 3, wn = wid >> 2;
    const int ld_r = tid >> 2;
    const int ld_c = tid & 3;

    uint32_t aoff[2], boff[4];
    #pragma unroll
    for (int m = 0; m < 2; m++)
        aoff[m] = (uint32_t)((wm * 32 + m * 16 + (lane & 15)) * TROWB + ((lane >> 4) << 4));
    #pragma unroll
    for (int j = 0; j < 4; j++)
        boff[j] = (uint32_t)((wn * 64 + j * 16 + (lane & 7) + ((lane >> 4) << 3)) * TROWB
                             + (((lane >> 3) & 1) << 4));

    float acc[2][8][4];
    #pragma unroll
    for (int m = 0; m < 2; m++)
        #pragma unroll
        for (int t = 0; t < 8; t++)
            #pragma unroll
            for (int u = 0; u < 4; u++) acc[m][t][u] = 0.f;

    const int nch = K >> 5;

    auto issue = [&](int c) {
        const int kb = c << 5;
        const uint32_t dstb = sb + (uint32_t)(c & 1) * STG_BYTES;
        #pragma unroll
        for (int q = 0; q < 12; q++) {
            const int r = (q & 1) * 64 + ld_r;
            const char* gsrc = (const char*)(srcs[q >> 1] + (size_t)r * K + kb) + ld_c * 16;
            cp16(dstb + (uint32_t)((q >> 1) * TILE_BYTES + r * TROWB + ld_c * 16), gsrc);
        }
        asm volatile("cp.async.commit_group;" ::: "memory");
    };

    issue(0);
    if (nch > 1) issue(1);

    for (int c = 0; c < nch; ++c) {
        if (c + 1 < nch) asm volatile("cp.async.wait_group 1;" ::: "memory");
        else             asm volatile("cp.async.wait_group 0;" ::: "memory");
        __syncthreads();

        const uint32_t base = sb + (uint32_t)(c & 1) * STG_BYTES;

        #pragma unroll
        for (int kk = 0; kk < 2; kk++) {
            const uint32_t kb = kk * 32;
            uint32_t ah[2][4], am[2][4], al[2][4];
            #pragma unroll
            for (int m = 0; m < 2; m++) {
                ldsm4(ah[m], base + 0 * TILE_BYTES + aoff[m] + kb);
                ldsm4(am[m], base + 1 * TILE_BYTES + aoff[m] + kb);
                ldsm4(al[m], base + 2 * TILE_BYTES + aoff[m] + kb);
            }
            #pragma unroll
            for (int j = 0; j < 4; j++) {
                uint32_t bh[4], bm[4], bl[4];
                ldsm4(bh, base + 3 * TILE_BYTES + boff[j] + kb);
                ldsm4(bm, base + 4 * TILE_BYTES + boff[j] + kb);
                ldsm4(bl, base + 5 * TILE_BYTES + boff[j] + kb);
                #pragma unroll
                for (int m = 0; m < 2; m++) {
                    #pragma unroll
                    for (int h = 0; h < 2; h++) {
                        float* d = acc[m][j * 2 + h];
                        mma_bf16(d, ah[m], &bh[h * 2]);
                        mma_bf16(d, ah[m], &bm[h * 2]);
                        mma_bf16(d, am[m], &bh[h * 2]);
                        mma_bf16(d, am[m], &bm[h * 2]);
                        mma_bf16(d, ah[m], &bl[h * 2]);
                        mma_bf16(d, al[m], &bh[h * 2]);
                    }
                }
            }
        }
        __syncthreads();
        if (c + 2 < nch) issue(c + 2);
    }

    const int grp = lane >> 2, qd = lane & 3;
    #pragma unroll
    for (int m = 0; m < 2; m++) {
        #pragma unroll
        for (int t = 0; t < 8; t++) {
            const int col = col0 + wn * 64 + t * 8 + qd * 2;
            #pragma unroll
            for (int half = 0; half < 2; half++) {
                const int row = row0 + wm * 32 + m * 16 + grp + half * 8;
                float2 o2;
                o2.x = acc[m][t][half * 2 + 0];
                o2.y = acc[m][t][half * 2 + 1];
                *(float2*)(Cf + (size_t)row * ldc + col) = o2;
            }
        }
    }
}

// ======================= split producers (FFN path only) =======================
__global__ void wsplit_kernel(const float* __restrict__ x, bf16* __restrict__ dst,
                              size_t elts, size_t n4) {
    size_t i = (size_t)blockIdx.x * 256 + threadIdx.x;
    if (i >= n4) return;
    float4 v = ((const float4*)x)[i];
    union { bf16 b[4]; uint2 u2; } H, M, L;
    split3(v.x, H.b[0], M.b[0], L.b[0]); split3(v.y, H.b[1], M.b[1], L.b[1]);
    split3(v.z, H.b[2], M.b[2], L.b[2]); split3(v.w, H.b[3], M.b[3], L.b[3]);
    ((uint2*)dst)[i] = H.u2;
    ((uint2*)(dst + elts))[i] = M.u2;
    ((uint2*)(dst + 2 * elts))[i] = L.u2;
}

__global__ void rmsnorm_split_kernel(const float* __restrict__ x, const float* __restrict__ w,
                                     bf16* __restrict__ dst, size_t elts, int cols) {
    int row = blockIdx.x;
    const float* xr = x + (size_t)row * cols;
    float ss = 0.f;
    for (int c = threadIdx.x; c < cols; c += 256) { float v = xr[c]; ss += v * v; }
    ss = blockReduceSum256(ss);
    float inv = rsqrtf(ss / (float)cols + EPSF);
    for (int c = threadIdx.x; c < cols; c += 256) {
        float y = xr[c] * inv * (1.f + w[c]);
        bf16 h, m, l; split3(y, h, m, l);
        size_t o = (size_t)row * cols + c;
        dst[o] = h; dst[elts + o] = m; dst[2 * elts + o] = l;
    }
}

__global__ void gelu_mul_split_kernel(const float* __restrict__ g, const float* __restrict__ u,
                                      bf16* __restrict__ dst, size_t elts, int n) {
    int i = blockIdx.x * 256 + threadIdx.x;
    if (i < n) {
        float y = gelu_tanh(g[i]) * u[i];
        bf16 h, m, l; split3(y, h, m, l);
        dst[i] = h; dst[elts + i] = m; dst[2 * elts + i] = l;
    }
}

// ======================= driver =======================
extern "C" void kernel_launch(void* const* d_in, const int* in_sizes, int n_in,
                              void* d_out, int out_size) {
    const float* hidden = (const float*)d_in[0];
    const float* plc    = (const float*)d_in[1];
    const float* mask   = (const float*)d_in[2];
    const float* cos_s  = (const float*)d_in[3];
    const float* sin_s  = (const float*)d_in[4];
    const float* cos_f  = (const float*)d_in[5];
    const float* sin_f  = (const float*)d_in[6];
    const float* Wq     = (const float*)d_in[7];
    const float* Wk     = (const float*)d_in[8];
    const float* Wv     = (const float*)d_in[9];
    const float* Wo     = (const float*)d_in[10];
    const float* Wg     = (const float*)d_in[11];
    const float* Wu     = (const float*)d_in[12];
    const float* Wd     = (const float*)d_in[13];
    const float* Wplg   = (const float*)d_in[14];
    const float* Wplp   = (const float*)d_in[15];
    const float* ln_in  = (const float*)d_in[16];
    const float* ln_pa  = (const float*)d_in[17];
    const float* ln_pf  = (const float*)d_in[18];
    const float* ln_ff  = (const float*)d_in[19];
    const float* ln_pl  = (const float*)d_in[20];
    const float* qn_w   = (const float*)d_in[21];
    const float* kn_w   = (const float*)d_in[22];
    const float* lscale = (const float*)d_in[23];

    cudaFuncSetAttribute(mma_gemm, cudaFuncAttributeMaxDynamicSharedMemorySize, GSMEM);

    char* scr = nullptr;
    cudaGetSymbolAddress((void**)&scr, g_scr);

    bf16* wg3 = (bf16*)(scr + OFF_WG3);
    bf16* wu3 = (bf16*)(scr + OFF_WU3);
    bf16* wd3 = (bf16*)(scr + OFF_WD3);

    float* hs     = (float*)(scr + OFF_HS);
    float* hbuf   = (float*)(scr + OFF_H);
    float* qraw   = (float*)(scr + OFF_QRAW);
    float* qt     = (float*)(scr + OFF_QT);
    float* kraw   = (float*)(scr + OFF_KRAW);
    float* vraw   = (float*)(scr + OFF_VRAW);
    float* scores = (float*)(scr + OFF_SC);
    float* ao     = (float*)(scr + OFF_AO);
    float* tmp    = (float*)(scr + OFF_TMP);
    float* gbuf   = (float*)(scr + OFF_G);
    float* ubuf   = (float*)(scr + OFF_U);
    float* plbuf  = (float*)(scr + OFF_PL);
    bf16*  h2     = (bf16*)(scr + OFF_H2);
    bf16*  m2     = (bf16*)(scr + OFF_M2);

    const long long eH2 = (long long)N_TOK * DMODEL;
    const long long eM2 = (long long)N_TOK * FFDIM;
    float* out = (float*)d_out;

    // split FFN weights to bf16 3-plane (once per call)
    {
        size_t n4 = E_WG / 4;
        unsigned nb = (unsigned)((n4 + 255) / 256);
        wsplit_kernel<<<nb, 256>>>(Wg, wg3, E_WG, n4);
        wsplit_kernel<<<nb, 256>>>(Wu, wu3, E_WG, n4);
        wsplit_kernel<<<nb, 256>>>(Wd, wd3, E_WG, n4);
    }

    cudaMemcpyAsync(hs, hidden, (size_t)N_TOK * DMODEL * sizeof(float), cudaMemcpyDeviceToDevice, 0);

    for (int i = 0; i < NLAYER; i++) {
        const int li = STARTL + i;
        const bool full = ((li + 1) % 5) == 0;
        const float* cost = full ? cos_f : cos_s;
        const float* sint = full ? sin_f : sin_s;
        float* Kout = out + (size_t)N_TOK * DMODEL + (size_t)i * 2 * NKV * N_TOK * HDIM;
        float* Vout = Kout + (size_t)NKV * N_TOK * HDIM;

        // ---- attention (round-1 fp32 path, verbatim) ----
        rmsnorm_kernel<<<N_TOK, 256>>>(hs, ln_in + (size_t)i * DMODEL, hbuf, DMODEL);

        launch_gemm_nt(hbuf, Wq + (size_t)i * NH * HDIM * DMODEL,  qraw, N_TOK, NH * HDIM,  DMODEL);
        launch_gemm_nt(hbuf, Wk + (size_t)i * NKV * HDIM * DMODEL, kraw, N_TOK, NKV * HDIM, DMODEL);
        launch_gemm_nt(hbuf, Wv + (size_t)i * NKV * HDIM * DMODEL, vraw, N_TOK, NKV * HDIM, DMODEL);

        rope_norm_kernel<<<dim3(N_TOK, NH),  256>>>(qraw, qn_w + (size_t)i * HDIM, cost, sint, qt,   NH);
        rope_norm_kernel<<<dim3(N_TOK, NKV), 256>>>(kraw, kn_w + (size_t)i * HDIM, cost, sint, Kout, NKV);
        vnorm_kernel    <<<dim3(N_TOK, NKV), 256>>>(vraw, Vout, NKV);

        gemm_kernel<true, true><<<dim3(N_TOK / 128, N_TOK / 128, NH), 256>>>(
            qt, Kout, scores, HDIM, 0, N_TOK,
            (long long)N_TOK * HDIM, (long long)N_TOK * HDIM,
            (long long)N_TOK * N_TOK, 2, mask);
        softmax_kernel<<<NH * N_TOK, 256>>>(scores);
        gemm_kernel<false, false><<<dim3(HDIM / 128, N_TOK / 128, NH), 256>>>(
            scores, Vout, ao, N_TOK, HDIM, NH * HDIM,
            (long long)N_TOK * N_TOK, (long long)N_TOK * HDIM,
            (long long)HDIM, 2, nullptr);

        launch_gemm_nt(ao, Wo + (size_t)i * DMODEL * NH * HDIM, tmp, N_TOK, DMODEL, NH * HDIM);
        add_rms_kernel<<<N_TOK, 256>>>(hs, tmp, ln_pa + (size_t)i * DMODEL, nullptr, DMODEL);

        // ---- FFN (bf16x3 6-term tensor-core path) ----
        const size_t lwg = (size_t)i * FFDIM * DMODEL;
        rmsnorm_split_kernel<<<N_TOK, 256>>>(hs, ln_pf + (size_t)i * DMODEL, h2, eH2, DMODEL);
        mma_gemm<<<dim3(FFDIM / 128, N_TOK / 128), 256, GSMEM>>>(
            h2, wg3 + lwg, eH2, (long long)E_WG, gbuf, DMODEL, FFDIM);
        mma_gemm<<<dim3(FFDIM / 128, N_TOK / 128), 256, GSMEM>>>(
            h2, wu3 + lwg, eH2, (long long)E_WG, ubuf, DMODEL, FFDIM);
        gelu_mul_split_kernel<<<(N_TOK * FFDIM + 255) / 256, 256>>>(gbuf, ubuf, m2, eM2, N_TOK * FFDIM);
        mma_gemm<<<dim3(DMODEL / 128, N_TOK / 128), 256, GSMEM>>>(
            m2, wd3 + lwg, eM2, (long long)E_WG, tmp, FFDIM, DMODEL);
        add_rms_kernel<<<N_TOK, 256>>>(hs, tmp, ln_ff + (size_t)i * DMODEL, nullptr, DMODEL);

        // ---- per-layer gating (round-1 fp32 path, verbatim) ----
        launch_gemm_nt(hs, Wplg + (size_t)i * HPL * DMODEL, plbuf, N_TOK, HPL, DMODEL);
        gelu_sl_kernel<<<(N_TOK * HPL + 255) / 256, 256>>>(plbuf, plc, li);
        launch_gemm_nt(plbuf, Wplp + (size_t)i * DMODEL * HPL, tmp, N_TOK, DMODEL, HPL);
        add_rms_kernel<<<N_TOK, 256>>>(hs, tmp, ln_pl + (size_t)i * DMODEL, lscale + i, DMODEL);
    }

    cudaMemcpyAsync(out, hs, (size_t)N_TOK * DMODEL * sizeof(float), cudaMemcpyDeviceToDevice, 0);
}

// round 8
// speedup vs baseline: 1.7146x; 1.4182x over previous
#include <cuda_runtime.h>
#include <cuda_bf16.h>
#include <math.h>
#include <stdint.h>

#define N_TOK 1024
#define DMODEL 2048
#define NH 8
#define NKV 2
#define HDIM 256
#define FFDIM 4096
#define HPL 256
#define NLAYER 7
#define STARTL 8
#define TOTAL_LAYERS 30
#define EPSF 1e-6f

typedef __nv_bfloat16 bf16;

// ======================= scratch layout (bytes) =======================
#define E_WQ  ((size_t)NLAYER * NH * HDIM * DMODEL)    // 29,360,128
#define E_WK  ((size_t)NLAYER * NKV * HDIM * DMODEL)   //  7,340,032
#define E_WO  E_WQ
#define E_WG  ((size_t)NLAYER * FFDIM * DMODEL)        // 58,720,256
#define E_WPL ((size_t)NLAYER * HPL * DMODEL)          //  3,670,016

#define OFF_WQ3   ((size_t)0)
#define OFF_WK3   (OFF_WQ3 + 6 * E_WQ)
#define OFF_WV3   (OFF_WK3 + 6 * E_WK)
#define OFF_WO3   (OFF_WV3 + 6 * E_WK)
#define OFF_WG3   (OFF_WO3 + 6 * E_WO)
#define OFF_WU3   (OFF_WG3 + 6 * E_WG)
#define OFF_WD3   (OFF_WU3 + 6 * E_WG)
#define OFF_WPLG3 (OFF_WD3 + 6 * E_WG)
#define OFF_WPLP3 (OFF_WPLG3 + 6 * E_WPL)
// fp32 activation buffers
#define OFF_HS    (OFF_WPLP3 + 6 * E_WPL)
#define OFF_QRAW  (OFF_HS   + 4ull * N_TOK * DMODEL)
#define OFF_QT    (OFF_QRAW + 4ull * N_TOK * NH * HDIM)
#define OFF_KRAW  (OFF_QT   + 4ull * N_TOK * NH * HDIM)
#define OFF_VRAW  (OFF_KRAW + 4ull * N_TOK * NKV * HDIM)
#define OFF_SC    (OFF_VRAW + 4ull * N_TOK * NKV * HDIM)
#define OFF_AO    (OFF_SC   + 4ull * NH * N_TOK * N_TOK)
#define OFF_TMP   (OFF_AO   + 4ull * N_TOK * NH * HDIM)
#define OFF_G     (OFF_TMP  + 4ull * N_TOK * DMODEL)
#define OFF_U     (OFF_G    + 4ull * N_TOK * FFDIM)
#define OFF_PL    (OFF_U    + 4ull * N_TOK * FFDIM)
// bf16 3-plane split activations (6 bytes per element)
#define OFF_H2    (OFF_PL   + 4ull * N_TOK * HPL)
#define OFF_AO3   (OFF_H2   + 6ull * N_TOK * DMODEL)
#define OFF_M2    (OFF_AO3  + 6ull * N_TOK * NH * HDIM)
#define OFF_HS3   (OFF_M2   + 6ull * N_TOK * FFDIM)
#define OFF_PL3   (OFF_HS3  + 6ull * N_TOK * DMODEL)
#define TOTAL_SCR (OFF_PL3  + 6ull * N_TOK * HPL)

__device__ __align__(1024) char g_scr[TOTAL_SCR];

// ======================= block reductions =======================
__device__ __forceinline__ float blockReduceSum256(float v) {
    __shared__ float sh[8]; __shared__ float res;
    int lane = threadIdx.x & 31, wid = threadIdx.x >> 5;
    #pragma unroll
    for (int o = 16; o > 0; o >>= 1) v += __shfl_xor_sync(0xffffffffu, v, o);
    if (lane == 0) sh[wid] = v;
    __syncthreads();
    if (wid == 0) {
        float x = (lane < 8) ? sh[lane] : 0.f;
        #pragma unroll
        for (int o = 4; o > 0; o >>= 1) x += __shfl_xor_sync(0xffffffffu, x, o);
        if (lane == 0) res = x;
    }
    __syncthreads();
    return res;
}
__device__ __forceinline__ float blockReduceMax256(float v) {
    __shared__ float sh[8]; __shared__ float res;
    int lane = threadIdx.x & 31, wid = threadIdx.x >> 5;
    #pragma unroll
    for (int o = 16; o > 0; o >>= 1) v = fmaxf(v, __shfl_xor_sync(0xffffffffu, v, o));
    if (lane == 0) sh[wid] = v;
    __syncthreads();
    if (wid == 0) {
        float x = (lane < 8) ? sh[lane] : -INFINITY;
        #pragma unroll
        for (int o = 4; o > 0; o >>= 1) x = fmaxf(x, __shfl_xor_sync(0xffffffffu, x, o));
        if (lane == 0) res = x;
    }
    __syncthreads();
    return res;
}
__device__ __forceinline__ float gelu_tanh(float x) {
    float t = tanhf(0.7978845608028654f * (x + 0.044715f * x * x * x));
    return 0.5f * x * (1.f + t);
}

// ======================= fp32 elementwise / norm kernels =======================
__global__ void add_rms_kernel(float* __restrict__ hs, const float* __restrict__ x,
                               const float* __restrict__ w,
                               const float* __restrict__ scale_ptr,
                               bf16* __restrict__ dst, size_t elts, int cols) {
    int row = blockIdx.x;
    const float* xr = x + (size_t)row * cols;
    float ss = 0.f;
    for (int c = threadIdx.x; c < cols; c += 256) { float v = xr[c]; ss += v * v; }
    ss = blockReduceSum256(ss);
    float inv = rsqrtf(ss / (float)cols + EPSF);
    float sc = scale_ptr ? *scale_ptr : 1.f;
    float* hr = hs + (size_t)row * cols;
    for (int c = threadIdx.x; c < cols; c += 256) {
        float y = (hr[c] + xr[c] * inv * (1.f + w[c])) * sc;
        hr[c] = y;
        if (dst) {
            bf16 h = __float2bfloat16_rn(y);
            float r = y - __bfloat162float(h);
            bf16 m = __float2bfloat16_rn(r);
            bf16 l = __float2bfloat16_rn(r - __bfloat162float(m));
            size_t o = (size_t)row * cols + c;
            dst[o] = h; dst[elts + o] = m; dst[2 * elts + o] = l;
        }
    }
}

__global__ void rope_norm_kernel(const float* __restrict__ x, const float* __restrict__ w,
                                 const float* __restrict__ cost, const float* __restrict__ sint,
                                 float* __restrict__ y, int nh) {
    int n = blockIdx.x, h = blockIdx.y, d = threadIdx.x;
    __shared__ float sx[HDIM];
    float v = x[((size_t)n * nh + h) * HDIM + d];
    float ss = blockReduceSum256(v * v);
    float inv = rsqrtf(ss / (float)HDIM + EPSF);
    float xn = v * inv * (1.f + w[d]);
    sx[d] = xn;
    __syncthreads();
    float rh = (d < HDIM / 2) ? -sx[d + HDIM / 2] : sx[d - HDIM / 2];
    y[((size_t)h * N_TOK + n) * HDIM + d] =
        xn * cost[(size_t)n * HDIM + d] + rh * sint[(size_t)n * HDIM + d];
}

__global__ void vnorm_kernel(const float* __restrict__ x, float* __restrict__ y, int nh) {
    int n = blockIdx.x, h = blockIdx.y, d = threadIdx.x;
    float v = x[((size_t)n * nh + h) * HDIM + d];
    float ss = blockReduceSum256(v * v);
    y[((size_t)h * N_TOK + n) * HDIM + d] = v * rsqrtf(ss / (float)HDIM + EPSF);
}

__global__ void softmax_kernel(float* __restrict__ p) {
    float* row = p + (size_t)blockIdx.x * N_TOK;
    int base = threadIdx.x * 4;
    float4 r4 = *reinterpret_cast<float4*>(row + base);
    float v0 = r4.x, v1 = r4.y, v2 = r4.z, v3 = r4.w;
    float m = fmaxf(fmaxf(v0, v1), fmaxf(v2, v3));
    m = blockReduceMax256(m);
    v0 = expf(v0 - m); v1 = expf(v1 - m); v2 = expf(v2 - m); v3 = expf(v3 - m);
    float s = blockReduceSum256(v0 + v1 + v2 + v3);
    float invs = 1.f / s;
    float4 o4; o4.x = v0 * invs; o4.y = v1 * invs; o4.z = v2 * invs; o4.w = v3 * invs;
    *reinterpret_cast<float4*>(row + base) = o4;
}

// ======================= SIMT fp32 GEMM (attention only, verbatim round-1) =======================
template <bool BT, bool MASK>
__global__ void __launch_bounds__(256)
gemm_kernel(const float* __restrict__ A, const float* __restrict__ B, float* __restrict__ C,
            int K, int ldb, int ldc,
            long long sA, long long sB, long long sC, int bshift,
            const float* __restrict__ maskAdd) {
    __shared__ float As[8][128];
    __shared__ float Bs[8][132];
    const int tid = threadIdx.x;
    const int bz = blockIdx.z;
    const float* Ab = A + (size_t)bz * sA + (size_t)blockIdx.y * 128 * K;
    const float* Bb = B + (size_t)(bz >> bshift) * sB;
    float* Cb = C + (size_t)bz * sC;

    const int ar = tid >> 1;
    const int ak = (tid & 1) << 2;
    const int bk = tid >> 5;
    const int bc = (tid & 31) << 2;
    const int ty = tid >> 4, tx = tid & 15;

    float acc[8][8];
    #pragma unroll
    for (int i = 0; i < 8; i++)
        #pragma unroll
        for (int j = 0; j < 8; j++) acc[i][j] = 0.f;

    for (int kb = 0; kb < K; kb += 8) {
        float4 a4 = *reinterpret_cast<const float4*>(Ab + (size_t)ar * K + kb + ak);
        As[ak + 0][ar] = a4.x; As[ak + 1][ar] = a4.y;
        As[ak + 2][ar] = a4.z; As[ak + 3][ar] = a4.w;
        if (BT) {
            const float4 b4 = *reinterpret_cast<const float4*>(
                Bb + ((size_t)blockIdx.x * 128 + ar) * K + kb + ak);
            Bs[ak + 0][ar] = b4.x; Bs[ak + 1][ar] = b4.y;
            Bs[ak + 2][ar] = b4.z; Bs[ak + 3][ar] = b4.w;
        } else {
            const float4 b4 = *reinterpret_cast<const float4*>(
                Bb + (size_t)(kb + bk) * ldb + (size_t)blockIdx.x * 128 + bc);
            *reinterpret_cast<float4*>(&Bs[bk][bc]) = b4;
        }
        __syncthreads();
        #pragma unroll
        for (int k = 0; k < 8; k++) {
            float a[8], b[8];
            *reinterpret_cast<float4*>(&a[0]) = *reinterpret_cast<const float4*>(&As[k][ty * 8]);
            *reinterpret_cast<float4*>(&a[4]) = *reinterpret_cast<const float4*>(&As[k][ty * 8 + 4]);
            *reinterpret_cast<float4*>(&b[0]) = *reinterpret_cast<const float4*>(&Bs[k][tx * 8]);
            *reinterpret_cast<float4*>(&b[4]) = *reinterpret_cast<const float4*>(&Bs[k][tx * 8 + 4]);
            #pragma unroll
            for (int i = 0; i < 8; i++)
                #pragma unroll
                for (int j = 0; j < 8; j++) acc[i][j] += a[i] * b[j];
        }
        __syncthreads();
    }

    const int row0 = blockIdx.y * 128 + ty * 8;
    const int col0 = blockIdx.x * 128 + tx * 8;
    #pragma unroll
    for (int i = 0; i < 8; i++) {
        #pragma unroll
        for (int j = 0; j < 8; j++) {
            float v = acc[i][j];
            if (MASK) v += maskAdd[(size_t)(row0 + i) * N_TOK + (col0 + j)];
            Cb[(size_t)(row0 + i) * ldc + col0 + j] = v;
        }
    }
}

// ======================= bf16x3 mma machinery =======================
__device__ __forceinline__ uint32_t smem_u32(const void* p) {
    uint32_t a;
    asm("{ .reg .u64 t; cvta.to.shared.u64 t, %1; cvt.u32.u64 %0, t; }" : "=r"(a) : "l"(p));
    return a;
}
__device__ __forceinline__ void cp16(uint32_t dst, const void* src) {
    asm volatile("cp.async.cg.shared.global [%0], [%1], 16;" :: "r"(dst), "l"(src) : "memory");
}
__device__ __forceinline__ void ldsm4(uint32_t* r, uint32_t addr) {
    asm volatile("ldmatrix.sync.aligned.m8n8.x4.shared.b16 {%0,%1,%2,%3}, [%4];"
                 : "=r"(r[0]), "=r"(r[1]), "=r"(r[2]), "=r"(r[3]) : "r"(addr));
}
__device__ __forceinline__ void mma_bf16(float* d, const uint32_t* a, const uint32_t* b) {
    asm volatile(
        "mma.sync.aligned.m16n8k16.row.col.f32.bf16.bf16.f32 "
        "{%0,%1,%2,%3}, {%4,%5,%6,%7}, {%8,%9}, {%0,%1,%2,%3};"
        : "+f"(d[0]), "+f"(d[1]), "+f"(d[2]), "+f"(d[3])
        : "r"(a[0]), "r"(a[1]), "r"(a[2]), "r"(a[3]), "r"(b[0]), "r"(b[1]));
}
__device__ __forceinline__ void split3(float v, bf16& h, bf16& m, bf16& l) {
    h = __float2bfloat16_rn(v);
    float r = v - __bfloat162float(h);
    m = __float2bfloat16_rn(r);
    l = __float2bfloat16_rn(r - __bfloat162float(m));
}

#define TROWB 80
#define TILE_BYTES (128 * TROWB)
#define STG_BYTES  (6 * TILE_BYTES)
#define GSMEM      (2 * STG_BYTES)

// C(1024 x M) = A(1024 x K) @ B(M x K)^T ; A,B bf16 3-plane (strides eA/eB), fp32 out.
// Dual accumulators: hh term into accM (fp32-gemm-like add count); the 5 smaller
// correction terms into accC; merged at epilogue. Error ~= plain fp32 GEMM.
__global__ void __launch_bounds__(256, 1)
mma_gemm(const bf16* __restrict__ A3, const bf16* __restrict__ B3,
         long long eA, long long eB,
         float* __restrict__ Cf, int K, int ldc) {
    extern __shared__ char smem[];
    const uint32_t sb = smem_u32(smem);
    const int tid = threadIdx.x;
    const int row0 = blockIdx.y * 128;
    const int col0 = blockIdx.x * 128;

    const bf16* srcs[6];
    #pragma unroll
    for (int p = 0; p < 3; p++) {
        srcs[p]     = A3 + (size_t)p * eA + (size_t)row0 * K;
        srcs[3 + p] = B3 + (size_t)p * eB + (size_t)col0 * K;
    }

    const int lane = tid & 31, wid = tid >> 5;
    const int wm = wid & 3, wn = wid >> 2;
    const int ld_r = tid >> 2;
    const int ld_c = tid & 3;

    uint32_t aoff[2], boff[4];
    #pragma unroll
    for (int m = 0; m < 2; m++)
        aoff[m] = (uint32_t)((wm * 32 + m * 16 + (lane & 15)) * TROWB + ((lane >> 4) << 4));
    #pragma unroll
    for (int j = 0; j < 4; j++)
        boff[j] = (uint32_t)((wn * 64 + j * 16 + (lane & 7) + ((lane >> 4) << 3)) * TROWB
                             + (((lane >> 3) & 1) << 4));

    float accM[2][8][4], accC[2][8][4];
    #pragma unroll
    for (int m = 0; m < 2; m++)
        #pragma unroll
        for (int t = 0; t < 8; t++)
            #pragma unroll
            for (int u = 0; u < 4; u++) { accM[m][t][u] = 0.f; accC[m][t][u] = 0.f; }

    const int nch = K >> 5;

    auto issue = [&](int c) {
        const int kb = c << 5;
        const uint32_t dstb = sb + (uint32_t)(c & 1) * STG_BYTES;
        #pragma unroll
        for (int q = 0; q < 12; q++) {
            const int r = (q & 1) * 64 + ld_r;
            const char* gsrc = (const char*)(srcs[q >> 1] + (size_t)r * K + kb) + ld_c * 16;
            cp16(dstb + (uint32_t)((q >> 1) * TILE_BYTES + r * TROWB + ld_c * 16), gsrc);
        }
        asm volatile("cp.async.commit_group;" ::: "memory");
    };

    issue(0);
    if (nch > 1) issue(1);

    for (int c = 0; c < nch; ++c) {
        if (c + 1 < nch) asm volatile("cp.async.wait_group 1;" ::: "memory");
        else             asm volatile("cp.async.wait_group 0;" ::: "memory");
        __syncthreads();

        const uint32_t base = sb + (uint32_t)(c & 1) * STG_BYTES;

        #pragma unroll
        for (int kk = 0; kk < 2; kk++) {
            const uint32_t kb = kk * 32;
            uint32_t ah[2][4], am[2][4], al[2][4];
            #pragma unroll
            for (int m = 0; m < 2; m++) {
                ldsm4(ah[m], base + 0 * TILE_BYTES + aoff[m] + kb);
                ldsm4(am[m], base + 1 * TILE_BYTES + aoff[m] + kb);
                ldsm4(al[m], base + 2 * TILE_BYTES + aoff[m] + kb);
            }
            #pragma unroll
            for (int j = 0; j < 4; j++) {
                uint32_t bh[4], bm[4], bl[4];
                ldsm4(bh, base + 3 * TILE_BYTES + boff[j] + kb);
                ldsm4(bm, base + 4 * TILE_BYTES + boff[j] + kb);
                ldsm4(bl, base + 5 * TILE_BYTES + boff[j] + kb);
                #pragma unroll
                for (int m = 0; m < 2; m++) {
                    #pragma unroll
                    for (int h = 0; h < 2; h++) {
                        float* dM = accM[m][j * 2 + h];
                        float* dC = accC[m][j * 2 + h];
                        mma_bf16(dM, ah[m], &bh[h * 2]);   // hh -> main
                        mma_bf16(dC, ah[m], &bm[h * 2]);   // corrections -> corr
                        mma_bf16(dC, am[m], &bh[h * 2]);
                        mma_bf16(dC, am[m], &bm[h * 2]);
                        mma_bf16(dC, ah[m], &bl[h * 2]);
                        mma_bf16(dC, al[m], &bh[h * 2]);
                    }
                }
            }
        }
        __syncthreads();
        if (c + 2 < nch) issue(c + 2);
    }

    const int grp = lane >> 2, qd = lane & 3;
    #pragma unroll
    for (int m = 0; m < 2; m++) {
        #pragma unroll
        for (int t = 0; t < 8; t++) {
            const int col = col0 + wn * 64 + t * 8 + qd * 2;
            #pragma unroll
            for (int half = 0; half < 2; half++) {
                const int row = row0 + wm * 32 + m * 16 + grp + half * 8;
                float2 o2;
                o2.x = accM[m][t][half * 2 + 0] + accC[m][t][half * 2 + 0];
                o2.y = accM[m][t][half * 2 + 1] + accC[m][t][half * 2 + 1];
                *(float2*)(Cf + (size_t)row * ldc + col) = o2;
            }
        }
    }
}

// ======================= split producers =======================
// generic fp32 -> 3-plane bf16 (used for weights AND for ao)
__global__ void wsplit_kernel(const float* __restrict__ x, bf16* __restrict__ dst,
                              size_t elts, size_t n4) {
    size_t i = (size_t)blockIdx.x * 256 + threadIdx.x;
    if (i >= n4) return;
    float4 v = ((const float4*)x)[i];
    union { bf16 b[4]; uint2 u2; } H, M, L;
    split3(v.x, H.b[0], M.b[0], L.b[0]); split3(v.y, H.b[1], M.b[1], L.b[1]);
    split3(v.z, H.b[2], M.b[2], L.b[2]); split3(v.w, H.b[3], M.b[3], L.b[3]);
    ((uint2*)dst)[i] = H.u2;
    ((uint2*)(dst + elts))[i] = M.u2;
    ((uint2*)(dst + 2 * elts))[i] = L.u2;
}

__global__ void rmsnorm_split_kernel(const float* __restrict__ x, const float* __restrict__ w,
                                     bf16* __restrict__ dst, size_t elts, int cols) {
    int row = blockIdx.x;
    const float* xr = x + (size_t)row * cols;
    float ss = 0.f;
    for (int c = threadIdx.x; c < cols; c += 256) { float v = xr[c]; ss += v * v; }
    ss = blockReduceSum256(ss);
    float inv = rsqrtf(ss / (float)cols + EPSF);
    for (int c = threadIdx.x; c < cols; c += 256) {
        float y = xr[c] * inv * (1.f + w[c]);
        bf16 h, m, l; split3(y, h, m, l);
        size_t o = (size_t)row * cols + c;
        dst[o] = h; dst[elts + o] = m; dst[2 * elts + o] = l;
    }
}

__global__ void gelu_mul_split_kernel(const float* __restrict__ g, const float* __restrict__ u,
                                      bf16* __restrict__ dst, size_t elts, int n) {
    int i = blockIdx.x * 256 + threadIdx.x;
    if (i < n) {
        float y = gelu_tanh(g[i]) * u[i];
        bf16 h, m, l; split3(y, h, m, l);
        dst[i] = h; dst[elts + i] = m; dst[2 * elts + i] = l;
    }
}

__global__ void gelu_sl_split_kernel(const float* __restrict__ g, const float* __restrict__ plc,
                                     int li, bf16* __restrict__ dst, size_t elts) {
    int i = blockIdx.x * 256 + threadIdx.x;
    if (i < N_TOK * HPL) {
        int n = i >> 8, j = i & 255;
        float y = gelu_tanh(g[i]) * plc[(size_t)n * (TOTAL_LAYERS * HPL) + (size_t)li * HPL + j];
        bf16 h, m, l; split3(y, h, m, l);
        dst[i] = h; dst[elts + i] = m; dst[2 * elts + i] = l;
    }
}

// ======================= driver =======================
extern "C" void kernel_launch(void* const* d_in, const int* in_sizes, int n_in,
                              void* d_out, int out_size) {
    const float* hidden = (const float*)d_in[0];
    const float* plc    = (const float*)d_in[1];
    const float* mask   = (const float*)d_in[2];
    const float* cos_s  = (const float*)d_in[3];
    const float* sin_s  = (const float*)d_in[4];
    const float* cos_f  = (const float*)d_in[5];
    const float* sin_f  = (const float*)d_in[6];
    const float* Wq     = (const float*)d_in[7];
    const float* Wk     = (const float*)d_in[8];
    const float* Wv     = (const float*)d_in[9];
    const float* Wo     = (const float*)d_in[10];
    const float* Wg     = (const float*)d_in[11];
    const float* Wu     = (const float*)d_in[12];
    const float* Wd     = (const float*)d_in[13];
    const float* Wplg   = (const float*)d_in[14];
    const float* Wplp   = (const float*)d_in[15];
    const float* ln_in  = (const float*)d_in[16];
    const float* ln_pa  = (const float*)d_in[17];
    const float* ln_pf  = (const float*)d_in[18];
    const float* ln_ff  = (const float*)d_in[19];
    const float* ln_pl  = (const float*)d_in[20];
    const float* qn_w   = (const float*)d_in[21];
    const float* kn_w   = (const float*)d_in[22];
    const float* lscale = (const float*)d_in[23];

    cudaFuncSetAttribute(mma_gemm, cudaFuncAttributeMaxDynamicSharedMemorySize, GSMEM);

    char* scr = nullptr;
    cudaGetSymbolAddress((void**)&scr, g_scr);

    bf16* wq3   = (bf16*)(scr + OFF_WQ3);
    bf16* wk3   = (bf16*)(scr + OFF_WK3);
    bf16* wv3   = (bf16*)(scr + OFF_WV3);
    bf16* wo3   = (bf16*)(scr + OFF_WO3);
    bf16* wg3   = (bf16*)(scr + OFF_WG3);
    bf16* wu3   = (bf16*)(scr + OFF_WU3);
    bf16* wd3   = (bf16*)(scr + OFF_WD3);
    bf16* wplg3 = (bf16*)(scr + OFF_WPLG3);
    bf16* wplp3 = (bf16*)(scr + OFF_WPLP3);

    float* hs     = (float*)(scr + OFF_HS);
    float* qraw   = (float*)(scr + OFF_QRAW);
    float* qt     = (float*)(scr + OFF_QT);
    float* kraw   = (float*)(scr + OFF_KRAW);
    float* vraw   = (float*)(scr + OFF_VRAW);
    float* scores = (float*)(scr + OFF_SC);
    float* ao     = (float*)(scr + OFF_AO);
    float* tmp    = (float*)(scr + OFF_TMP);
    float* gbuf   = (float*)(scr + OFF_G);
    float* ubuf   = (float*)(scr + OFF_U);
    float* plbuf  = (float*)(scr + OFF_PL);
    bf16*  h2     = (bf16*)(scr + OFF_H2);
    bf16*  ao3    = (bf16*)(scr + OFF_AO3);
    bf16*  m2     = (bf16*)(scr + OFF_M2);
    bf16*  hs3    = (bf16*)(scr + OFF_HS3);
    bf16*  pl3    = (bf16*)(scr + OFF_PL3);

    const long long eH2 = (long long)N_TOK * DMODEL;
    const long long eAO = (long long)N_TOK * NH * HDIM;
    const long long eM2 = (long long)N_TOK * FFDIM;
    const long long ePL = (long long)N_TOK * HPL;
    float* out = (float*)d_out;

    // split ALL weights to bf16 3-plane (once per call)
    auto wsplit = [&](const float* w, bf16* dst, size_t elts) {
        size_t n4 = elts / 4;
        wsplit_kernel<<<(unsigned)((n4 + 255) / 256), 256>>>(w, dst, elts, n4);
    };
    wsplit(Wq, wq3, E_WQ);       wsplit(Wk, wk3, E_WK);     wsplit(Wv, wv3, E_WK);
    wsplit(Wo, wo3, E_WO);       wsplit(Wg, wg3, E_WG);     wsplit(Wu, wu3, E_WG);
    wsplit(Wd, wd3, E_WG);       wsplit(Wplg, wplg3, E_WPL); wsplit(Wplp, wplp3, E_WPL);

    cudaMemcpyAsync(hs, hidden, (size_t)N_TOK * DMODEL * sizeof(float), cudaMemcpyDeviceToDevice, 0);

    for (int i = 0; i < NLAYER; i++) {
        const int li = STARTL + i;
        const bool full = ((li + 1) % 5) == 0;
        const float* cost = full ? cos_f : cos_s;
        const float* sint = full ? sin_f : sin_s;
        float* Kout = out + (size_t)N_TOK * DMODEL + (size_t)i * 2 * NKV * N_TOK * HDIM;
        float* Vout = Kout + (size_t)NKV * N_TOK * HDIM;

        const size_t lwq = (size_t)i * NH * HDIM * DMODEL;
        const size_t lwk = (size_t)i * NKV * HDIM * DMODEL;
        const size_t lwg = (size_t)i * FFDIM * DMODEL;
        const size_t lpl = (size_t)i * HPL * DMODEL;

        // ---- pre-attention norm + QKV (mma) ----
        rmsnorm_split_kernel<<<N_TOK, 256>>>(hs, ln_in + (size_t)i * DMODEL, h2, eH2, DMODEL);
        mma_gemm<<<dim3((NH * HDIM) / 128, 8), 256, GSMEM>>>(
            h2, wq3 + lwq, eH2, (long long)E_WQ, qraw, DMODEL, NH * HDIM);
        mma_gemm<<<dim3((NKV * HDIM) / 128, 8), 256, GSMEM>>>(
            h2, wk3 + lwk, eH2, (long long)E_WK, kraw, DMODEL, NKV * HDIM);
        mma_gemm<<<dim3((NKV * HDIM) / 128, 8), 256, GSMEM>>>(
            h2, wv3 + lwk, eH2, (long long)E_WK, vraw, DMODEL, NKV * HDIM);

        rope_norm_kernel<<<dim3(N_TOK, NH),  256>>>(qraw, qn_w + (size_t)i * HDIM, cost, sint, qt,   NH);
        rope_norm_kernel<<<dim3(N_TOK, NKV), 256>>>(kraw, kn_w + (size_t)i * HDIM, cost, sint, Kout, NKV);
        vnorm_kernel    <<<dim3(N_TOK, NKV), 256>>>(vraw, Vout, NKV);

        // ---- attention core (fp32 SIMT, verified) ----
        gemm_kernel<true, true><<<dim3(N_TOK / 128, N_TOK / 128, NH), 256>>>(
            qt, Kout, scores, HDIM, 0, N_TOK,
            (long long)N_TOK * HDIM, (long long)N_TOK * HDIM,
            (long long)N_TOK * N_TOK, 2, mask);
        softmax_kernel<<<NH * N_TOK, 256>>>(scores);
        gemm_kernel<false, false><<<dim3(HDIM / 128, N_TOK / 128, NH), 256>>>(
            scores, Vout, ao, N_TOK, HDIM, NH * HDIM,
            (long long)N_TOK * N_TOK, (long long)N_TOK * HDIM,
            (long long)HDIM, 2, nullptr);

        // ---- Wo (mma) + residual ----
        wsplit_kernel<<<(unsigned)((eAO / 4 + 255) / 256), 256>>>(ao, ao3, eAO, eAO / 4);
        mma_gemm<<<dim3(DMODEL / 128, 8), 256, GSMEM>>>(
            ao3, wo3 + lwq, eAO, (long long)E_WO, tmp, NH * HDIM, DMODEL);
        add_rms_kernel<<<N_TOK, 256>>>(hs, tmp, ln_pa + (size_t)i * DMODEL, nullptr,
                                       nullptr, 0, DMODEL);

        // ---- FFN (mma) ----
        rmsnorm_split_kernel<<<N_TOK, 256>>>(hs, ln_pf + (size_t)i * DMODEL, h2, eH2, DMODEL);
        mma_gemm<<<dim3(FFDIM / 128, 8), 256, GSMEM>>>(
            h2, wg3 + lwg, eH2, (long long)E_WG, gbuf, DMODEL, FFDIM);
        mma_gemm<<<dim3(FFDIM / 128, 8), 256, GSMEM>>>(
            h2, wu3 + lwg, eH2, (long long)E_WG, ubuf, DMODEL, FFDIM);
        gelu_mul_split_kernel<<<(N_TOK * FFDIM + 255) / 256, 256>>>(gbuf, ubuf, m2, eM2, N_TOK * FFDIM);
        mma_gemm<<<dim3(DMODEL / 128, 8), 256, GSMEM>>>(
            m2, wd3 + lwg, eM2, (long long)E_WG, tmp, FFDIM, DMODEL);
        add_rms_kernel<<<N_TOK, 256>>>(hs, tmp, ln_ff + (size_t)i * DMODEL, nullptr,
                                       hs3, eH2, DMODEL);

        // ---- per-layer gating (mma) ----
        mma_gemm<<<dim3(HPL / 128, 8), 256, GSMEM>>>(
            hs3, wplg3 + lpl, eH2, (long long)E_WPL, plbuf, DMODEL, HPL);
        gelu_sl_split_kernel<<<(N_TOK * HPL + 255) / 256, 256>>>(plbuf, plc, li, pl3, ePL);
        mma_gemm<<<dim3(DMODEL / 128, 8), 256, GSMEM>>>(
            pl3, wplp3 + lpl, ePL, (long long)E_WPL, tmp, HPL, DMODEL);
        add_rms_kernel<<<N_TOK, 256>>>(hs, tmp, ln_pl + (size_t)i * DMODEL, lscale + i,
                                       nullptr, 0, DMODEL);
    }

    cudaMemcpyAsync(out, hs, (size_t)N_TOK * DMODEL * sizeof(float), cudaMemcpyDeviceToDevice, 0);
}

// round 9
// speedup vs baseline: 1.8404x; 1.0734x over previous
#include <cuda_runtime.h>
#include <cuda_bf16.h>
#include <math.h>
#include <stdint.h>

#define N_TOK 1024
#define DMODEL 2048
#define NH 8
#define NKV 2
#define HDIM 256
#define FFDIM 4096
#define HPL 256
#define NLAYER 7
#define STARTL 8
#define TOTAL_LAYERS 30
#define EPSF 1e-6f

typedef __nv_bfloat16 bf16;

// ======================= weight plane sizes (elements) =======================
#define E_QKV ((size_t)NLAYER * 3072 * DMODEL)     // fused [Wq|Wk|Wv] per layer
#define E_WO  ((size_t)NLAYER * DMODEL * (NH * HDIM))
#define E_GU  ((size_t)NLAYER * 8192 * DMODEL)     // fused [Wg|Wu] per layer
#define E_WD  ((size_t)NLAYER * DMODEL * FFDIM)
#define E_WPL ((size_t)NLAYER * HPL * DMODEL)

// ======================= scratch layout (bytes) =======================
#define OFF_WQKV  ((size_t)0)
#define OFF_WO3   (OFF_WQKV + 6 * E_QKV)
#define OFF_WGU   (OFF_WO3  + 6 * E_WO)
#define OFF_WD3   (OFF_WGU  + 6 * E_GU)
#define OFF_WPLG3 (OFF_WD3  + 6 * E_WD)
#define OFF_WPLP3 (OFF_WPLG3 + 6 * E_WPL)
// fp32 activations
#define OFF_HS     (OFF_WPLP3 + 6 * E_WPL)
#define OFF_QKVRAW (OFF_HS     + 4ull * N_TOK * DMODEL)
#define OFF_QT     (OFF_QKVRAW + 4ull * N_TOK * 3072)
#define OFF_SC     (OFF_QT     + 4ull * N_TOK * NH * HDIM)
#define OFF_AO     (OFF_SC     + 4ull * NH * N_TOK * N_TOK)
#define OFF_TMP    (OFF_AO     + 4ull * N_TOK * NH * HDIM)
#define OFF_GU     (OFF_TMP    + 4ull * N_TOK * DMODEL)
#define OFF_PLB    (OFF_GU     + 4ull * N_TOK * 8192)
// bf16 3-plane activations (6 bytes per element)
#define OFF_H2     (OFF_PLB + 4ull * N_TOK * HPL)
#define OFF_AO3    (OFF_H2  + 6ull * N_TOK * DMODEL)
#define OFF_M2     (OFF_AO3 + 6ull * N_TOK * NH * HDIM)
#define OFF_HS3    (OFF_M2  + 6ull * N_TOK * FFDIM)
#define OFF_PL3    (OFF_HS3 + 6ull * N_TOK * DMODEL)
#define TOTAL_SCR  (OFF_PL3 + 6ull * N_TOK * HPL)

__device__ __align__(1024) char g_scr[TOTAL_SCR];

// ======================= block reductions =======================
__device__ __forceinline__ float blockReduceSum256(float v) {
    __shared__ float sh[8]; __shared__ float res;
    int lane = threadIdx.x & 31, wid = threadIdx.x >> 5;
    #pragma unroll
    for (int o = 16; o > 0; o >>= 1) v += __shfl_xor_sync(0xffffffffu, v, o);
    if (lane == 0) sh[wid] = v;
    __syncthreads();
    if (wid == 0) {
        float x = (lane < 8) ? sh[lane] : 0.f;
        #pragma unroll
        for (int o = 4; o > 0; o >>= 1) x += __shfl_xor_sync(0xffffffffu, x, o);
        if (lane == 0) res = x;
    }
    __syncthreads();
    return res;
}
__device__ __forceinline__ float blockReduceMax256(float v) {
    __shared__ float sh[8]; __shared__ float res;
    int lane = threadIdx.x & 31, wid = threadIdx.x >> 5;
    #pragma unroll
    for (int o = 16; o > 0; o >>= 1) v = fmaxf(v, __shfl_xor_sync(0xffffffffu, v, o));
    if (lane == 0) sh[wid] = v;
    __syncthreads();
    if (wid == 0) {
        float x = (lane < 8) ? sh[lane] : -INFINITY;
        #pragma unroll
        for (int o = 4; o > 0; o >>= 1) x = fmaxf(x, __shfl_xor_sync(0xffffffffu, x, o));
        if (lane == 0) res = x;
    }
    __syncthreads();
    return res;
}
__device__ __forceinline__ float gelu_tanh(float x) {
    float t = tanhf(0.7978845608028654f * (x + 0.044715f * x * x * x));
    return 0.5f * x * (1.f + t);
}

// ======================= fp32 elementwise / norm kernels =======================
__global__ void add_rms_kernel(float* __restrict__ hs, const float* __restrict__ x,
                               const float* __restrict__ w,
                               const float* __restrict__ scale_ptr,
                               bf16* __restrict__ dst, size_t elts, int cols) {
    int row = blockIdx.x;
    const float* xr = x + (size_t)row * cols;
    float ss = 0.f;
    for (int c = threadIdx.x; c < cols; c += 256) { float v = xr[c]; ss += v * v; }
    ss = blockReduceSum256(ss);
    float inv = rsqrtf(ss / (float)cols + EPSF);
    float sc = scale_ptr ? *scale_ptr : 1.f;
    float* hr = hs + (size_t)row * cols;
    for (int c = threadIdx.x; c < cols; c += 256) {
        float y = (hr[c] + xr[c] * inv * (1.f + w[c])) * sc;
        hr[c] = y;
        if (dst) {
            bf16 h = __float2bfloat16_rn(y);
            float r = y - __bfloat162float(h);
            bf16 m = __float2bfloat16_rn(r);
            bf16 l = __float2bfloat16_rn(r - __bfloat162float(m));
            size_t o = (size_t)row * cols + c;
            dst[o] = h; dst[elts + o] = m; dst[2 * elts + o] = l;
        }
    }
}

// x indexed as x[n*ldx + h*HDIM + d] (slice of fused qkv buffer)
__global__ void rope_norm_kernel(const float* __restrict__ x, int ldx,
                                 const float* __restrict__ w,
                                 const float* __restrict__ cost, const float* __restrict__ sint,
                                 float* __restrict__ y) {
    int n = blockIdx.x, h = blockIdx.y, d = threadIdx.x;
    __shared__ float sx[HDIM];
    float v = x[(size_t)n * ldx + h * HDIM + d];
    float ss = blockReduceSum256(v * v);
    float inv = rsqrtf(ss / (float)HDIM + EPSF);
    float xn = v * inv * (1.f + w[d]);
    sx[d] = xn;
    __syncthreads();
    float rh = (d < HDIM / 2) ? -sx[d + HDIM / 2] : sx[d - HDIM / 2];
    y[((size_t)h * N_TOK + n) * HDIM + d] =
        xn * cost[(size_t)n * HDIM + d] + rh * sint[(size_t)n * HDIM + d];
}

__global__ void vnorm_kernel(const float* __restrict__ x, int ldx, float* __restrict__ y) {
    int n = blockIdx.x, h = blockIdx.y, d = threadIdx.x;
    float v = x[(size_t)n * ldx + h * HDIM + d];
    float ss = blockReduceSum256(v * v);
    y[((size_t)h * N_TOK + n) * HDIM + d] = v * rsqrtf(ss / (float)HDIM + EPSF);
}

__global__ void softmax_kernel(float* __restrict__ p) {
    float* row = p + (size_t)blockIdx.x * N_TOK;
    int base = threadIdx.x * 4;
    float4 r4 = *reinterpret_cast<float4*>(row + base);
    float v0 = r4.x, v1 = r4.y, v2 = r4.z, v3 = r4.w;
    float m = fmaxf(fmaxf(v0, v1), fmaxf(v2, v3));
    m = blockReduceMax256(m);
    v0 = expf(v0 - m); v1 = expf(v1 - m); v2 = expf(v2 - m); v3 = expf(v3 - m);
    float s = blockReduceSum256(v0 + v1 + v2 + v3);
    float invs = 1.f / s;
    float4 o4; o4.x = v0 * invs; o4.y = v1 * invs; o4.z = v2 * invs; o4.w = v3 * invs;
    *reinterpret_cast<float4*>(row + base) = o4;
}

// ======================= SIMT fp32 GEMM (attention only) =======================
template <bool BT, bool MASK>
__global__ void __launch_bounds__(256)
gemm_kernel(const float* __restrict__ A, const float* __restrict__ B, float* __restrict__ C,
            int K, int ldb, int ldc,
            long long sA, long long sB, long long sC, int bshift,
            const float* __restrict__ maskAdd) {
    __shared__ float As[8][128];
    __shared__ float Bs[8][132];
    const int tid = threadIdx.x;
    const int bz = blockIdx.z;
    const float* Ab = A + (size_t)bz * sA + (size_t)blockIdx.y * 128 * K;
    const float* Bb = B + (size_t)(bz >> bshift) * sB;
    float* Cb = C + (size_t)bz * sC;

    const int ar = tid >> 1;
    const int ak = (tid & 1) << 2;
    const int bk = tid >> 5;
    const int bc = (tid & 31) << 2;
    const int ty = tid >> 4, tx = tid & 15;

    float acc[8][8];
    #pragma unroll
    for (int i = 0; i < 8; i++)
        #pragma unroll
        for (int j = 0; j < 8; j++) acc[i][j] = 0.f;

    for (int kb = 0; kb < K; kb += 8) {
        float4 a4 = *reinterpret_cast<const float4*>(Ab + (size_t)ar * K + kb + ak);
        As[ak + 0][ar] = a4.x; As[ak + 1][ar] = a4.y;
        As[ak + 2][ar] = a4.z; As[ak + 3][ar] = a4.w;
        if (BT) {
            const float4 b4 = *reinterpret_cast<const float4*>(
                Bb + ((size_t)blockIdx.x * 128 + ar) * K + kb + ak);
            Bs[ak + 0][ar] = b4.x; Bs[ak + 1][ar] = b4.y;
            Bs[ak + 2][ar] = b4.z; Bs[ak + 3][ar] = b4.w;
        } else {
            const float4 b4 = *reinterpret_cast<const float4*>(
                Bb + (size_t)(kb + bk) * ldb + (size_t)blockIdx.x * 128 + bc);
            *reinterpret_cast<float4*>(&Bs[bk][bc]) = b4;
        }
        __syncthreads();
        #pragma unroll
        for (int k = 0; k < 8; k++) {
            float a[8], b[8];
            *reinterpret_cast<float4*>(&a[0]) = *reinterpret_cast<const float4*>(&As[k][ty * 8]);
            *reinterpret_cast<float4*>(&a[4]) = *reinterpret_cast<const float4*>(&As[k][ty * 8 + 4]);
            *reinterpret_cast<float4*>(&b[0]) = *reinterpret_cast<const float4*>(&Bs[k][tx * 8]);
            *reinterpret_cast<float4*>(&b[4]) = *reinterpret_cast<const float4*>(&Bs[k][tx * 8 + 4]);
            #pragma unroll
            for (int i = 0; i < 8; i++)
                #pragma unroll
                for (int j = 0; j < 8; j++) acc[i][j] += a[i] * b[j];
        }
        __syncthreads();
    }

    const int row0 = blockIdx.y * 128 + ty * 8;
    const int col0 = blockIdx.x * 128 + tx * 8;
    #pragma unroll
    for (int i = 0; i < 8; i++) {
        #pragma unroll
        for (int j = 0; j < 8; j++) {
            float v = acc[i][j];
            if (MASK) v += maskAdd[(size_t)(row0 + i) * N_TOK + (col0 + j)];
            Cb[(size_t)(row0 + i) * ldc + col0 + j] = v;
        }
    }
}

// ======================= bf16x3 mma machinery =======================
__device__ __forceinline__ uint32_t smem_u32(const void* p) {
    uint32_t a;
    asm("{ .reg .u64 t; cvta.to.shared.u64 t, %1; cvt.u32.u64 %0, t; }" : "=r"(a) : "l"(p));
    return a;
}
__device__ __forceinline__ void cp16(uint32_t dst, const void* src) {
    asm volatile("cp.async.cg.shared.global [%0], [%1], 16;" :: "r"(dst), "l"(src) : "memory");
}
__device__ __forceinline__ void ldsm4(uint32_t* r, uint32_t addr) {
    asm volatile("ldmatrix.sync.aligned.m8n8.x4.shared.b16 {%0,%1,%2,%3}, [%4];"
                 : "=r"(r[0]), "=r"(r[1]), "=r"(r[2]), "=r"(r[3]) : "r"(addr));
}
__device__ __forceinline__ void mma_bf16(float* d, const uint32_t* a, const uint32_t* b) {
    asm volatile(
        "mma.sync.aligned.m16n8k16.row.col.f32.bf16.bf16.f32 "
        "{%0,%1,%2,%3}, {%4,%5,%6,%7}, {%8,%9}, {%0,%1,%2,%3};"
        : "+f"(d[0]), "+f"(d[1]), "+f"(d[2]), "+f"(d[3])
        : "r"(a[0]), "r"(a[1]), "r"(a[2]), "r"(a[3]), "r"(b[0]), "r"(b[1]));
}
__device__ __forceinline__ void split3(float v, bf16& h, bf16& m, bf16& l) {
    h = __float2bfloat16_rn(v);
    float r = v - __bfloat162float(h);
    m = __float2bfloat16_rn(r);
    l = __float2bfloat16_rn(r - __bfloat162float(m));
}

#define TROWB 80
#define TILE_BYTES (128 * TROWB)
#define STG_BYTES  (6 * TILE_BYTES)   // 61440
#define GSMEM      (3 * STG_BYTES)    // 184320 (3-stage)

// C(1024 x M) = A(1024 x K) @ B(M x K)^T ; A,B bf16 3-plane (strides eA/eB), fp32 out.
// Dual accumulators (hh -> accM; corrections -> accC). 3-stage cp.async pipeline.
__global__ void __launch_bounds__(256, 1)
mma_gemm(const bf16* __restrict__ A3, const bf16* __restrict__ B3,
         long long eA, long long eB,
         float* __restrict__ Cf, int K, int ldc) {
    extern __shared__ char smem[];
    const uint32_t sb = smem_u32(smem);
    const int tid = threadIdx.x;
    const int row0 = blockIdx.y * 128;
    const int col0 = blockIdx.x * 128;

    const bf16* srcs[6];
    #pragma unroll
    for (int p = 0; p < 3; p++) {
        srcs[p]     = A3 + (size_t)p * eA + (size_t)row0 * K;
        srcs[3 + p] = B3 + (size_t)p * eB + (size_t)col0 * K;
    }

    const int lane = tid & 31, wid = tid >> 5;
    const int wm = wid & 3, wn = wid >> 2;
    const int ld_r = tid >> 2;
    const int ld_c = tid & 3;

    uint32_t aoff[2], boff[4];
    #pragma unroll
    for (int m = 0; m < 2; m++)
        aoff[m] = (uint32_t)((wm * 32 + m * 16 + (lane & 15)) * TROWB + ((lane >> 4) << 4));
    #pragma unroll
    for (int j = 0; j < 4; j++)
        boff[j] = (uint32_t)((wn * 64 + j * 16 + (lane & 7) + ((lane >> 4) << 3)) * TROWB
                             + (((lane >> 3) & 1) << 4));

    float accM[2][8][4], accC[2][8][4];
    #pragma unroll
    for (int m = 0; m < 2; m++)
        #pragma unroll
        for (int t = 0; t < 8; t++)
            #pragma unroll
            for (int u = 0; u < 4; u++) { accM[m][t][u] = 0.f; accC[m][t][u] = 0.f; }

    const int nch = K >> 5;

    auto issue = [&](int c, uint32_t dstb) {
        const int kb = c << 5;
        #pragma unroll
        for (int q = 0; q < 12; q++) {
            const int r = (q & 1) * 64 + ld_r;
            const char* gsrc = (const char*)(srcs[q >> 1] + (size_t)r * K + kb) + ld_c * 16;
            cp16(dstb + (uint32_t)((q >> 1) * TILE_BYTES + r * TROWB + ld_c * 16), gsrc);
        }
        asm volatile("cp.async.commit_group;" ::: "memory");
    };

    issue(0, sb);
    if (nch > 1) issue(1, sb + STG_BYTES);
    if (nch > 2) issue(2, sb + 2 * STG_BYTES);

    int stage = 0;
    for (int c = 0; c < nch; ++c) {
        const int rem = nch - 1 - c;
        if (rem >= 2)      asm volatile("cp.async.wait_group 2;" ::: "memory");
        else if (rem == 1) asm volatile("cp.async.wait_group 1;" ::: "memory");
        else               asm volatile("cp.async.wait_group 0;" ::: "memory");
        __syncthreads();

        const uint32_t base = sb + (uint32_t)stage * STG_BYTES;

        #pragma unroll
        for (int kk = 0; kk < 2; kk++) {
            const uint32_t kb = kk * 32;
            uint32_t ah[2][4], am[2][4], al[2][4];
            #pragma unroll
            for (int m = 0; m < 2; m++) {
                ldsm4(ah[m], base + 0 * TILE_BYTES + aoff[m] + kb);
                ldsm4(am[m], base + 1 * TILE_BYTES + aoff[m] + kb);
                ldsm4(al[m], base + 2 * TILE_BYTES + aoff[m] + kb);
            }
            #pragma unroll
            for (int j = 0; j < 4; j++) {
                uint32_t bh[4], bm[4], bl[4];
                ldsm4(bh, base + 3 * TILE_BYTES + boff[j] + kb);
                ldsm4(bm, base + 4 * TILE_BYTES + boff[j] + kb);
                ldsm4(bl, base + 5 * TILE_BYTES + boff[j] + kb);
                #pragma unroll
                for (int m = 0; m < 2; m++) {
                    #pragma unroll
                    for (int h = 0; h < 2; h++) {
                        float* dM = accM[m][j * 2 + h];
                        float* dC = accC[m][j * 2 + h];
                        mma_bf16(dM, ah[m], &bh[h * 2]);   // hh -> main
                        mma_bf16(dC, ah[m], &bm[h * 2]);   // corrections -> corr
                        mma_bf16(dC, am[m], &bh[h * 2]);
                        mma_bf16(dC, am[m], &bm[h * 2]);
                        mma_bf16(dC, ah[m], &bl[h * 2]);
                        mma_bf16(dC, al[m], &bh[h * 2]);
                    }
                }
            }
        }
        __syncthreads();
        if (c + 3 < nch) issue(c + 3, base);
        stage = (stage == 2) ? 0 : stage + 1;
    }

    const int grp = lane >> 2, qd = lane & 3;
    #pragma unroll
    for (int m = 0; m < 2; m++) {
        #pragma unroll
        for (int t = 0; t < 8; t++) {
            const int col = col0 + wn * 64 + t * 8 + qd * 2;
            #pragma unroll
            for (int half = 0; half < 2; half++) {
                const int row = row0 + wm * 32 + m * 16 + grp + half * 8;
                float2 o2;
                o2.x = accM[m][t][half * 2 + 0] + accC[m][t][half * 2 + 0];
                o2.y = accM[m][t][half * 2 + 1] + accC[m][t][half * 2 + 1];
                *(float2*)(Cf + (size_t)row * ldc + col) = o2;
            }
        }
    }
}

// ======================= split producers =======================
// fp32 -> 3-plane bf16 with explicit plane stride
__global__ void wsplit_kernel(const float* __restrict__ x, bf16* __restrict__ dst,
                              size_t plane, size_t n4) {
    size_t i = (size_t)blockIdx.x * 256 + threadIdx.x;
    if (i >= n4) return;
    float4 v = ((const float4*)x)[i];
    union { bf16 b[4]; uint2 u2; } H, M, L;
    split3(v.x, H.b[0], M.b[0], L.b[0]); split3(v.y, H.b[1], M.b[1], L.b[1]);
    split3(v.z, H.b[2], M.b[2], L.b[2]); split3(v.w, H.b[3], M.b[3], L.b[3]);
    ((uint2*)dst)[i] = H.u2;
    ((uint2*)(dst + plane))[i] = M.u2;
    ((uint2*)(dst + 2 * plane))[i] = L.u2;
}

__global__ void rmsnorm_split_kernel(const float* __restrict__ x, const float* __restrict__ w,
                                     bf16* __restrict__ dst, size_t elts, int cols) {
    int row = blockIdx.x;
    const float* xr = x + (size_t)row * cols;
    float ss = 0.f;
    for (int c = threadIdx.x; c < cols; c += 256) { float v = xr[c]; ss += v * v; }
    ss = blockReduceSum256(ss);
    float inv = rsqrtf(ss / (float)cols + EPSF);
    for (int c = threadIdx.x; c < cols; c += 256) {
        float y = xr[c] * inv * (1.f + w[c]);
        bf16 h, m, l; split3(y, h, m, l);
        size_t o = (size_t)row * cols + c;
        dst[o] = h; dst[elts + o] = m; dst[2 * elts + o] = l;
    }
}

// reads fused [g|u] buffer (row stride 8192)
__global__ void gelu_mul_split_kernel(const float* __restrict__ gu,
                                      bf16* __restrict__ dst, size_t elts, int n) {
    int i = blockIdx.x * 256 + threadIdx.x;
    if (i < n) {
        int row = i >> 12, j = i & 4095;
        float g = gu[(size_t)row * 8192 + j];
        float u = gu[(size_t)row * 8192 + 4096 + j];
        float y = gelu_tanh(g) * u;
        bf16 h, m, l; split3(y, h, m, l);
        dst[i] = h; dst[elts + i] = m; dst[2 * elts + i] = l;
    }
}

__global__ void gelu_sl_split_kernel(const float* __restrict__ g, const float* __restrict__ plc,
                                     int li, bf16* __restrict__ dst, size_t elts) {
    int i = blockIdx.x * 256 + threadIdx.x;
    if (i < N_TOK * HPL) {
        int n = i >> 8, j = i & 255;
        float y = gelu_tanh(g[i]) * plc[(size_t)n * (TOTAL_LAYERS * HPL) + (size_t)li * HPL + j];
        bf16 h, m, l; split3(y, h, m, l);
        dst[i] = h; dst[elts + i] = m; dst[2 * elts + i] = l;
    }
}

// ======================= driver =======================
extern "C" void kernel_launch(void* const* d_in, const int* in_sizes, int n_in,
                              void* d_out, int out_size) {
    const float* hidden = (const float*)d_in[0];
    const float* plc    = (const float*)d_in[1];
    const float* mask   = (const float*)d_in[2];
    const float* cos_s  = (const float*)d_in[3];
    const float* sin_s  = (const float*)d_in[4];
    const float* cos_f  = (const float*)d_in[5];
    const float* sin_f  = (const float*)d_in[6];
    const float* Wq     = (const float*)d_in[7];
    const float* Wk     = (const float*)d_in[8];
    const float* Wv     = (const float*)d_in[9];
    const float* Wo     = (const float*)d_in[10];
    const float* Wg     = (const float*)d_in[11];
    const float* Wu     = (const float*)d_in[12];
    const float* Wd     = (const float*)d_in[13];
    const float* Wplg   = (const float*)d_in[14];
    const float* Wplp   = (const float*)d_in[15];
    const float* ln_in  = (const float*)d_in[16];
    const float* ln_pa  = (const float*)d_in[17];
    const float* ln_pf  = (const float*)d_in[18];
    const float* ln_ff  = (const float*)d_in[19];
    const float* ln_pl  = (const float*)d_in[20];
    const float* qn_w   = (const float*)d_in[21];
    const float* kn_w   = (const float*)d_in[22];
    const float* lscale = (const float*)d_in[23];

    cudaFuncSetAttribute(mma_gemm, cudaFuncAttributeMaxDynamicSharedMemorySize, GSMEM);

    char* scr = nullptr;
    cudaGetSymbolAddress((void**)&scr, g_scr);

    bf16* wqkv3 = (bf16*)(scr + OFF_WQKV);
    bf16* wo3   = (bf16*)(scr + OFF_WO3);
    bf16* wgu3  = (bf16*)(scr + OFF_WGU);
    bf16* wd3   = (bf16*)(scr + OFF_WD3);
    bf16* wplg3 = (bf16*)(scr + OFF_WPLG3);
    bf16* wplp3 = (bf16*)(scr + OFF_WPLP3);

    float* hs     = (float*)(scr + OFF_HS);
    float* qkvraw = (float*)(scr + OFF_QKVRAW);
    float* qt     = (float*)(scr + OFF_QT);
    float* scores = (float*)(scr + OFF_SC);
    float* ao     = (float*)(scr + OFF_AO);
    float* tmp    = (float*)(scr + OFF_TMP);
    float* gu     = (float*)(scr + OFF_GU);
    float* plbuf  = (float*)(scr + OFF_PLB);
    bf16*  h2     = (bf16*)(scr + OFF_H2);
    bf16*  ao3    = (bf16*)(scr + OFF_AO3);
    bf16*  m2     = (bf16*)(scr + OFF_M2);
    bf16*  hs3    = (bf16*)(scr + OFF_HS3);
    bf16*  pl3    = (bf16*)(scr + OFF_PL3);

    const long long eH2 = (long long)N_TOK * DMODEL;
    const long long eAO = (long long)N_TOK * NH * HDIM;
    const long long eM2 = (long long)N_TOK * FFDIM;
    const long long ePL = (long long)N_TOK * HPL;
    float* out = (float*)d_out;

    // ---- split weights into fused 3-plane layouts (once per call) ----
    auto wsplit = [&](const float* src, bf16* dst, size_t plane, size_t count) {
        size_t n4 = count / 4;
        wsplit_kernel<<<(unsigned)((n4 + 255) / 256), 256>>>(src, dst, plane, n4);
    };
    for (int i = 0; i < NLAYER; i++) {
        const size_t lq = (size_t)i * 2048 * 2048;   // within Wq
        const size_t lk = (size_t)i * 512 * 2048;    // within Wk / Wv
        bf16* dst = wqkv3 + (size_t)i * 3072 * 2048;
        wsplit(Wq + lq, dst,                   E_QKV, (size_t)2048 * 2048);
        wsplit(Wk + lk, dst + 2048 * 2048,     E_QKV, (size_t)512 * 2048);
        wsplit(Wv + lk, dst + 2560 * 2048,     E_QKV, (size_t)512 * 2048);

        const size_t lg = (size_t)i * 4096 * 2048;
        bf16* dgu = wgu3 + (size_t)i * 8192 * 2048;
        wsplit(Wg + lg, dgu,                   E_GU, (size_t)4096 * 2048);
        wsplit(Wu + lg, dgu + 4096 * 2048,     E_GU, (size_t)4096 * 2048);
    }
    wsplit(Wo,   wo3,   E_WO,  E_WO);
    wsplit(Wd,   wd3,   E_WD,  E_WD);
    wsplit(Wplg, wplg3, E_WPL, E_WPL);
    wsplit(Wplp, wplp3, E_WPL, E_WPL);

    cudaMemcpyAsync(hs, hidden, (size_t)N_TOK * DMODEL * sizeof(float), cudaMemcpyDeviceToDevice, 0);

    for (int i = 0; i < NLAYER; i++) {
        const int li = STARTL + i;
        const bool full = ((li + 1) % 5) == 0;
        const float* cost = full ? cos_f : cos_s;
        const float* sint = full ? sin_f : sin_s;
        float* Kout = out + (size_t)N_TOK * DMODEL + (size_t)i * 2 * NKV * N_TOK * HDIM;
        float* Vout = Kout + (size_t)NKV * N_TOK * HDIM;

        // ---- pre-attention norm + fused QKV (mma) ----
        rmsnorm_split_kernel<<<N_TOK, 256>>>(hs, ln_in + (size_t)i * DMODEL, h2, eH2, DMODEL);
        mma_gemm<<<dim3(3072 / 128, 8), 256, GSMEM>>>(
            h2, wqkv3 + (size_t)i * 3072 * 2048, eH2, (long long)E_QKV, qkvraw, DMODEL, 3072);

        rope_norm_kernel<<<dim3(N_TOK, NH),  256>>>(qkvraw,        3072, qn_w + (size_t)i * HDIM, cost, sint, qt);
        rope_norm_kernel<<<dim3(N_TOK, NKV), 256>>>(qkvraw + 2048, 3072, kn_w + (size_t)i * HDIM, cost, sint, Kout);
        vnorm_kernel    <<<dim3(N_TOK, NKV), 256>>>(qkvraw + 2560, 3072, Vout);

        // ---- attention core (fp32 SIMT, verified) ----
        gemm_kernel<true, true><<<dim3(N_TOK / 128, N_TOK / 128, NH), 256>>>(
            qt, Kout, scores, HDIM, 0, N_TOK,
            (long long)N_TOK * HDIM, (long long)N_TOK * HDIM,
            (long long)N_TOK * N_TOK, 2, mask);
        softmax_kernel<<<NH * N_TOK, 256>>>(scores);
        gemm_kernel<false, false><<<dim3(HDIM / 128, N_TOK / 128, NH), 256>>>(
            scores, Vout, ao, N_TOK, HDIM, NH * HDIM,
            (long long)N_TOK * N_TOK, (long long)N_TOK * HDIM,
            (long long)HDIM, 2, nullptr);

        // ---- Wo (mma) + residual ----
        wsplit_kernel<<<(unsigned)((eAO / 4 + 255) / 256), 256>>>(ao, ao3, eAO, eAO / 4);
        mma_gemm<<<dim3(DMODEL / 128, 8), 256, GSMEM>>>(
            ao3, wo3 + (size_t)i * 2048 * 2048, eAO, (long long)E_WO, tmp, NH * HDIM, DMODEL);
        add_rms_kernel<<<N_TOK, 256>>>(hs, tmp, ln_pa + (size_t)i * DMODEL, nullptr,
                                       nullptr, 0, DMODEL);

        // ---- FFN: fused G+U, gelu*u, Wd (mma) ----
        rmsnorm_split_kernel<<<N_TOK, 256>>>(hs, ln_pf + (size_t)i * DMODEL, h2, eH2, DMODEL);
        mma_gemm<<<dim3(8192 / 128, 8), 256, GSMEM>>>(
            h2, wgu3 + (size_t)i * 8192 * 2048, eH2, (long long)E_GU, gu, DMODEL, 8192);
        gelu_mul_split_kernel<<<(N_TOK * FFDIM + 255) / 256, 256>>>(gu, m2, eM2, N_TOK * FFDIM);
        mma_gemm<<<dim3(DMODEL / 128, 8), 256, GSMEM>>>(
            m2, wd3 + (size_t)i * 2048 * 4096, eM2, (long long)E_WD, tmp, FFDIM, DMODEL);
        add_rms_kernel<<<N_TOK, 256>>>(hs, tmp, ln_ff + (size_t)i * DMODEL, nullptr,
                                       hs3, eH2, DMODEL);

        // ---- per-layer gating (mma) ----
        mma_gemm<<<dim3(HPL / 128, 8), 256, GSMEM>>>(
            hs3, wplg3 + (size_t)i * HPL * 2048, eH2, (long long)E_WPL, plbuf, DMODEL, HPL);
        gelu_sl_split_kernel<<<(N_TOK * HPL + 255) / 256, 256>>>(plbuf, plc, li, pl3, ePL);
        mma_gemm<<<dim3(DMODEL / 128, 8), 256, GSMEM>>>(
            pl3, wplp3 + (size_t)i * 2048 * HPL, ePL, (long long)E_WPL, tmp, HPL, DMODEL);
        add_rms_kernel<<<N_TOK, 256>>>(hs, tmp, ln_pl + (size_t)i * DMODEL, lscale + i,
                                       nullptr, 0, DMODEL);
    }

    cudaMemcpyAsync(out, hs, (size_t)N_TOK * DMODEL * sizeof(float), cudaMemcpyDeviceToDevice, 0);
}

// round 10
// speedup vs baseline: 1.9724x; 1.0717x over previous
#include <cuda_runtime.h>
#include <cuda_bf16.h>
#include <math.h>
#include <stdint.h>

#define N_TOK 1024
#define DMODEL 2048
#define NH 8
#define NKV 2
#define HDIM 256
#define FFDIM 4096
#define HPL 256
#define NLAYER 7
#define STARTL 8
#define TOTAL_LAYERS 30
#define EPSF 1e-6f

typedef __nv_bfloat16 bf16;

// ======================= weight plane sizes (elements) =======================
#define E_QKV ((size_t)NLAYER * 3072 * DMODEL)
#define E_WO  ((size_t)NLAYER * DMODEL * (NH * HDIM))
#define E_GU  ((size_t)NLAYER * 8192 * DMODEL)
#define E_WD  ((size_t)NLAYER * DMODEL * FFDIM)
#define E_WPL ((size_t)NLAYER * HPL * DMODEL)
// activation plane sizes (elements)
#define E_H2  ((size_t)N_TOK * DMODEL)
#define E_QT  ((size_t)N_TOK * NH * HDIM)
#define E_KT  ((size_t)N_TOK * NKV * HDIM)
#define E_P3  ((size_t)NH * N_TOK * N_TOK)
#define E_AO  ((size_t)N_TOK * NH * HDIM)
#define E_M2  ((size_t)N_TOK * FFDIM)
#define E_PL  ((size_t)N_TOK * HPL)

// ======================= scratch layout (bytes) =======================
#define OFF_WQKV  ((size_t)0)
#define OFF_WO3   (OFF_WQKV + 6 * E_QKV)
#define OFF_WGU   (OFF_WO3  + 6 * E_WO)
#define OFF_WD3   (OFF_WGU  + 6 * E_GU)
#define OFF_WPLG3 (OFF_WD3  + 6 * E_WD)
#define OFF_WPLP3 (OFF_WPLG3 + 6 * E_WPL)
// fp32 activations
#define OFF_HS     (OFF_WPLP3 + 6 * E_WPL)
#define OFF_QKVRAW (OFF_HS     + 4ull * N_TOK * DMODEL)
#define OFF_SC     (OFF_QKVRAW + 4ull * N_TOK * 3072)
#define OFF_AO     (OFF_SC     + 4ull * E_P3)
#define OFF_TMP    (OFF_AO     + 4ull * E_AO)
#define OFF_GU     (OFF_TMP    + 4ull * N_TOK * DMODEL)
#define OFF_PLB    (OFF_GU     + 4ull * N_TOK * 8192)
// bf16 3-plane activations (6 bytes per element)
#define OFF_H2     (OFF_PLB + 4ull * E_PL)
#define OFF_QT3    (OFF_H2  + 6ull * E_H2)
#define OFF_KT3    (OFF_QT3 + 6ull * E_QT)
#define OFF_VT3    (OFF_KT3 + 6ull * E_KT)
#define OFF_P3     (OFF_VT3 + 6ull * E_KT)
#define OFF_AO3    (OFF_P3  + 6ull * E_P3)
#define OFF_M2     (OFF_AO3 + 6ull * E_AO)
#define OFF_HS3    (OFF_M2  + 6ull * E_M2)
#define OFF_PL3    (OFF_HS3 + 6ull * E_H2)
#define TOTAL_SCR  (OFF_PL3 + 6ull * E_PL)

__device__ __align__(1024) char g_scr[TOTAL_SCR];

// ======================= block reductions =======================
__device__ __forceinline__ float blockReduceSum256(float v) {
    __shared__ float sh[8]; __shared__ float res;
    int lane = threadIdx.x & 31, wid = threadIdx.x >> 5;
    #pragma unroll
    for (int o = 16; o > 0; o >>= 1) v += __shfl_xor_sync(0xffffffffu, v, o);
    if (lane == 0) sh[wid] = v;
    __syncthreads();
    if (wid == 0) {
        float x = (lane < 8) ? sh[lane] : 0.f;
        #pragma unroll
        for (int o = 4; o > 0; o >>= 1) x += __shfl_xor_sync(0xffffffffu, x, o);
        if (lane == 0) res = x;
    }
    __syncthreads();
    return res;
}
__device__ __forceinline__ float blockReduceMax256(float v) {
    __shared__ float sh[8]; __shared__ float res;
    int lane = threadIdx.x & 31, wid = threadIdx.x >> 5;
    #pragma unroll
    for (int o = 16; o > 0; o >>= 1) v = fmaxf(v, __shfl_xor_sync(0xffffffffu, v, o));
    if (lane == 0) sh[wid] = v;
    __syncthreads();
    if (wid == 0) {
        float x = (lane < 8) ? sh[lane] : -INFINITY;
        #pragma unroll
        for (int o = 4; o > 0; o >>= 1) x = fmaxf(x, __shfl_xor_sync(0xffffffffu, x, o));
        if (lane == 0) res = x;
    }
    __syncthreads();
    return res;
}
__device__ __forceinline__ float gelu_tanh(float x) {
    float t = tanhf(0.7978845608028654f * (x + 0.044715f * x * x * x));
    return 0.5f * x * (1.f + t);
}
__device__ __forceinline__ void split3(float v, bf16& h, bf16& m, bf16& l) {
    h = __float2bfloat16_rn(v);
    float r = v - __bfloat162float(h);
    m = __float2bfloat16_rn(r);
    l = __float2bfloat16_rn(r - __bfloat162float(m));
}

// ======================= norm / elementwise kernels =======================
__global__ void add_rms_kernel(float* __restrict__ hs, const float* __restrict__ x,
                               const float* __restrict__ w,
                               const float* __restrict__ scale_ptr,
                               bf16* __restrict__ dst, size_t elts, int cols) {
    int row = blockIdx.x;
    const float* xr = x + (size_t)row * cols;
    float ss = 0.f;
    for (int c = threadIdx.x; c < cols; c += 256) { float v = xr[c]; ss += v * v; }
    ss = blockReduceSum256(ss);
    float inv = rsqrtf(ss / (float)cols + EPSF);
    float sc = scale_ptr ? *scale_ptr : 1.f;
    float* hr = hs + (size_t)row * cols;
    for (int c = threadIdx.x; c < cols; c += 256) {
        float y = (hr[c] + xr[c] * inv * (1.f + w[c])) * sc;
        hr[c] = y;
        if (dst) {
            bf16 h, m, l; split3(y, h, m, l);
            size_t o = (size_t)row * cols + c;
            dst[o] = h; dst[elts + o] = m; dst[2 * elts + o] = l;
        }
    }
}

// qk-norm + rope from fused qkv (row stride ldx); optional fp32 out; split planes out
__global__ void rope_norm_split_kernel(const float* __restrict__ x, int ldx,
                                       const float* __restrict__ w,
                                       const float* __restrict__ cost, const float* __restrict__ sint,
                                       float* __restrict__ f32out,
                                       bf16* __restrict__ dst, size_t elts) {
    int n = blockIdx.x, h = blockIdx.y, d = threadIdx.x;
    __shared__ float sx[HDIM];
    float v = x[(size_t)n * ldx + h * HDIM + d];
    float ss = blockReduceSum256(v * v);
    float inv = rsqrtf(ss / (float)HDIM + EPSF);
    float xn = v * inv * (1.f + w[d]);
    sx[d] = xn;
    __syncthreads();
    float rh = (d < HDIM / 2) ? -sx[d + HDIM / 2] : sx[d - HDIM / 2];
    float y = xn * cost[(size_t)n * HDIM + d] + rh * sint[(size_t)n * HDIM + d];
    size_t idx = ((size_t)h * N_TOK + n) * HDIM + d;
    if (f32out) f32out[idx] = y;
    bf16 bh, bm, bl; split3(y, bh, bm, bl);
    dst[idx] = bh; dst[elts + idx] = bm; dst[2 * elts + idx] = bl;
}

// v-norm: fp32 out (kv, N, HD) + transposed split planes (kv, HD, N)
__global__ void vnorm_split_kernel(const float* __restrict__ x, int ldx,
                                   float* __restrict__ f32out,
                                   bf16* __restrict__ dst, size_t elts) {
    int n = blockIdx.x, h = blockIdx.y, d = threadIdx.x;
    float v = x[(size_t)n * ldx + h * HDIM + d];
    float ss = blockReduceSum256(v * v);
    float y = v * rsqrtf(ss / (float)HDIM + EPSF);
    f32out[((size_t)h * N_TOK + n) * HDIM + d] = y;
    bf16 bh, bm, bl; split3(y, bh, bm, bl);
    size_t tidx = ((size_t)h * HDIM + d) * N_TOK + n;
    dst[tidx] = bh; dst[elts + tidx] = bm; dst[2 * elts + tidx] = bl;
}

// causal softmax over rows of 1024 (entries beyond diagonal -> exactly 0, identical
// to mask-add since exp(-1e9 - max) underflows to 0 in fp32), output split planes
__global__ void softmax_causal_split_kernel(const float* __restrict__ p,
                                            bf16* __restrict__ dst, size_t elts) {
    const float* row = p + (size_t)blockIdx.x * N_TOK;
    const int r = blockIdx.x & (N_TOK - 1);
    int base = threadIdx.x * 4;
    float4 r4 = *(const float4*)(row + base);
    float v[4] = {r4.x, r4.y, r4.z, r4.w};
    float m = -INFINITY;
    #pragma unroll
    for (int i = 0; i < 4; i++) if (base + i <= r) m = fmaxf(m, v[i]);
    m = blockReduceMax256(m);
    float e[4];
    #pragma unroll
    for (int i = 0; i < 4; i++) e[i] = (base + i <= r) ? expf(v[i] - m) : 0.f;
    float s = blockReduceSum256(e[0] + e[1] + e[2] + e[3]);
    float invs = 1.f / s;
    union { bf16 b[4]; uint2 u2; } H, M, L;
    #pragma unroll
    for (int i = 0; i < 4; i++) split3(e[i] * invs, H.b[i], M.b[i], L.b[i]);
    size_t o = (size_t)blockIdx.x * N_TOK + base;
    *(uint2*)(dst + o) = H.u2;
    *(uint2*)(dst + elts + o) = M.u2;
    *(uint2*)(dst + 2 * elts + o) = L.u2;
}

// ======================= bf16x3 mma machinery =======================
__device__ __forceinline__ uint32_t smem_u32(const void* p) {
    uint32_t a;
    asm("{ .reg .u64 t; cvta.to.shared.u64 t, %1; cvt.u32.u64 %0, t; }" : "=r"(a) : "l"(p));
    return a;
}
__device__ __forceinline__ void cp16(uint32_t dst, const void* src) {
    asm volatile("cp.async.cg.shared.global [%0], [%1], 16;" :: "r"(dst), "l"(src) : "memory");
}
__device__ __forceinline__ void ldsm4(uint32_t* r, uint32_t addr) {
    asm volatile("ldmatrix.sync.aligned.m8n8.x4.shared.b16 {%0,%1,%2,%3}, [%4];"
                 : "=r"(r[0]), "=r"(r[1]), "=r"(r[2]), "=r"(r[3]) : "r"(addr));
}
__device__ __forceinline__ void mma_bf16(float* d, const uint32_t* a, const uint32_t* b) {
    asm volatile(
        "mma.sync.aligned.m16n8k16.row.col.f32.bf16.bf16.f32 "
        "{%0,%1,%2,%3}, {%4,%5,%6,%7}, {%8,%9}, {%0,%1,%2,%3};"
        : "+f"(d[0]), "+f"(d[1]), "+f"(d[2]), "+f"(d[3])
        : "r"(a[0]), "r"(a[1]), "r"(a[2]), "r"(a[3]), "r"(b[0]), "r"(b[1]));
}

#define TROWB 80
#define TILE_BYTES (128 * TROWB)
#define STG_BYTES  (6 * TILE_BYTES)   // 61440
#define GSMEM      (3 * STG_BYTES)    // 184320 (3-stage)

// C[z](1024/rows x M) tile = A[z](rows x K) @ B[z>>bshift](M x K)^T
// A,B bf16 3-plane (plane strides eA/eB); fp32 out. Dual accumulators; 3-stage pipeline.
__global__ void __launch_bounds__(256, 1)
mma_gemm(const bf16* __restrict__ A3, const bf16* __restrict__ B3,
         long long eA, long long eB,
         float* __restrict__ Cf, int K, int ldc,
         long long sA, long long sB, long long sC, int bshift) {
    extern __shared__ char smem[];
    const uint32_t sb = smem_u32(smem);
    const int tid = threadIdx.x;
    const int bz = blockIdx.z;
    const int row0 = blockIdx.y * 128;
    const int col0 = blockIdx.x * 128;
    Cf += (size_t)bz * sC;

    const bf16* srcs[6];
    #pragma unroll
    for (int p = 0; p < 3; p++) {
        srcs[p]     = A3 + (size_t)p * eA + (size_t)bz * sA + (size_t)row0 * K;
        srcs[3 + p] = B3 + (size_t)p * eB + (size_t)(bz >> bshift) * sB + (size_t)col0 * K;
    }

    const int lane = tid & 31, wid = tid >> 5;
    const int wm = wid & 3, wn = wid >> 2;
    const int ld_r = tid >> 2;
    const int ld_c = tid & 3;

    uint32_t aoff[2], boff[4];
    #pragma unroll
    for (int m = 0; m < 2; m++)
        aoff[m] = (uint32_t)((wm * 32 + m * 16 + (lane & 15)) * TROWB + ((lane >> 4) << 4));
    #pragma unroll
    for (int j = 0; j < 4; j++)
        boff[j] = (uint32_t)((wn * 64 + j * 16 + (lane & 7) + ((lane >> 4) << 3)) * TROWB
                             + (((lane >> 3) & 1) << 4));

    float accM[2][8][4], accC[2][8][4];
    #pragma unroll
    for (int m = 0; m < 2; m++)
        #pragma unroll
        for (int t = 0; t < 8; t++)
            #pragma unroll
            for (int u = 0; u < 4; u++) { accM[m][t][u] = 0.f; accC[m][t][u] = 0.f; }

    const int nch = K >> 5;

    auto issue = [&](int c, uint32_t dstb) {
        const int kb = c << 5;
        #pragma unroll
        for (int q = 0; q < 12; q++) {
            const int r = (q & 1) * 64 + ld_r;
            const char* gsrc = (const char*)(srcs[q >> 1] + (size_t)r * K + kb) + ld_c * 16;
            cp16(dstb + (uint32_t)((q >> 1) * TILE_BYTES + r * TROWB + ld_c * 16), gsrc);
        }
        asm volatile("cp.async.commit_group;" ::: "memory");
    };

    issue(0, sb);
    if (nch > 1) issue(1, sb + STG_BYTES);
    if (nch > 2) issue(2, sb + 2 * STG_BYTES);

    int stage = 0;
    for (int c = 0; c < nch; ++c) {
        const int rem = nch - 1 - c;
        if (rem >= 2)      asm volatile("cp.async.wait_group 2;" ::: "memory");
        else if (rem == 1) asm volatile("cp.async.wait_group 1;" ::: "memory");
        else               asm volatile("cp.async.wait_group 0;" ::: "memory");
        __syncthreads();

        const uint32_t base = sb + (uint32_t)stage * STG_BYTES;

        #pragma unroll
        for (int kk = 0; kk < 2; kk++) {
            const uint32_t kb = kk * 32;
            uint32_t ah[2][4], am[2][4], al[2][4];
            #pragma unroll
            for (int m = 0; m < 2; m++) {
                ldsm4(ah[m], base + 0 * TILE_BYTES + aoff[m] + kb);
                ldsm4(am[m], base + 1 * TILE_BYTES + aoff[m] + kb);
                ldsm4(al[m], base + 2 * TILE_BYTES + aoff[m] + kb);
            }
            #pragma unroll
            for (int j = 0; j < 4; j++) {
                uint32_t bh[4], bm[4], bl[4];
                ldsm4(bh, base + 3 * TILE_BYTES + boff[j] + kb);
                ldsm4(bm, base + 4 * TILE_BYTES + boff[j] + kb);
                ldsm4(bl, base + 5 * TILE_BYTES + boff[j] + kb);
                #pragma unroll
                for (int m = 0; m < 2; m++) {
                    #pragma unroll
                    for (int h = 0; h < 2; h++) {
                        float* dM = accM[m][j * 2 + h];
                        float* dC = accC[m][j * 2 + h];
                        mma_bf16(dM, ah[m], &bh[h * 2]);   // hh -> main
                        mma_bf16(dC, ah[m], &bm[h * 2]);   // corrections -> corr
                        mma_bf16(dC, am[m], &bh[h * 2]);
                        mma_bf16(dC, am[m], &bm[h * 2]);
                        mma_bf16(dC, ah[m], &bl[h * 2]);
                        mma_bf16(dC, al[m], &bh[h * 2]);
                    }
                }
            }
        }
        __syncthreads();
        if (c + 3 < nch) issue(c + 3, base);
        stage = (stage == 2) ? 0 : stage + 1;
    }

    const int grp = lane >> 2, qd = lane & 3;
    #pragma unroll
    for (int m = 0; m < 2; m++) {
        #pragma unroll
        for (int t = 0; t < 8; t++) {
            const int col = col0 + wn * 64 + t * 8 + qd * 2;
            #pragma unroll
            for (int half = 0; half < 2; half++) {
                const int row = row0 + wm * 32 + m * 16 + grp + half * 8;
                float2 o2;
                o2.x = accM[m][t][half * 2 + 0] + accC[m][t][half * 2 + 0];
                o2.y = accM[m][t][half * 2 + 1] + accC[m][t][half * 2 + 1];
                *(float2*)(Cf + (size_t)row * ldc + col) = o2;
            }
        }
    }
}

// ======================= split producers =======================
__global__ void wsplit_kernel(const float* __restrict__ x, bf16* __restrict__ dst,
                              size_t plane, size_t n4) {
    size_t i = (size_t)blockIdx.x * 256 + threadIdx.x;
    if (i >= n4) return;
    float4 v = ((const float4*)x)[i];
    union { bf16 b[4]; uint2 u2; } H, M, L;
    split3(v.x, H.b[0], M.b[0], L.b[0]); split3(v.y, H.b[1], M.b[1], L.b[1]);
    split3(v.z, H.b[2], M.b[2], L.b[2]); split3(v.w, H.b[3], M.b[3], L.b[3]);
    ((uint2*)dst)[i] = H.u2;
    ((uint2*)(dst + plane))[i] = M.u2;
    ((uint2*)(dst + 2 * plane))[i] = L.u2;
}

__global__ void rmsnorm_split_kernel(const float* __restrict__ x, const float* __restrict__ w,
                                     bf16* __restrict__ dst, size_t elts, int cols) {
    int row = blockIdx.x;
    const float* xr = x + (size_t)row * cols;
    float ss = 0.f;
    for (int c = threadIdx.x; c < cols; c += 256) { float v = xr[c]; ss += v * v; }
    ss = blockReduceSum256(ss);
    float inv = rsqrtf(ss / (float)cols + EPSF);
    for (int c = threadIdx.x; c < cols; c += 256) {
        float y = xr[c] * inv * (1.f + w[c]);
        bf16 h, m, l; split3(y, h, m, l);
        size_t o = (size_t)row * cols + c;
        dst[o] = h; dst[elts + o] = m; dst[2 * elts + o] = l;
    }
}

// reads fused [g|u] buffer (row stride 8192)
__global__ void gelu_mul_split_kernel(const float* __restrict__ gu,
                                      bf16* __restrict__ dst, size_t elts, int n) {
    int i = blockIdx.x * 256 + threadIdx.x;
    if (i < n) {
        int row = i >> 12, j = i & 4095;
        float g = gu[(size_t)row * 8192 + j];
        float u = gu[(size_t)row * 8192 + 4096 + j];
        float y = gelu_tanh(g) * u;
        bf16 h, m, l; split3(y, h, m, l);
        dst[i] = h; dst[elts + i] = m; dst[2 * elts + i] = l;
    }
}

__global__ void gelu_sl_split_kernel(const float* __restrict__ g, const float* __restrict__ plc,
                                     int li, bf16* __restrict__ dst, size_t elts) {
    int i = blockIdx.x * 256 + threadIdx.x;
    if (i < N_TOK * HPL) {
        int n = i >> 8, j = i & 255;
        float y = gelu_tanh(g[i]) * plc[(size_t)n * (TOTAL_LAYERS * HPL) + (size_t)li * HPL + j];
        bf16 h, m, l; split3(y, h, m, l);
        dst[i] = h; dst[elts + i] = m; dst[2 * elts + i] = l;
    }
}

// ======================= driver =======================
extern "C" void kernel_launch(void* const* d_in, const int* in_sizes, int n_in,
                              void* d_out, int out_size) {
    const float* hidden = (const float*)d_in[0];
    const float* plc    = (const float*)d_in[1];
    const float* cos_s  = (const float*)d_in[3];
    const float* sin_s  = (const float*)d_in[4];
    const float* cos_f  = (const float*)d_in[5];
    const float* sin_f  = (const float*)d_in[6];
    const float* Wq     = (const float*)d_in[7];
    const float* Wk     = (const float*)d_in[8];
    const float* Wv     = (const float*)d_in[9];
    const float* Wo     = (const float*)d_in[10];
    const float* Wg     = (const float*)d_in[11];
    const float* Wu     = (const float*)d_in[12];
    const float* Wd     = (const float*)d_in[13];
    const float* Wplg   = (const float*)d_in[14];
    const float* Wplp   = (const float*)d_in[15];
    const float* ln_in  = (const float*)d_in[16];
    const float* ln_pa  = (const float*)d_in[17];
    const float* ln_pf  = (const float*)d_in[18];
    const float* ln_ff  = (const float*)d_in[19];
    const float* ln_pl  = (const float*)d_in[20];
    const float* qn_w   = (const float*)d_in[21];
    const float* kn_w   = (const float*)d_in[22];
    const float* lscale = (const float*)d_in[23];

    cudaFuncSetAttribute(mma_gemm, cudaFuncAttributeMaxDynamicSharedMemorySize, GSMEM);

    char* scr = nullptr;
    cudaGetSymbolAddress((void**)&scr, g_scr);

    bf16* wqkv3 = (bf16*)(scr + OFF_WQKV);
    bf16* wo3   = (bf16*)(scr + OFF_WO3);
    bf16* wgu3  = (bf16*)(scr + OFF_WGU);
    bf16* wd3   = (bf16*)(scr + OFF_WD3);
    bf16* wplg3 = (bf16*)(scr + OFF_WPLG3);
    bf16* wplp3 = (bf16*)(scr + OFF_WPLP3);

    float* hs     = (float*)(scr + OFF_HS);
    float* qkvraw = (float*)(scr + OFF_QKVRAW);
    float* scores = (float*)(scr + OFF_SC);
    float* ao     = (float*)(scr + OFF_AO);
    float* tmp    = (float*)(scr + OFF_TMP);
    float* gu     = (float*)(scr + OFF_GU);
    float* plbuf  = (float*)(scr + OFF_PLB);
    bf16*  h2     = (bf16*)(scr + OFF_H2);
    bf16*  qt3    = (bf16*)(scr + OFF_QT3);
    bf16*  kt3    = (bf16*)(scr + OFF_KT3);
    bf16*  vt3    = (bf16*)(scr + OFF_VT3);
    bf16*  p3     = (bf16*)(scr + OFF_P3);
    bf16*  ao3    = (bf16*)(scr + OFF_AO3);
    bf16*  m2     = (bf16*)(scr + OFF_M2);
    bf16*  hs3    = (bf16*)(scr + OFF_HS3);
    bf16*  pl3    = (bf16*)(scr + OFF_PL3);

    float* out = (float*)d_out;

    // ---- split weights into fused 3-plane layouts (once per call) ----
    auto wsplit = [&](const float* src, bf16* dst, size_t plane, size_t count) {
        size_t n4 = count / 4;
        wsplit_kernel<<<(unsigned)((n4 + 255) / 256), 256>>>(src, dst, plane, n4);
    };
    for (int i = 0; i < NLAYER; i++) {
        const size_t lq = (size_t)i * 2048 * 2048;
        const size_t lk = (size_t)i * 512 * 2048;
        bf16* dst = wqkv3 + (size_t)i * 3072 * 2048;
        wsplit(Wq + lq, dst,               E_QKV, (size_t)2048 * 2048);
        wsplit(Wk + lk, dst + 2048 * 2048, E_QKV, (size_t)512 * 2048);
        wsplit(Wv + lk, dst + 2560 * 2048, E_QKV, (size_t)512 * 2048);

        const size_t lg = (size_t)i * 4096 * 2048;
        bf16* dgu = wgu3 + (size_t)i * 8192 * 2048;
        wsplit(Wg + lg, dgu,               E_GU, (size_t)4096 * 2048);
        wsplit(Wu + lg, dgu + 4096 * 2048, E_GU, (size_t)4096 * 2048);
    }
    wsplit(Wo,   wo3,   E_WO,  E_WO);
    wsplit(Wd,   wd3,   E_WD,  E_WD);
    wsplit(Wplg, wplg3, E_WPL, E_WPL);
    wsplit(Wplp, wplp3, E_WPL, E_WPL);

    cudaMemcpyAsync(hs, hidden, (size_t)N_TOK * DMODEL * sizeof(float), cudaMemcpyDeviceToDevice, 0);

    for (int i = 0; i < NLAYER; i++) {
        const int li = STARTL + i;
        const bool full = ((li + 1) % 5) == 0;
        const float* cost = full ? cos_f : cos_s;
        const float* sint = full ? sin_f : sin_s;
        float* Kout = out + (size_t)N_TOK * DMODEL + (size_t)i * 2 * NKV * N_TOK * HDIM;
        float* Vout = Kout + (size_t)NKV * N_TOK * HDIM;

        // ---- pre-attention norm + fused QKV (mma) ----
        rmsnorm_split_kernel<<<N_TOK, 256>>>(hs, ln_in + (size_t)i * DMODEL, h2, E_H2, DMODEL);
        mma_gemm<<<dim3(3072 / 128, 8), 256, GSMEM>>>(
            h2, wqkv3 + (size_t)i * 3072 * 2048, (long long)E_H2, (long long)E_QKV,
            qkvraw, DMODEL, 3072, 0, 0, 0, 0);

        rope_norm_split_kernel<<<dim3(N_TOK, NH),  256>>>(qkvraw,        3072, qn_w + (size_t)i * HDIM,
                                                          cost, sint, nullptr, qt3, E_QT);
        rope_norm_split_kernel<<<dim3(N_TOK, NKV), 256>>>(qkvraw + 2048, 3072, kn_w + (size_t)i * HDIM,
                                                          cost, sint, Kout, kt3, E_KT);
        vnorm_split_kernel<<<dim3(N_TOK, NKV), 256>>>(qkvraw + 2560, 3072, Vout, vt3, E_KT);

        // ---- attention on mma (dual-acc): scores = q @ K^T (mask via causal softmax) ----
        mma_gemm<<<dim3(N_TOK / 128, N_TOK / 128, NH), 256, GSMEM>>>(
            qt3, kt3, (long long)E_QT, (long long)E_KT, scores, HDIM, N_TOK,
            (long long)N_TOK * HDIM, (long long)N_TOK * HDIM, (long long)N_TOK * N_TOK, 2);
        softmax_causal_split_kernel<<<NH * N_TOK, 256>>>(scores, p3, E_P3);
        // ao = P @ V  (B = transposed V planes, K-contiguous over tokens)
        mma_gemm<<<dim3(HDIM / 128, N_TOK / 128, NH), 256, GSMEM>>>(
            p3, vt3, (long long)E_P3, (long long)E_KT, ao, N_TOK, NH * HDIM,
            (long long)N_TOK * N_TOK, (long long)HDIM * N_TOK, (long long)HDIM, 2);

        // ---- Wo (mma) + residual ----
        wsplit_kernel<<<(unsigned)((E_AO / 4 + 255) / 256), 256>>>(ao, ao3, E_AO, E_AO / 4);
        mma_gemm<<<dim3(DMODEL / 128, 8), 256, GSMEM>>>(
            ao3, wo3 + (size_t)i * 2048 * 2048, (long long)E_AO, (long long)E_WO,
            tmp, NH * HDIM, DMODEL, 0, 0, 0, 0);
        add_rms_kernel<<<N_TOK, 256>>>(hs, tmp, ln_pa + (size_t)i * DMODEL, nullptr,
                                       nullptr, 0, DMODEL);

        // ---- FFN: fused G+U, gelu*u, Wd (mma) ----
        rmsnorm_split_kernel<<<N_TOK, 256>>>(hs, ln_pf + (size_t)i * DMODEL, h2, E_H2, DMODEL);
        mma_gemm<<<dim3(8192 / 128, 8), 256, GSMEM>>>(
            h2, wgu3 + (size_t)i * 8192 * 2048, (long long)E_H2, (long long)E_GU,
            gu, DMODEL, 8192, 0, 0, 0, 0);
        gelu_mul_split_kernel<<<(N_TOK * FFDIM + 255) / 256, 256>>>(gu, m2, E_M2, N_TOK * FFDIM);
        mma_gemm<<<dim3(DMODEL / 128, 8), 256, GSMEM>>>(
            m2, wd3 + (size_t)i * 2048 * 4096, (long long)E_M2, (long long)E_WD,
            tmp, FFDIM, DMODEL, 0, 0, 0, 0);
        add_rms_kernel<<<N_TOK, 256>>>(hs, tmp, ln_ff + (size_t)i * DMODEL, nullptr,
                                       hs3, E_H2, DMODEL);

        // ---- per-layer gating (mma) ----
        mma_gemm<<<dim3(HPL / 128, 8), 256, GSMEM>>>(
            hs3, wplg3 + (size_t)i * HPL * 2048, (long long)E_H2, (long long)E_WPL,
            plbuf, DMODEL, HPL, 0, 0, 0, 0);
        gelu_sl_split_kernel<<<(N_TOK * HPL + 255) / 256, 256>>>(plbuf, plc, li, pl3, E_PL);
        mma_gemm<<<dim3(DMODEL / 128, 8), 256, GSMEM>>>(
            pl3, wplp3 + (size_t)i * 2048 * HPL, (long long)E_PL, (long long)E_WPL,
            tmp, HPL, DMODEL, 0, 0, 0, 0);
        add_rms_kernel<<<N_TOK, 256>>>(hs, tmp, ln_pl + (size_t)i * DMODEL, lscale + i,
                                       nullptr, 0, DMODEL);
    }

    cudaMemcpyAsync(out, hs, (size_t)N_TOK * DMODEL * sizeof(float), cudaMemcpyDeviceToDevice, 0);
}

// round 11
// speedup vs baseline: 3.1651x; 1.6047x over previous
#include <cuda_runtime.h>
#include <cuda_fp16.h>
#include <math.h>
#include <stdint.h>

#define N_TOK 1024
#define DMODEL 2048
#define NH 8
#define NKV 2
#define HDIM 256
#define FFDIM 4096
#define HPL 256
#define NLAYER 7
#define STARTL 8
#define TOTAL_LAYERS 30
#define EPSF 1e-6f
#define SPLIT_SCALE 2048.f
#define SPLIT_INV   (1.f / 2048.f)

typedef __half fp16;

// ======================= plane sizes (elements) =======================
#define E_QKV ((size_t)NLAYER * 3072 * DMODEL)
#define E_WO  ((size_t)NLAYER * DMODEL * (NH * HDIM))
#define E_GU  ((size_t)NLAYER * 8192 * DMODEL)
#define E_WD  ((size_t)NLAYER * DMODEL * FFDIM)
#define E_WPL ((size_t)NLAYER * HPL * DMODEL)
#define E_H2  ((size_t)N_TOK * DMODEL)
#define E_QT  ((size_t)N_TOK * NH * HDIM)
#define E_KT  ((size_t)N_TOK * NKV * HDIM)
#define E_P3  ((size_t)NH * N_TOK * N_TOK)
#define E_AO  ((size_t)N_TOK * NH * HDIM)
#define E_M2  ((size_t)N_TOK * FFDIM)
#define E_PL  ((size_t)N_TOK * HPL)

// ======================= scratch layout (bytes; 2 planes x 2B = 4B/elt) =======================
#define OFF_WQKV  ((size_t)0)
#define OFF_WO3   (OFF_WQKV + 4 * E_QKV)
#define OFF_WGU   (OFF_WO3  + 4 * E_WO)
#define OFF_WD3   (OFF_WGU  + 4 * E_GU)
#define OFF_WPLG3 (OFF_WD3  + 4 * E_WD)
#define OFF_WPLP3 (OFF_WPLG3 + 4 * E_WPL)
// fp32 activations
#define OFF_HS     (OFF_WPLP3 + 4 * E_WPL)
#define OFF_QKVRAW (OFF_HS     + 4ull * N_TOK * DMODEL)
#define OFF_SC     (OFF_QKVRAW + 4ull * N_TOK * 3072)
#define OFF_AO     (OFF_SC     + 4ull * E_P3)
#define OFF_TMP    (OFF_AO     + 4ull * E_AO)
#define OFF_GU     (OFF_TMP    + 4ull * N_TOK * DMODEL)
#define OFF_PLB    (OFF_GU     + 4ull * N_TOK * 8192)
// fp16 2-plane activations
#define OFF_H2     (OFF_PLB + 4ull * E_PL)
#define OFF_QT3    (OFF_H2  + 4ull * E_H2)
#define OFF_KT3    (OFF_QT3 + 4ull * E_QT)
#define OFF_VT3    (OFF_KT3 + 4ull * E_KT)
#define OFF_P3     (OFF_VT3 + 4ull * E_KT)
#define OFF_AO3    (OFF_P3  + 4ull * E_P3)
#define OFF_M2     (OFF_AO3 + 4ull * E_AO)
#define OFF_HS3    (OFF_M2  + 4ull * E_M2)
#define OFF_PL3    (OFF_HS3 + 4ull * E_H2)
#define TOTAL_SCR  (OFF_PL3 + 4ull * E_PL)

__device__ __align__(1024) char g_scr[TOTAL_SCR];

// ======================= block reductions =======================
__device__ __forceinline__ float blockReduceSum256(float v) {
    __shared__ float sh[8]; __shared__ float res;
    int lane = threadIdx.x & 31, wid = threadIdx.x >> 5;
    #pragma unroll
    for (int o = 16; o > 0; o >>= 1) v += __shfl_xor_sync(0xffffffffu, v, o);
    if (lane == 0) sh[wid] = v;
    __syncthreads();
    if (wid == 0) {
        float x = (lane < 8) ? sh[lane] : 0.f;
        #pragma unroll
        for (int o = 4; o > 0; o >>= 1) x += __shfl_xor_sync(0xffffffffu, x, o);
        if (lane == 0) res = x;
    }
    __syncthreads();
    return res;
}
__device__ __forceinline__ float blockReduceMax256(float v) {
    __shared__ float sh[8]; __shared__ float res;
    int lane = threadIdx.x & 31, wid = threadIdx.x >> 5;
    #pragma unroll
    for (int o = 16; o > 0; o >>= 1) v = fmaxf(v, __shfl_xor_sync(0xffffffffu, v, o));
    if (lane == 0) sh[wid] = v;
    __syncthreads();
    if (wid == 0) {
        float x = (lane < 8) ? sh[lane] : -INFINITY;
        #pragma unroll
        for (int o = 4; o > 0; o >>= 1) x = fmaxf(x, __shfl_xor_sync(0xffffffffu, x, o));
        if (lane == 0) res = x;
    }
    __syncthreads();
    return res;
}
__device__ __forceinline__ float gelu_tanh(float x) {
    float t = tanhf(0.7978845608028654f * (x + 0.044715f * x * x * x));
    return 0.5f * x * (1.f + t);
}
// scaled fp16 2-way split: v ~= h + l*(1/2048), l' normalized into fp16's sweet spot
__device__ __forceinline__ void split2h(float v, fp16& h, fp16& l) {
    h = __float2half_rn(v);
    l = __float2half_rn((v - __half2float(h)) * SPLIT_SCALE);
}

// ======================= norm / elementwise kernels =======================
__global__ void add_rms_kernel(float* __restrict__ hs, const float* __restrict__ x,
                               const float* __restrict__ w,
                               const float* __restrict__ scale_ptr,
                               fp16* __restrict__ dst, size_t elts, int cols) {
    int row = blockIdx.x;
    const float* xr = x + (size_t)row * cols;
    float ss = 0.f;
    for (int c = threadIdx.x; c < cols; c += 256) { float v = xr[c]; ss += v * v; }
    ss = blockReduceSum256(ss);
    float inv = rsqrtf(ss / (float)cols + EPSF);
    float sc = scale_ptr ? *scale_ptr : 1.f;
    float* hr = hs + (size_t)row * cols;
    for (int c = threadIdx.x; c < cols; c += 256) {
        float y = (hr[c] + xr[c] * inv * (1.f + w[c])) * sc;
        hr[c] = y;
        if (dst) {
            fp16 h, l; split2h(y, h, l);
            size_t o = (size_t)row * cols + c;
            dst[o] = h; dst[elts + o] = l;
        }
    }
}

__global__ void rope_norm_split_kernel(const float* __restrict__ x, int ldx,
                                       const float* __restrict__ w,
                                       const float* __restrict__ cost, const float* __restrict__ sint,
                                       float* __restrict__ f32out,
                                       fp16* __restrict__ dst, size_t elts) {
    int n = blockIdx.x, h = blockIdx.y, d = threadIdx.x;
    __shared__ float sx[HDIM];
    float v = x[(size_t)n * ldx + h * HDIM + d];
    float ss = blockReduceSum256(v * v);
    float inv = rsqrtf(ss / (float)HDIM + EPSF);
    float xn = v * inv * (1.f + w[d]);
    sx[d] = xn;
    __syncthreads();
    float rh = (d < HDIM / 2) ? -sx[d + HDIM / 2] : sx[d - HDIM / 2];
    float y = xn * cost[(size_t)n * HDIM + d] + rh * sint[(size_t)n * HDIM + d];
    size_t idx = ((size_t)h * N_TOK + n) * HDIM + d;
    if (f32out) f32out[idx] = y;
    fp16 bh, bl; split2h(y, bh, bl);
    dst[idx] = bh; dst[elts + idx] = bl;
}

__global__ void vnorm_split_kernel(const float* __restrict__ x, int ldx,
                                   float* __restrict__ f32out,
                                   fp16* __restrict__ dst, size_t elts) {
    int n = blockIdx.x, h = blockIdx.y, d = threadIdx.x;
    float v = x[(size_t)n * ldx + h * HDIM + d];
    float ss = blockReduceSum256(v * v);
    float y = v * rsqrtf(ss / (float)HDIM + EPSF);
    f32out[((size_t)h * N_TOK + n) * HDIM + d] = y;
    fp16 bh, bl; split2h(y, bh, bl);
    size_t tidx = ((size_t)h * HDIM + d) * N_TOK + n;
    dst[tidx] = bh; dst[elts + tidx] = bl;
}

// causal softmax over rows of 1024 (exp(-1e9-max) underflows to exactly 0 in fp32)
__global__ void softmax_causal_split_kernel(const float* __restrict__ p,
                                            fp16* __restrict__ dst, size_t elts) {
    const float* row = p + (size_t)blockIdx.x * N_TOK;
    const int r = blockIdx.x & (N_TOK - 1);
    int base = threadIdx.x * 4;
    float4 r4 = *(const float4*)(row + base);
    float v[4] = {r4.x, r4.y, r4.z, r4.w};
    float m = -INFINITY;
    #pragma unroll
    for (int i = 0; i < 4; i++) if (base + i <= r) m = fmaxf(m, v[i]);
    m = blockReduceMax256(m);
    float e[4];
    #pragma unroll
    for (int i = 0; i < 4; i++) e[i] = (base + i <= r) ? expf(v[i] - m) : 0.f;
    float s = blockReduceSum256(e[0] + e[1] + e[2] + e[3]);
    float invs = 1.f / s;
    union { fp16 b[4]; uint2 u2; } H, L;
    #pragma unroll
    for (int i = 0; i < 4; i++) split2h(e[i] * invs, H.b[i], L.b[i]);
    size_t o = (size_t)blockIdx.x * N_TOK + base;
    *(uint2*)(dst + o) = H.u2;
    *(uint2*)(dst + elts + o) = L.u2;
}

// ======================= fp16x2 mma machinery =======================
__device__ __forceinline__ uint32_t smem_u32(const void* p) {
    uint32_t a;
    asm("{ .reg .u64 t; cvta.to.shared.u64 t, %1; cvt.u32.u64 %0, t; }" : "=r"(a) : "l"(p));
    return a;
}
__device__ __forceinline__ void cp16(uint32_t dst, const void* src) {
    asm volatile("cp.async.cg.shared.global [%0], [%1], 16;" :: "r"(dst), "l"(src) : "memory");
}
__device__ __forceinline__ void ldsm4(uint32_t* r, uint32_t addr) {
    asm volatile("ldmatrix.sync.aligned.m8n8.x4.shared.b16 {%0,%1,%2,%3}, [%4];"
                 : "=r"(r[0]), "=r"(r[1]), "=r"(r[2]), "=r"(r[3]) : "r"(addr));
}
__device__ __forceinline__ void mma_f16(float* d, const uint32_t* a, const uint32_t* b) {
    asm volatile(
        "mma.sync.aligned.m16n8k16.row.col.f32.f16.f16.f32 "
        "{%0,%1,%2,%3}, {%4,%5,%6,%7}, {%8,%9}, {%0,%1,%2,%3};"
        : "+f"(d[0]), "+f"(d[1]), "+f"(d[2]), "+f"(d[3])
        : "r"(a[0]), "r"(a[1]), "r"(a[2]), "r"(a[3]), "r"(b[0]), "r"(b[1]));
}

#define TROWB 80
#define TILE_BYTES (128 * TROWB)
#define STG_BYTES  (4 * TILE_BYTES)   // 40960 (Ah, Al, Bh, Bl)
#define GSMEM      (3 * STG_BYTES)    // 122880 (3-stage)

// C[z] tile = A[z](rows x K) @ B[z>>bshift](M x K)^T ; A,B fp16 2-plane (scaled split).
// accM: hh; accC: hl'+l'h (scaled by 2048); epilogue: accM + accC/2048.
__global__ void __launch_bounds__(256, 1)
mma_gemm(const fp16* __restrict__ A3, const fp16* __restrict__ B3,
         long long eA, long long eB,
         float* __restrict__ Cf, int K, int ldc,
         long long sA, long long sB, long long sC, int bshift) {
    extern __shared__ char smem[];
    const uint32_t sb = smem_u32(smem);
    const int tid = threadIdx.x;
    const int bz = blockIdx.z;
    const int row0 = blockIdx.y * 128;
    const int col0 = blockIdx.x * 128;
    Cf += (size_t)bz * sC;

    const fp16* srcs[4];
    #pragma unroll
    for (int p = 0; p < 2; p++) {
        srcs[p]     = A3 + (size_t)p * eA + (size_t)bz * sA + (size_t)row0 * K;
        srcs[2 + p] = B3 + (size_t)p * eB + (size_t)(bz >> bshift) * sB + (size_t)col0 * K;
    }

    const int lane = tid & 31, wid = tid >> 5;
    const int wm = wid & 3, wn = wid >> 2;
    const int ld_r = tid >> 2;
    const int ld_c = tid & 3;

    uint32_t aoff[2], boff[4];
    #pragma unroll
    for (int m = 0; m < 2; m++)
        aoff[m] = (uint32_t)((wm * 32 + m * 16 + (lane & 15)) * TROWB + ((lane >> 4) << 4));
    #pragma unroll
    for (int j = 0; j < 4; j++)
        boff[j] = (uint32_t)((wn * 64 + j * 16 + (lane & 7) + ((lane >> 4) << 3)) * TROWB
                             + (((lane >> 3) & 1) << 4));

    float accM[2][8][4], accC[2][8][4];
    #pragma unroll
    for (int m = 0; m < 2; m++)
        #pragma unroll
        for (int t = 0; t < 8; t++)
            #pragma unroll
            for (int u = 0; u < 4; u++) { accM[m][t][u] = 0.f; accC[m][t][u] = 0.f; }

    const int nch = K >> 5;

    auto issue = [&](int c, uint32_t dstb) {
        const int kb = c << 5;
        #pragma unroll
        for (int q = 0; q < 8; q++) {
            const int r = (q & 1) * 64 + ld_r;
            const char* gsrc = (const char*)(srcs[q >> 1] + (size_t)r * K + kb) + ld_c * 16;
            cp16(dstb + (uint32_t)((q >> 1) * TILE_BYTES + r * TROWB + ld_c * 16), gsrc);
        }
        asm volatile("cp.async.commit_group;" ::: "memory");
    };

    issue(0, sb);
    if (nch > 1) issue(1, sb + STG_BYTES);
    if (nch > 2) issue(2, sb + 2 * STG_BYTES);

    int stage = 0;
    for (int c = 0; c < nch; ++c) {
        const int rem = nch - 1 - c;
        if (rem >= 2)      asm volatile("cp.async.wait_group 2;" ::: "memory");
        else if (rem == 1) asm volatile("cp.async.wait_group 1;" ::: "memory");
        else               asm volatile("cp.async.wait_group 0;" ::: "memory");
        __syncthreads();

        const uint32_t base = sb + (uint32_t)stage * STG_BYTES;

        #pragma unroll
        for (int kk = 0; kk < 2; kk++) {
            const uint32_t kb = kk * 32;
            uint32_t ah[2][4], al[2][4];
            #pragma unroll
            for (int m = 0; m < 2; m++) {
                ldsm4(ah[m], base + 0 * TILE_BYTES + aoff[m] + kb);
                ldsm4(al[m], base + 1 * TILE_BYTES + aoff[m] + kb);
            }
            #pragma unroll
            for (int j = 0; j < 4; j++) {
                uint32_t bh[4], bl[4];
                ldsm4(bh, base + 2 * TILE_BYTES + boff[j] + kb);
                ldsm4(bl, base + 3 * TILE_BYTES + boff[j] + kb);
                #pragma unroll
                for (int m = 0; m < 2; m++) {
                    #pragma unroll
                    for (int h = 0; h < 2; h++) {
                        float* dM = accM[m][j * 2 + h];
                        float* dC = accC[m][j * 2 + h];
                        mma_f16(dM, ah[m], &bh[h * 2]);   // hh -> main
                        mma_f16(dC, ah[m], &bl[h * 2]);   // h*l' + l'*h -> corr (x2048)
                        mma_f16(dC, al[m], &bh[h * 2]);
                    }
                }
            }
        }
        __syncthreads();
        if (c + 3 < nch) issue(c + 3, base);
        stage = (stage == 2) ? 0 : stage + 1;
    }

    const int grp = lane >> 2, qd = lane & 3;
    #pragma unroll
    for (int m = 0; m < 2; m++) {
        #pragma unroll
        for (int t = 0; t < 8; t++) {
            const int col = col0 + wn * 64 + t * 8 + qd * 2;
            #pragma unroll
            for (int half = 0; half < 2; half++) {
                const int row = row0 + wm * 32 + m * 16 + grp + half * 8;
                float2 o2;
                o2.x = accM[m][t][half * 2 + 0] + accC[m][t][half * 2 + 0] * SPLIT_INV;
                o2.y = accM[m][t][half * 2 + 1] + accC[m][t][half * 2 + 1] * SPLIT_INV;
                *(float2*)(Cf + (size_t)row * ldc + col) = o2;
            }
        }
    }
}

// ======================= split producers =======================
__global__ void wsplit_kernel(const float* __restrict__ x, fp16* __restrict__ dst,
                              size_t plane, size_t n4) {
    size_t i = (size_t)blockIdx.x * 256 + threadIdx.x;
    if (i >= n4) return;
    float4 v = ((const float4*)x)[i];
    union { fp16 b[4]; uint2 u2; } H, L;
    split2h(v.x, H.b[0], L.b[0]); split2h(v.y, H.b[1], L.b[1]);
    split2h(v.z, H.b[2], L.b[2]); split2h(v.w, H.b[3], L.b[3]);
    ((uint2*)dst)[i] = H.u2;
    ((uint2*)(dst + plane))[i] = L.u2;
}

__global__ void rmsnorm_split_kernel(const float* __restrict__ x, const float* __restrict__ w,
                                     fp16* __restrict__ dst, size_t elts, int cols) {
    int row = blockIdx.x;
    const float* xr = x + (size_t)row * cols;
    float ss = 0.f;
    for (int c = threadIdx.x; c < cols; c += 256) { float v = xr[c]; ss += v * v; }
    ss = blockReduceSum256(ss);
    float inv = rsqrtf(ss / (float)cols + EPSF);
    for (int c = threadIdx.x; c < cols; c += 256) {
        float y = xr[c] * inv * (1.f + w[c]);
        fp16 h, l; split2h(y, h, l);
        size_t o = (size_t)row * cols + c;
        dst[o] = h; dst[elts + o] = l;
    }
}

// reads fused [g|u] buffer (row stride 8192)
__global__ void gelu_mul_split_kernel(const float* __restrict__ gu,
                                      fp16* __restrict__ dst, size_t elts, int n) {
    int i = blockIdx.x * 256 + threadIdx.x;
    if (i < n) {
        int row = i >> 12, j = i & 4095;
        float g = gu[(size_t)row * 8192 + j];
        float u = gu[(size_t)row * 8192 + 4096 + j];
        float y = gelu_tanh(g) * u;
        fp16 h, l; split2h(y, h, l);
        dst[i] = h; dst[elts + i] = l;
    }
}

__global__ void gelu_sl_split_kernel(const float* __restrict__ g, const float* __restrict__ plc,
                                     int li, fp16* __restrict__ dst, size_t elts) {
    int i = blockIdx.x * 256 + threadIdx.x;
    if (i < N_TOK * HPL) {
        int n = i >> 8, j = i & 255;
        float y = gelu_tanh(g[i]) * plc[(size_t)n * (TOTAL_LAYERS * HPL) + (size_t)li * HPL + j];
        fp16 h, l; split2h(y, h, l);
        dst[i] = h; dst[elts + i] = l;
    }
}

// ======================= driver =======================
extern "C" void kernel_launch(void* const* d_in, const int* in_sizes, int n_in,
                              void* d_out, int out_size) {
    const float* hidden = (const float*)d_in[0];
    const float* plc    = (const float*)d_in[1];
    const float* cos_s  = (const float*)d_in[3];
    const float* sin_s  = (const float*)d_in[4];
    const float* cos_f  = (const float*)d_in[5];
    const float* sin_f  = (const float*)d_in[6];
    const float* Wq     = (const float*)d_in[7];
    const float* Wk     = (const float*)d_in[8];
    const float* Wv     = (const float*)d_in[9];
    const float* Wo     = (const float*)d_in[10];
    const float* Wg     = (const float*)d_in[11];
    const float* Wu     = (const float*)d_in[12];
    const float* Wd     = (const float*)d_in[13];
    const float* Wplg   = (const float*)d_in[14];
    const float* Wplp   = (const float*)d_in[15];
    const float* ln_in  = (const float*)d_in[16];
    const float* ln_pa  = (const float*)d_in[17];
    const float* ln_pf  = (const float*)d_in[18];
    const float* ln_ff  = (const float*)d_in[19];
    const float* ln_pl  = (const float*)d_in[20];
    const float* qn_w   = (const float*)d_in[21];
    const float* kn_w   = (const float*)d_in[22];
    const float* lscale = (const float*)d_in[23];

    cudaFuncSetAttribute(mma_gemm, cudaFuncAttributeMaxDynamicSharedMemorySize, GSMEM);

    char* scr = nullptr;
    cudaGetSymbolAddress((void**)&scr, g_scr);

    fp16* wqkv3 = (fp16*)(scr + OFF_WQKV);
    fp16* wo3   = (fp16*)(scr + OFF_WO3);
    fp16* wgu3  = (fp16*)(scr + OFF_WGU);
    fp16* wd3   = (fp16*)(scr + OFF_WD3);
    fp16* wplg3 = (fp16*)(scr + OFF_WPLG3);
    fp16* wplp3 = (fp16*)(scr + OFF_WPLP3);

    float* hs     = (float*)(scr + OFF_HS);
    float* qkvraw = (float*)(scr + OFF_QKVRAW);
    float* scores = (float*)(scr + OFF_SC);
    float* ao     = (float*)(scr + OFF_AO);
    float* tmp    = (float*)(scr + OFF_TMP);
    float* gu     = (float*)(scr + OFF_GU);
    float* plbuf  = (float*)(scr + OFF_PLB);
    fp16*  h2     = (fp16*)(scr + OFF_H2);
    fp16*  qt3    = (fp16*)(scr + OFF_QT3);
    fp16*  kt3    = (fp16*)(scr + OFF_KT3);
    fp16*  vt3    = (fp16*)(scr + OFF_VT3);
    fp16*  p3     = (fp16*)(scr + OFF_P3);
    fp16*  ao3    = (fp16*)(scr + OFF_AO3);
    fp16*  m2     = (fp16*)(scr + OFF_M2);
    fp16*  hs3    = (fp16*)(scr + OFF_HS3);
    fp16*  pl3    = (fp16*)(scr + OFF_PL3);

    float* out = (float*)d_out;

    // ---- split weights into fused 2-plane layouts (once per call) ----
    auto wsplit = [&](const float* src, fp16* dst, size_t plane, size_t count) {
        size_t n4 = count / 4;
        wsplit_kernel<<<(unsigned)((n4 + 255) / 256), 256>>>(src, dst, plane, n4);
    };
    for (int i = 0; i < NLAYER; i++) {
        const size_t lq = (size_t)i * 2048 * 2048;
        const size_t lk = (size_t)i * 512 * 2048;
        fp16* dst = wqkv3 + (size_t)i * 3072 * 2048;
        wsplit(Wq + lq, dst,               E_QKV, (size_t)2048 * 2048);
        wsplit(Wk + lk, dst + 2048 * 2048, E_QKV, (size_t)512 * 2048);
        wsplit(Wv + lk, dst + 2560 * 2048, E_QKV, (size_t)512 * 2048);

        const size_t lg = (size_t)i * 4096 * 2048;
        fp16* dgu = wgu3 + (size_t)i * 8192 * 2048;
        wsplit(Wg + lg, dgu,               E_GU, (size_t)4096 * 2048);
        wsplit(Wu + lg, dgu + 4096 * 2048, E_GU, (size_t)4096 * 2048);
    }
    wsplit(Wo,   wo3,   E_WO,  E_WO);
    wsplit(Wd,   wd3,   E_WD,  E_WD);
    wsplit(Wplg, wplg3, E_WPL, E_WPL);
    wsplit(Wplp, wplp3, E_WPL, E_WPL);

    cudaMemcpyAsync(hs, hidden, (size_t)N_TOK * DMODEL * sizeof(float), cudaMemcpyDeviceToDevice, 0);

    for (int i = 0; i < NLAYER; i++) {
        const int li = STARTL + i;
        const bool full = ((li + 1) % 5) == 0;
        const float* cost = full ? cos_f : cos_s;
        const float* sint = full ? sin_f : sin_s;
        float* Kout = out + (size_t)N_TOK * DMODEL + (size_t)i * 2 * NKV * N_TOK * HDIM;
        float* Vout = Kout + (size_t)NKV * N_TOK * HDIM;

        // ---- pre-attention norm + fused QKV (mma) ----
        rmsnorm_split_kernel<<<N_TOK, 256>>>(hs, ln_in + (size_t)i * DMODEL, h2, E_H2, DMODEL);
        mma_gemm<<<dim3(3072 / 128, 8), 256, GSMEM>>>(
            h2, wqkv3 + (size_t)i * 3072 * 2048, (long long)E_H2, (long long)E_QKV,
            qkvraw, DMODEL, 3072, 0, 0, 0, 0);

        rope_norm_split_kernel<<<dim3(N_TOK, NH),  256>>>(qkvraw,        3072, qn_w + (size_t)i * HDIM,
                                                          cost, sint, nullptr, qt3, E_QT);
        rope_norm_split_kernel<<<dim3(N_TOK, NKV), 256>>>(qkvraw + 2048, 3072, kn_w + (size_t)i * HDIM,
                                                          cost, sint, Kout, kt3, E_KT);
        vnorm_split_kernel<<<dim3(N_TOK, NKV), 256>>>(qkvraw + 2560, 3072, Vout, vt3, E_KT);

        // ---- attention (mma, dual-acc): scores = q @ K^T, causal softmax, P @ V ----
        mma_gemm<<<dim3(N_TOK / 128, N_TOK / 128, NH), 256, GSMEM>>>(
            qt3, kt3, (long long)E_QT, (long long)E_KT, scores, HDIM, N_TOK,
            (long long)N_TOK * HDIM, (long long)N_TOK * HDIM, (long long)N_TOK * N_TOK, 2);
        softmax_causal_split_kernel<<<NH * N_TOK, 256>>>(scores, p3, E_P3);
        mma_gemm<<<dim3(HDIM / 128, N_TOK / 128, NH), 256, GSMEM>>>(
            p3, vt3, (long long)E_P3, (long long)E_KT, ao, N_TOK, NH * HDIM,
            (long long)N_TOK * N_TOK, (long long)HDIM * N_TOK, (long long)HDIM, 2);

        // ---- Wo (mma) + residual ----
        wsplit_kernel<<<(unsigned)((E_AO / 4 + 255) / 256), 256>>>(ao, ao3, E_AO, E_AO / 4);
        mma_gemm<<<dim3(DMODEL / 128, 8), 256, GSMEM>>>(
            ao3, wo3 + (size_t)i * 2048 * 2048, (long long)E_AO, (long long)E_WO,
            tmp, NH * HDIM, DMODEL, 0, 0, 0, 0);
        add_rms_kernel<<<N_TOK, 256>>>(hs, tmp, ln_pa + (size_t)i * DMODEL, nullptr,
                                       nullptr, 0, DMODEL);

        // ---- FFN: fused G+U, gelu*u, Wd (mma) ----
        rmsnorm_split_kernel<<<N_TOK, 256>>>(hs, ln_pf + (size_t)i * DMODEL, h2, E_H2, DMODEL);
        mma_gemm<<<dim3(8192 / 128, 8), 256, GSMEM>>>(
            h2, wgu3 + (size_t)i * 8192 * 2048, (long long)E_H2, (long long)E_GU,
            gu, DMODEL, 8192, 0, 0, 0, 0);
        gelu_mul_split_kernel<<<(N_TOK * FFDIM + 255) / 256, 256>>>(gu, m2, E_M2, N_TOK * FFDIM);
        mma_gemm<<<dim3(DMODEL / 128, 8), 256, GSMEM>>>(
            m2, wd3 + (size_t)i * 2048 * 4096, (long long)E_M2, (long long)E_WD,
            tmp, FFDIM, DMODEL, 0, 0, 0, 0);
        add_rms_kernel<<<N_TOK, 256>>>(hs, tmp, ln_ff + (size_t)i * DMODEL, nullptr,
                                       hs3, E_H2, DMODEL);

        // ---- per-layer gating (mma) ----
        mma_gemm<<<dim3(HPL / 128, 8), 256, GSMEM>>>(
            hs3, wplg3 + (size_t)i * HPL * 2048, (long long)E_H2, (long long)E_WPL,
            plbuf, DMODEL, HPL, 0, 0, 0, 0);
        gelu_sl_split_kernel<<<(N_TOK * HPL + 255) / 256, 256>>>(plbuf, plc, li, pl3, E_PL);
        mma_gemm<<<dim3(DMODEL / 128, 8), 256, GSMEM>>>(
            pl3, wplp3 + (size_t)i * 2048 * HPL, (long long)E_PL, (long long)E_WPL,
            tmp, HPL, DMODEL, 0, 0, 0, 0);
        add_rms_kernel<<<N_TOK, 256>>>(hs, tmp, ln_pl + (size_t)i * DMODEL, lscale + i,
                                       nullptr, 0, DMODEL);
    }

    cudaMemcpyAsync(out, hs, (size_t)N_TOK * DMODEL * sizeof(float), cudaMemcpyDeviceToDevice, 0);
}

// round 12
// speedup vs baseline: 3.2598x; 1.0299x over previous
#include <cuda_runtime.h>
#include <cuda_fp16.h>
#include <math.h>
#include <stdint.h>

#define N_TOK 1024
#define DMODEL 2048
#define NH 8
#define NKV 2
#define HDIM 256
#define FFDIM 4096
#define HPL 256
#define NLAYER 7
#define STARTL 8
#define TOTAL_LAYERS 30
#define EPSF 1e-6f
#define SPLIT_SCALE 2048.f
#define SPLIT_INV   (1.f / 2048.f)

typedef __half fp16;

// ======================= plane sizes (elements) =======================
#define E_QKV ((size_t)NLAYER * 3072 * DMODEL)
#define E_WO  ((size_t)NLAYER * DMODEL * (NH * HDIM))
#define E_GU  ((size_t)NLAYER * 8192 * DMODEL)
#define E_WD  ((size_t)NLAYER * DMODEL * FFDIM)
#define E_WPL ((size_t)NLAYER * HPL * DMODEL)
#define E_H2  ((size_t)N_TOK * DMODEL)
#define E_QT  ((size_t)N_TOK * NH * HDIM)
#define E_KT  ((size_t)N_TOK * NKV * HDIM)
#define E_P3  ((size_t)NH * N_TOK * N_TOK)
#define E_AO  ((size_t)N_TOK * NH * HDIM)
#define E_M2  ((size_t)N_TOK * FFDIM)
#define E_PL  ((size_t)N_TOK * HPL)

// ======================= scratch layout (bytes) =======================
#define OFF_WQKV  ((size_t)0)
#define OFF_WO3   (OFF_WQKV + 4 * E_QKV)
#define OFF_WGU   (OFF_WO3  + 4 * E_WO)
#define OFF_WD3   (OFF_WGU  + 4 * E_GU)
#define OFF_WPLG3 (OFF_WD3  + 4 * E_WD)
#define OFF_WPLP3 (OFF_WPLG3 + 4 * E_WPL)
// fp32 activations
#define OFF_HS     (OFF_WPLP3 + 4 * E_WPL)
#define OFF_QKVRAW (OFF_HS     + 4ull * N_TOK * DMODEL)
#define OFF_SC     (OFF_QKVRAW + 4ull * N_TOK * 3072)
#define OFF_TMP    (OFF_SC     + 4ull * E_P3)
#define OFF_GU     (OFF_TMP    + 4ull * N_TOK * DMODEL)
#define OFF_PLB    (OFF_GU     + 4ull * N_TOK * 8192)
// fp16 2-plane activations
#define OFF_H2     (OFF_PLB + 4ull * E_PL)
#define OFF_QT3    (OFF_H2  + 4ull * E_H2)
#define OFF_KT3    (OFF_QT3 + 4ull * E_QT)
#define OFF_VT3    (OFF_KT3 + 4ull * E_KT)
#define OFF_P3     (OFF_VT3 + 4ull * E_KT)
#define OFF_AO3    (OFF_P3  + 4ull * E_P3)
#define OFF_M2     (OFF_AO3 + 4ull * E_AO)
#define OFF_HS3    (OFF_M2  + 4ull * E_M2)
#define OFF_PL3    (OFF_HS3 + 4ull * E_H2)
#define TOTAL_SCR  (OFF_PL3 + 4ull * E_PL)

__device__ __align__(1024) char g_scr[TOTAL_SCR];

// ======================= block reductions =======================
__device__ __forceinline__ float blockReduceSum256(float v) {
    __shared__ float sh[8]; __shared__ float res;
    int lane = threadIdx.x & 31, wid = threadIdx.x >> 5;
    #pragma unroll
    for (int o = 16; o > 0; o >>= 1) v += __shfl_xor_sync(0xffffffffu, v, o);
    if (lane == 0) sh[wid] = v;
    __syncthreads();
    if (wid == 0) {
        float x = (lane < 8) ? sh[lane] : 0.f;
        #pragma unroll
        for (int o = 4; o > 0; o >>= 1) x += __shfl_xor_sync(0xffffffffu, x, o);
        if (lane == 0) res = x;
    }
    __syncthreads();
    return res;
}
__device__ __forceinline__ float blockReduceMax256(float v) {
    __shared__ float sh[8]; __shared__ float res;
    int lane = threadIdx.x & 31, wid = threadIdx.x >> 5;
    #pragma unroll
    for (int o = 16; o > 0; o >>= 1) v = fmaxf(v, __shfl_xor_sync(0xffffffffu, v, o));
    if (lane == 0) sh[wid] = v;
    __syncthreads();
    if (wid == 0) {
        float x = (lane < 8) ? sh[lane] : -INFINITY;
        #pragma unroll
        for (int o = 4; o > 0; o >>= 1) x = fmaxf(x, __shfl_xor_sync(0xffffffffu, x, o));
        if (lane == 0) res = x;
    }
    __syncthreads();
    return res;
}
__device__ __forceinline__ float gelu_tanh(float x) {
    float t = tanhf(0.7978845608028654f * (x + 0.044715f * x * x * x));
    return 0.5f * x * (1.f + t);
}
__device__ __forceinline__ void split2h(float v, fp16& h, fp16& l) {
    h = __float2half_rn(v);
    l = __float2half_rn((v - __half2float(h)) * SPLIT_SCALE);
}

// ======================= norm / elementwise kernels =======================
// plain add_rms: hs = (hs + rms(x,w))*sc ; optional split of new hs
__global__ void add_rms_kernel(float* __restrict__ hs, const float* __restrict__ x,
                               const float* __restrict__ w,
                               const float* __restrict__ scale_ptr,
                               fp16* __restrict__ dst, size_t elts, int cols) {
    int row = blockIdx.x;
    const float* xr = x + (size_t)row * cols;
    float ss = 0.f;
    for (int c = threadIdx.x; c < cols; c += 256) { float v = xr[c]; ss += v * v; }
    ss = blockReduceSum256(ss);
    float inv = rsqrtf(ss / (float)cols + EPSF);
    float sc = scale_ptr ? *scale_ptr : 1.f;
    float* hr = hs + (size_t)row * cols;
    for (int c = threadIdx.x; c < cols; c += 256) {
        float y = (hr[c] + xr[c] * inv * (1.f + w[c])) * sc;
        hr[c] = y;
        if (dst) {
            fp16 h, l; split2h(y, h, l);
            size_t o = (size_t)row * cols + c;
            dst[o] = h; dst[elts + o] = l;
        }
    }
}

// fused: hs = (hs + rms(x,w1))*sc; then dst planes = split(rms(hs, w2))   (cols == 2048)
__global__ void add_rms_norm_kernel(float* __restrict__ hs, const float* __restrict__ x,
                                    const float* __restrict__ w1,
                                    const float* __restrict__ scale_ptr,
                                    const float* __restrict__ w2,
                                    fp16* __restrict__ dst, size_t elts) {
    const int cols = DMODEL;
    int row = blockIdx.x;
    const float* xr = x + (size_t)row * cols;
    float* hr = hs + (size_t)row * cols;
    float ss = 0.f;
    #pragma unroll
    for (int q = 0; q < 8; q++) { float v = xr[threadIdx.x + q * 256]; ss += v * v; }
    ss = blockReduceSum256(ss);
    float inv = rsqrtf(ss / (float)cols + EPSF);
    float sc = scale_ptr ? *scale_ptr : 1.f;
    float ys[8];
    float ss2 = 0.f;
    #pragma unroll
    for (int q = 0; q < 8; q++) {
        int c = threadIdx.x + q * 256;
        float y = (hr[c] + xr[c] * inv * (1.f + w1[c])) * sc;
        ys[q] = y; hr[c] = y; ss2 += y * y;
    }
    ss2 = blockReduceSum256(ss2);
    float inv2 = rsqrtf(ss2 / (float)cols + EPSF);
    #pragma unroll
    for (int q = 0; q < 8; q++) {
        int c = threadIdx.x + q * 256;
        float z = ys[q] * inv2 * (1.f + w2[c]);
        fp16 h, l; split2h(z, h, l);
        size_t o = (size_t)row * cols + c;
        dst[o] = h; dst[elts + o] = l;
    }
}

// fused q-rope / k-rope / v-norm from fused qkv buffer. grid (N_TOK, 12):
// y in [0,8): q head; [8,10): k head; [10,12): v head.
__global__ void qkv_norm_kernel(const float* __restrict__ x,
                                const float* __restrict__ qw, const float* __restrict__ kw,
                                const float* __restrict__ cost, const float* __restrict__ sint,
                                float* __restrict__ Kout, float* __restrict__ Vout,
                                fp16* __restrict__ qt, fp16* __restrict__ kt,
                                fp16* __restrict__ vt) {
    int n = blockIdx.x, g = blockIdx.y, d = threadIdx.x;
    __shared__ float sx[HDIM];
    if (g < 10) {  // rope path (q or k)
        const int isq = (g < 8);
        const int h = isq ? g : (g - 8);
        const float* w = isq ? qw : kw;
        const int off = isq ? (h * HDIM) : (2048 + h * HDIM);
        float v = x[(size_t)n * 3072 + off + d];
        float ss = blockReduceSum256(v * v);
        float inv = rsqrtf(ss / (float)HDIM + EPSF);
        float xn = v * inv * (1.f + w[d]);
        sx[d] = xn;
        __syncthreads();
        float rh = (d < HDIM / 2) ? -sx[d + HDIM / 2] : sx[d - HDIM / 2];
        float y = xn * cost[(size_t)n * HDIM + d] + rh * sint[(size_t)n * HDIM + d];
        size_t idx = ((size_t)h * N_TOK + n) * HDIM + d;
        fp16 bh, bl; split2h(y, bh, bl);
        if (isq) {
            qt[idx] = bh; qt[E_QT + idx] = bl;
        } else {
            Kout[idx] = y;
            kt[idx] = bh; kt[E_KT + idx] = bl;
        }
    } else {       // v-norm path
        const int h = g - 10;
        float v = x[(size_t)n * 3072 + 2560 + h * HDIM + d];
        float ss = blockReduceSum256(v * v);
        float y = v * rsqrtf(ss / (float)HDIM + EPSF);
        Vout[((size_t)h * N_TOK + n) * HDIM + d] = y;
        fp16 bh, bl; split2h(y, bh, bl);
        size_t tidx = ((size_t)h * HDIM + d) * N_TOK + n;
        vt[tidx] = bh; vt[E_KT + tidx] = bl;
    }
}

// causal softmax over rows of 1024 (masked lanes never enter max/sum -> exact)
__global__ void softmax_causal_split_kernel(const float* __restrict__ p,
                                            fp16* __restrict__ dst, size_t elts) {
    const float* row = p + (size_t)blockIdx.x * N_TOK;
    const int r = blockIdx.x & (N_TOK - 1);
    int base = threadIdx.x * 4;
    float4 r4 = *(const float4*)(row + base);
    float v[4] = {r4.x, r4.y, r4.z, r4.w};
    float m = -INFINITY;
    #pragma unroll
    for (int i = 0; i < 4; i++) if (base + i <= r) m = fmaxf(m, v[i]);
    m = blockReduceMax256(m);
    float e[4];
    #pragma unroll
    for (int i = 0; i < 4; i++) e[i] = (base + i <= r) ? expf(v[i] - m) : 0.f;
    float s = blockReduceSum256(e[0] + e[1] + e[2] + e[3]);
    float invs = 1.f / s;
    union { fp16 b[4]; uint2 u2; } H, L;
    #pragma unroll
    for (int i = 0; i < 4; i++) split2h(e[i] * invs, H.b[i], L.b[i]);
    size_t o = (size_t)blockIdx.x * N_TOK + base;
    *(uint2*)(dst + o) = H.u2;
    *(uint2*)(dst + elts + o) = L.u2;
}

// ======================= fp16x2 mma machinery =======================
__device__ __forceinline__ uint32_t smem_u32(const void* p) {
    uint32_t a;
    asm("{ .reg .u64 t; cvta.to.shared.u64 t, %1; cvt.u32.u64 %0, t; }" : "=r"(a) : "l"(p));
    return a;
}
__device__ __forceinline__ void cp16(uint32_t dst, const void* src) {
    asm volatile("cp.async.cg.shared.global [%0], [%1], 16;" :: "r"(dst), "l"(src) : "memory");
}
__device__ __forceinline__ void ldsm4(uint32_t* r, uint32_t addr) {
    asm volatile("ldmatrix.sync.aligned.m8n8.x4.shared.b16 {%0,%1,%2,%3}, [%4];"
                 : "=r"(r[0]), "=r"(r[1]), "=r"(r[2]), "=r"(r[3]) : "r"(addr));
}
__device__ __forceinline__ void mma_f16(float* d, const uint32_t* a, const uint32_t* b) {
    asm volatile(
        "mma.sync.aligned.m16n8k16.row.col.f32.f16.f16.f32 "
        "{%0,%1,%2,%3}, {%4,%5,%6,%7}, {%8,%9}, {%0,%1,%2,%3};"
        : "+f"(d[0]), "+f"(d[1]), "+f"(d[2]), "+f"(d[3])
        : "r"(a[0]), "r"(a[1]), "r"(a[2]), "r"(a[3]), "r"(b[0]), "r"(b[1]));
}

#define TROWB 80
#define TILE_BYTES (128 * TROWB)
#define STG_BYTES  (4 * TILE_BYTES)   // 40960
#define GSMEM      (3 * STG_BYTES)    // 122880 (3-stage)

// C[z] tile = A[z](rows x K) @ B[z>>bshift](M x K)^T ; fp16 2-plane scaled split.
// CAUSAL: skip blocks strictly above the diagonal. SPLIT: emit fp16 planes (C3/eC).
template <bool CAUSAL, bool SPLIT>
__global__ void __launch_bounds__(256, 1)
mma_gemm(const fp16* __restrict__ A3, const fp16* __restrict__ B3,
         long long eA, long long eB,
         float* __restrict__ Cf, fp16* __restrict__ C3, long long eC,
         int K, int ldc,
         long long sA, long long sB, long long sC, int bshift) {
    if (CAUSAL && blockIdx.x > blockIdx.y) return;
    extern __shared__ char smem[];
    const uint32_t sb = smem_u32(smem);
    const int tid = threadIdx.x;
    const int bz = blockIdx.z;
    const int row0 = blockIdx.y * 128;
    const int col0 = blockIdx.x * 128;

    const fp16* srcs[4];
    #pragma unroll
    for (int p = 0; p < 2; p++) {
        srcs[p]     = A3 + (size_t)p * eA + (size_t)bz * sA + (size_t)row0 * K;
        srcs[2 + p] = B3 + (size_t)p * eB + (size_t)(bz >> bshift) * sB + (size_t)col0 * K;
    }

    const int lane = tid & 31, wid = tid >> 5;
    const int wm = wid & 3, wn = wid >> 2;
    const int ld_r = tid >> 2;
    const int ld_c = tid & 3;

    uint32_t aoff[2], boff[4];
    #pragma unroll
    for (int m = 0; m < 2; m++)
        aoff[m] = (uint32_t)((wm * 32 + m * 16 + (lane & 15)) * TROWB + ((lane >> 4) << 4));
    #pragma unroll
    for (int j = 0; j < 4; j++)
        boff[j] = (uint32_t)((wn * 64 + j * 16 + (lane & 7) + ((lane >> 4) << 3)) * TROWB
                             + (((lane >> 3) & 1) << 4));

    float accM[2][8][4], accC[2][8][4];
    #pragma unroll
    for (int m = 0; m < 2; m++)
        #pragma unroll
        for (int t = 0; t < 8; t++)
            #pragma unroll
            for (int u = 0; u < 4; u++) { accM[m][t][u] = 0.f; accC[m][t][u] = 0.f; }

    const int nch = K >> 5;

    auto issue = [&](int c, uint32_t dstb) {
        const int kb = c << 5;
        #pragma unroll
        for (int q = 0; q < 8; q++) {
            const int r = (q & 1) * 64 + ld_r;
            const char* gsrc = (const char*)(srcs[q >> 1] + (size_t)r * K + kb) + ld_c * 16;
            cp16(dstb + (uint32_t)((q >> 1) * TILE_BYTES + r * TROWB + ld_c * 16), gsrc);
        }
        asm volatile("cp.async.commit_group;" ::: "memory");
    };

    issue(0, sb);
    if (nch > 1) issue(1, sb + STG_BYTES);
    if (nch > 2) issue(2, sb + 2 * STG_BYTES);

    int stage = 0;
    for (int c = 0; c < nch; ++c) {
        const int rem = nch - 1 - c;
        if (rem >= 2)      asm volatile("cp.async.wait_group 2;" ::: "memory");
        else if (rem == 1) asm volatile("cp.async.wait_group 1;" ::: "memory");
        else               asm volatile("cp.async.wait_group 0;" ::: "memory");
        __syncthreads();

        const uint32_t base = sb + (uint32_t)stage * STG_BYTES;

        #pragma unroll
        for (int kk = 0; kk < 2; kk++) {
            const uint32_t kb = kk * 32;
            uint32_t ah[2][4], al[2][4];
            #pragma unroll
            for (int m = 0; m < 2; m++) {
                ldsm4(ah[m], base + 0 * TILE_BYTES + aoff[m] + kb);
                ldsm4(al[m], base + 1 * TILE_BYTES + aoff[m] + kb);
            }
            #pragma unroll
            for (int j = 0; j < 4; j++) {
                uint32_t bh[4], bl[4];
                ldsm4(bh, base + 2 * TILE_BYTES + boff[j] + kb);
                ldsm4(bl, base + 3 * TILE_BYTES + boff[j] + kb);
                #pragma unroll
                for (int m = 0; m < 2; m++) {
                    #pragma unroll
                    for (int h = 0; h < 2; h++) {
                        float* dM = accM[m][j * 2 + h];
                        float* dC = accC[m][j * 2 + h];
                        mma_f16(dM, ah[m], &bh[h * 2]);   // hh -> main
                        mma_f16(dC, ah[m], &bl[h * 2]);   // corrections (x2048) -> corr
                        mma_f16(dC, al[m], &bh[h * 2]);
                    }
                }
            }
        }
        __syncthreads();
        if (c + 3 < nch) issue(c + 3, base);
        stage = (stage == 2) ? 0 : stage + 1;
    }

    const int grp = lane >> 2, qd = lane & 3;
    #pragma unroll
    for (int m = 0; m < 2; m++) {
        #pragma unroll
        for (int t = 0; t < 8; t++) {
            const int col = col0 + wn * 64 + t * 8 + qd * 2;
            #pragma unroll
            for (int half = 0; half < 2; half++) {
                const int row = row0 + wm * 32 + m * 16 + grp + half * 8;
                float v0 = accM[m][t][half * 2 + 0] + accC[m][t][half * 2 + 0] * SPLIT_INV;
                float v1 = accM[m][t][half * 2 + 1] + accC[m][t][half * 2 + 1] * SPLIT_INV;
                const size_t o = (size_t)bz * sC + (size_t)row * ldc + col;
                if (SPLIT) {
                    union { fp16 b[2]; uint32_t u; } H, L;
                    split2h(v0, H.b[0], L.b[0]); split2h(v1, H.b[1], L.b[1]);
                    *(uint32_t*)(C3 + o) = H.u;
                    *(uint32_t*)(C3 + (size_t)eC + o) = L.u;
                } else {
                    float2 o2; o2.x = v0; o2.y = v1;
                    *(float2*)(Cf + o) = o2;
                }
            }
        }
    }
}

// ======================= split producers =======================
// grid-stride, 2-wide ILP fp32 -> 2-plane fp16
__global__ void wsplit_kernel(const float* __restrict__ x, fp16* __restrict__ dst,
                              size_t plane, size_t n4) {
    const size_t stride = (size_t)gridDim.x * 256;
    for (size_t i = (size_t)blockIdx.x * 256 + threadIdx.x; i < n4; i += 2 * stride) {
        size_t i2 = i + stride;
        float4 v0 = ((const float4*)x)[i];
        float4 v1 = (i2 < n4) ? ((const float4*)x)[i2] : make_float4(0, 0, 0, 0);
        union { fp16 b[4]; uint2 u2; } H0, L0, H1, L1;
        split2h(v0.x, H0.b[0], L0.b[0]); split2h(v0.y, H0.b[1], L0.b[1]);
        split2h(v0.z, H0.b[2], L0.b[2]); split2h(v0.w, H0.b[3], L0.b[3]);
        split2h(v1.x, H1.b[0], L1.b[0]); split2h(v1.y, H1.b[1], L1.b[1]);
        split2h(v1.z, H1.b[2], L1.b[2]); split2h(v1.w, H1.b[3], L1.b[3]);
        ((uint2*)dst)[i] = H0.u2;
        ((uint2*)(dst + plane))[i] = L0.u2;
        if (i2 < n4) {
            ((uint2*)dst)[i2] = H1.u2;
            ((uint2*)(dst + plane))[i2] = L1.u2;
        }
    }
}

__global__ void rmsnorm_split_kernel(const float* __restrict__ x, const float* __restrict__ w,
                                     fp16* __restrict__ dst, size_t elts, int cols) {
    int row = blockIdx.x;
    const float* xr = x + (size_t)row * cols;
    float ss = 0.f;
    for (int c = threadIdx.x; c < cols; c += 256) { float v = xr[c]; ss += v * v; }
    ss = blockReduceSum256(ss);
    float inv = rsqrtf(ss / (float)cols + EPSF);
    for (int c = threadIdx.x; c < cols; c += 256) {
        float y = xr[c] * inv * (1.f + w[c]);
        fp16 h, l; split2h(y, h, l);
        size_t o = (size_t)row * cols + c;
        dst[o] = h; dst[elts + o] = l;
    }
}

// reads fused [g|u] buffer (row stride 8192)
__global__ void gelu_mul_split_kernel(const float* __restrict__ gu,
                                      fp16* __restrict__ dst, size_t elts, int n) {
    int i = blockIdx.x * 256 + threadIdx.x;
    if (i < n) {
        int row = i >> 12, j = i & 4095;
        float g = gu[(size_t)row * 8192 + j];
        float u = gu[(size_t)row * 8192 + 4096 + j];
        float y = gelu_tanh(g) * u;
        fp16 h, l; split2h(y, h, l);
        dst[i] = h; dst[elts + i] = l;
    }
}

__global__ void gelu_sl_split_kernel(const float* __restrict__ g, const float* __restrict__ plc,
                                     int li, fp16* __restrict__ dst, size_t elts) {
    int i = blockIdx.x * 256 + threadIdx.x;
    if (i < N_TOK * HPL) {
        int n = i >> 8, j = i & 255;
        float y = gelu_tanh(g[i]) * plc[(size_t)n * (TOTAL_LAYERS * HPL) + (size_t)li * HPL + j];
        fp16 h, l; split2h(y, h, l);
        dst[i] = h; dst[elts + i] = l;
    }
}

// ======================= driver =======================
extern "C" void kernel_launch(void* const* d_in, const int* in_sizes, int n_in,
                              void* d_out, int out_size) {
    const float* hidden = (const float*)d_in[0];
    const float* plc    = (const float*)d_in[1];
    const float* cos_s  = (const float*)d_in[3];
    const float* sin_s  = (const float*)d_in[4];
    const float* cos_f  = (const float*)d_in[5];
    const float* sin_f  = (const float*)d_in[6];
    const float* Wq     = (const float*)d_in[7];
    const float* Wk     = (const float*)d_in[8];
    const float* Wv     = (const float*)d_in[9];
    const float* Wo     = (const float*)d_in[10];
    const float* Wg     = (const float*)d_in[11];
    const float* Wu     = (const float*)d_in[12];
    const float* Wd     = (const float*)d_in[13];
    const float* Wplg   = (const float*)d_in[14];
    const float* Wplp   = (const float*)d_in[15];
    const float* ln_in  = (const float*)d_in[16];
    const float* ln_pa  = (const float*)d_in[17];
    const float* ln_pf  = (const float*)d_in[18];
    const float* ln_ff  = (const float*)d_in[19];
    const float* ln_pl  = (const float*)d_in[20];
    const float* qn_w   = (const float*)d_in[21];
    const float* kn_w   = (const float*)d_in[22];
    const float* lscale = (const float*)d_in[23];

    cudaFuncSetAttribute(mma_gemm<false, false>, cudaFuncAttributeMaxDynamicSharedMemorySize, GSMEM);
    cudaFuncSetAttribute(mma_gemm<true, false>,  cudaFuncAttributeMaxDynamicSharedMemorySize, GSMEM);
    cudaFuncSetAttribute(mma_gemm<false, true>,  cudaFuncAttributeMaxDynamicSharedMemorySize, GSMEM);

    char* scr = nullptr;
    cudaGetSymbolAddress((void**)&scr, g_scr);

    fp16* wqkv3 = (fp16*)(scr + OFF_WQKV);
    fp16* wo3   = (fp16*)(scr + OFF_WO3);
    fp16* wgu3  = (fp16*)(scr + OFF_WGU);
    fp16* wd3   = (fp16*)(scr + OFF_WD3);
    fp16* wplg3 = (fp16*)(scr + OFF_WPLG3);
    fp16* wplp3 = (fp16*)(scr + OFF_WPLP3);

    float* hs     = (float*)(scr + OFF_HS);
    float* qkvraw = (float*)(scr + OFF_QKVRAW);
    float* scores = (float*)(scr + OFF_SC);
    float* tmp    = (float*)(scr + OFF_TMP);
    float* gu     = (float*)(scr + OFF_GU);
    float* plbuf  = (float*)(scr + OFF_PLB);
    fp16*  h2     = (fp16*)(scr + OFF_H2);
    fp16*  qt3    = (fp16*)(scr + OFF_QT3);
    fp16*  kt3    = (fp16*)(scr + OFF_KT3);
    fp16*  vt3    = (fp16*)(scr + OFF_VT3);
    fp16*  p3     = (fp16*)(scr + OFF_P3);
    fp16*  ao3    = (fp16*)(scr + OFF_AO3);
    fp16*  m2     = (fp16*)(scr + OFF_M2);
    fp16*  hs3    = (fp16*)(scr + OFF_HS3);
    fp16*  pl3    = (fp16*)(scr + OFF_PL3);

    float* out = (float*)d_out;

    // ---- split weights into fused 2-plane layouts (grid-stride) ----
    auto wsplit = [&](const float* src, fp16* dst, size_t plane, size_t count) {
        size_t n4 = count / 4;
        unsigned blocks = (unsigned)((n4 + 511) / 512);
        if (blocks > 4096) blocks = 4096;
        wsplit_kernel<<<blocks, 256>>>(src, dst, plane, n4);
    };
    for (int i = 0; i < NLAYER; i++) {
        const size_t lq = (size_t)i * 2048 * 2048;
        const size_t lk = (size_t)i * 512 * 2048;
        fp16* dst = wqkv3 + (size_t)i * 3072 * 2048;
        wsplit(Wq + lq, dst,               E_QKV, (size_t)2048 * 2048);
        wsplit(Wk + lk, dst + 2048 * 2048, E_QKV, (size_t)512 * 2048);
        wsplit(Wv + lk, dst + 2560 * 2048, E_QKV, (size_t)512 * 2048);

        const size_t lg = (size_t)i * 4096 * 2048;
        fp16* dgu = wgu3 + (size_t)i * 8192 * 2048;
        wsplit(Wg + lg, dgu,               E_GU, (size_t)4096 * 2048);
        wsplit(Wu + lg, dgu + 4096 * 2048, E_GU, (size_t)4096 * 2048);
    }
    wsplit(Wo,   wo3,   E_WO,  E_WO);
    wsplit(Wd,   wd3,   E_WD,  E_WD);
    wsplit(Wplg, wplg3, E_WPL, E_WPL);
    wsplit(Wplp, wplp3, E_WPL, E_WPL);

    cudaMemcpyAsync(hs, hidden, (size_t)N_TOK * DMODEL * sizeof(float), cudaMemcpyDeviceToDevice, 0);

    // initial pre-attention norm (layer 0)
    rmsnorm_split_kernel<<<N_TOK, 256>>>(hs, ln_in, h2, E_H2, DMODEL);

    for (int i = 0; i < NLAYER; i++) {
        const int li = STARTL + i;
        const bool full = ((li + 1) % 5) == 0;
        const float* cost = full ? cos_f : cos_s;
        const float* sint = full ? sin_f : sin_s;
        float* Kout = out + (size_t)N_TOK * DMODEL + (size_t)i * 2 * NKV * N_TOK * HDIM;
        float* Vout = Kout + (size_t)NKV * N_TOK * HDIM;

        // ---- fused QKV (mma) + fused norms ----
        mma_gemm<false, false><<<dim3(3072 / 128, 8), 256, GSMEM>>>(
            h2, wqkv3 + (size_t)i * 3072 * 2048, (long long)E_H2, (long long)E_QKV,
            qkvraw, nullptr, 0, DMODEL, 3072, 0, 0, 0, 0);
        qkv_norm_kernel<<<dim3(N_TOK, 12), 256>>>(
            qkvraw, qn_w + (size_t)i * HDIM, kn_w + (size_t)i * HDIM, cost, sint,
            Kout, Vout, qt3, kt3, vt3);

        // ---- attention: causal scores, softmax, PV (split epilogue) ----
        mma_gemm<true, false><<<dim3(N_TOK / 128, N_TOK / 128, NH), 256, GSMEM>>>(
            qt3, kt3, (long long)E_QT, (long long)E_KT, scores, nullptr, 0, HDIM, N_TOK,
            (long long)N_TOK * HDIM, (long long)N_TOK * HDIM, (long long)N_TOK * N_TOK, 2);
        softmax_causal_split_kernel<<<NH * N_TOK, 256>>>(scores, p3, E_P3);
        mma_gemm<false, true><<<dim3(HDIM / 128, N_TOK / 128, NH), 256, GSMEM>>>(
            p3, vt3, (long long)E_P3, (long long)E_KT, nullptr, ao3, (long long)E_AO,
            N_TOK, NH * HDIM,
            (long long)N_TOK * N_TOK, (long long)HDIM * N_TOK, (long long)HDIM, 2);

        // ---- Wo (mma) + fused residual + pre-FFN norm ----
        mma_gemm<false, false><<<dim3(DMODEL / 128, 8), 256, GSMEM>>>(
            ao3, wo3 + (size_t)i * 2048 * 2048, (long long)E_AO, (long long)E_WO,
            tmp, nullptr, 0, NH * HDIM, DMODEL, 0, 0, 0, 0);
        add_rms_norm_kernel<<<N_TOK, 256>>>(hs, tmp, ln_pa + (size_t)i * DMODEL, nullptr,
                                            ln_pf + (size_t)i * DMODEL, h2, E_H2);

        // ---- FFN: fused G+U, gelu*u, Wd (mma) + residual (emits hs planes) ----
        mma_gemm<false, false><<<dim3(8192 / 128, 8), 256, GSMEM>>>(
            h2, wgu3 + (size_t)i * 8192 * 2048, (long long)E_H2, (long long)E_GU,
            gu, nullptr, 0, DMODEL, 8192, 0, 0, 0, 0);
        gelu_mul_split_kernel<<<(N_TOK * FFDIM + 255) / 256, 256>>>(gu, m2, E_M2, N_TOK * FFDIM);
        mma_gemm<false, false><<<dim3(DMODEL / 128, 8), 256, GSMEM>>>(
            m2, wd3 + (size_t)i * 2048 * 4096, (long long)E_M2, (long long)E_WD,
            tmp, nullptr, 0, FFDIM, DMODEL, 0, 0, 0, 0);
        add_rms_kernel<<<N_TOK, 256>>>(hs, tmp, ln_ff + (size_t)i * DMODEL, nullptr,
                                       hs3, E_H2, DMODEL);

        // ---- per-layer gating (mma) + fused residual + next-layer norm ----
        mma_gemm<false, false><<<dim3(HPL / 128, 8), 256, GSMEM>>>(
            hs3, wplg3 + (size_t)i * HPL * 2048, (long long)E_H2, (long long)E_WPL,
            plbuf, nullptr, 0, DMODEL, HPL, 0, 0, 0, 0);
        gelu_sl_split_kernel<<<(N_TOK * HPL + 255) / 256, 256>>>(plbuf, plc, li, pl3, E_PL);
        mma_gemm<false, false><<<dim3(DMODEL / 128, 8), 256, GSMEM>>>(
            pl3, wplp3 + (size_t)i * 2048 * HPL, (long long)E_PL, (long long)E_WPL,
            tmp, nullptr, 0, HPL, DMODEL, 0, 0, 0, 0);
        if (i + 1 < NLAYER) {
            add_rms_norm_kernel<<<N_TOK, 256>>>(hs, tmp, ln_pl + (size_t)i * DMODEL, lscale + i,
                                                ln_in + (size_t)(i + 1) * DMODEL, h2, E_H2);
        } else {
            add_rms_kernel<<<N_TOK, 256>>>(hs, tmp, ln_pl + (size_t)i * DMODEL, lscale + i,
                                           nullptr, 0, DMODEL);
        }
    }

    cudaMemcpyAsync(out, hs, (size_t)N_TOK * DMODEL * sizeof(float), cudaMemcpyDeviceToDevice, 0);
}

// round 13
// speedup vs baseline: 3.4066x; 1.0450x over previous
#include <cuda_runtime.h>
#include <cuda_fp16.h>
#include <math.h>
#include <stdint.h>

#define N_TOK 1024
#define DMODEL 2048
#define NH 8
#define NKV 2
#define HDIM 256
#define FFDIM 4096
#define HPL 256
#define NLAYER 7
#define STARTL 8
#define TOTAL_LAYERS 30
#define EPSF 1e-6f
#define SPLIT_SCALE 2048.f
#define SPLIT_INV   (1.f / 2048.f)

typedef __half fp16;

// ======================= plane sizes (elements) =======================
#define E_QKV ((size_t)NLAYER * 3072 * DMODEL)
#define E_WO  ((size_t)NLAYER * DMODEL * (NH * HDIM))
#define E_GU  ((size_t)NLAYER * 8192 * DMODEL)
#define E_WD  ((size_t)NLAYER * DMODEL * FFDIM)
#define E_WPL ((size_t)NLAYER * HPL * DMODEL)
#define E_H2  ((size_t)N_TOK * DMODEL)
#define E_QT  ((size_t)N_TOK * NH * HDIM)
#define E_KT  ((size_t)N_TOK * NKV * HDIM)
#define E_P3  ((size_t)NH * N_TOK * N_TOK)
#define E_AO  ((size_t)N_TOK * NH * HDIM)
#define E_M2  ((size_t)N_TOK * FFDIM)
#define E_PL  ((size_t)N_TOK * HPL)

// ======================= scratch layout (bytes) =======================
#define OFF_WQKV  ((size_t)0)
#define OFF_WO3   (OFF_WQKV + 4 * E_QKV)
#define OFF_WGU   (OFF_WO3  + 4 * E_WO)
#define OFF_WD3   (OFF_WGU  + 4 * E_GU)
#define OFF_WPLG3 (OFF_WD3  + 4 * E_WD)
#define OFF_WPLP3 (OFF_WPLG3 + 4 * E_WPL)
// fp32 activations
#define OFF_HS     (OFF_WPLP3 + 4 * E_WPL)
#define OFF_QKVRAW (OFF_HS     + 4ull * N_TOK * DMODEL)
#define OFF_SC     (OFF_QKVRAW + 4ull * N_TOK * 3072)
#define OFF_TMP    (OFF_SC     + 4ull * E_P3)
#define OFF_GU     (OFF_TMP    + 4ull * N_TOK * DMODEL)
#define OFF_PLB    (OFF_GU     + 4ull * N_TOK * 8192)
// fp16 2-plane activations
#define OFF_H2     (OFF_PLB + 4ull * E_PL)
#define OFF_QT3    (OFF_H2  + 4ull * E_H2)
#define OFF_KT3    (OFF_QT3 + 4ull * E_QT)
#define OFF_VT3    (OFF_KT3 + 4ull * E_KT)
#define OFF_P3     (OFF_VT3 + 4ull * E_KT)
#define OFF_AO3    (OFF_P3  + 4ull * E_P3)
#define OFF_M2     (OFF_AO3 + 4ull * E_AO)
#define OFF_HS3    (OFF_M2  + 4ull * E_M2)
#define OFF_PL3    (OFF_HS3 + 4ull * E_H2)
#define TOTAL_SCR  (OFF_PL3 + 4ull * E_PL)

__device__ __align__(1024) char g_scr[TOTAL_SCR];

// ======================= block reductions =======================
__device__ __forceinline__ float blockReduceSum256(float v) {
    __shared__ float sh[8]; __shared__ float res;
    int lane = threadIdx.x & 31, wid = threadIdx.x >> 5;
    #pragma unroll
    for (int o = 16; o > 0; o >>= 1) v += __shfl_xor_sync(0xffffffffu, v, o);
    if (lane == 0) sh[wid] = v;
    __syncthreads();
    if (wid == 0) {
        float x = (lane < 8) ? sh[lane] : 0.f;
        #pragma unroll
        for (int o = 4; o > 0; o >>= 1) x += __shfl_xor_sync(0xffffffffu, x, o);
        if (lane == 0) res = x;
    }
    __syncthreads();
    return res;
}
__device__ __forceinline__ float blockReduceMax256(float v) {
    __shared__ float sh[8]; __shared__ float res;
    int lane = threadIdx.x & 31, wid = threadIdx.x >> 5;
    #pragma unroll
    for (int o = 16; o > 0; o >>= 1) v = fmaxf(v, __shfl_xor_sync(0xffffffffu, v, o));
    if (lane == 0) sh[wid] = v;
    __syncthreads();
    if (wid == 0) {
        float x = (lane < 8) ? sh[lane] : -INFINITY;
        #pragma unroll
        for (int o = 4; o > 0; o >>= 1) x = fmaxf(x, __shfl_xor_sync(0xffffffffu, x, o));
        if (lane == 0) res = x;
    }
    __syncthreads();
    return res;
}
__device__ __forceinline__ float gelu_tanh(float x) {
    float t = tanhf(0.7978845608028654f * (x + 0.044715f * x * x * x));
    return 0.5f * x * (1.f + t);
}
__device__ __forceinline__ void split2h(float v, fp16& h, fp16& l) {
    h = __float2half_rn(v);
    l = __float2half_rn((v - __half2float(h)) * SPLIT_SCALE);
}

// ======================= norm / elementwise kernels =======================
__global__ void add_rms_kernel(float* __restrict__ hs, const float* __restrict__ x,
                               const float* __restrict__ w,
                               const float* __restrict__ scale_ptr,
                               fp16* __restrict__ dst, size_t elts, int cols) {
    int row = blockIdx.x;
    const float* xr = x + (size_t)row * cols;
    float ss = 0.f;
    for (int c = threadIdx.x; c < cols; c += 256) { float v = xr[c]; ss += v * v; }
    ss = blockReduceSum256(ss);
    float inv = rsqrtf(ss / (float)cols + EPSF);
    float sc = scale_ptr ? *scale_ptr : 1.f;
    float* hr = hs + (size_t)row * cols;
    for (int c = threadIdx.x; c < cols; c += 256) {
        float y = (hr[c] + xr[c] * inv * (1.f + w[c])) * sc;
        hr[c] = y;
        if (dst) {
            fp16 h, l; split2h(y, h, l);
            size_t o = (size_t)row * cols + c;
            dst[o] = h; dst[elts + o] = l;
        }
    }
}

__global__ void add_rms_norm_kernel(float* __restrict__ hs, const float* __restrict__ x,
                                    const float* __restrict__ w1,
                                    const float* __restrict__ scale_ptr,
                                    const float* __restrict__ w2,
                                    fp16* __restrict__ dst, size_t elts) {
    const int cols = DMODEL;
    int row = blockIdx.x;
    const float* xr = x + (size_t)row * cols;
    float* hr = hs + (size_t)row * cols;
    float ss = 0.f;
    #pragma unroll
    for (int q = 0; q < 8; q++) { float v = xr[threadIdx.x + q * 256]; ss += v * v; }
    ss = blockReduceSum256(ss);
    float inv = rsqrtf(ss / (float)cols + EPSF);
    float sc = scale_ptr ? *scale_ptr : 1.f;
    float ys[8];
    float ss2 = 0.f;
    #pragma unroll
    for (int q = 0; q < 8; q++) {
        int c = threadIdx.x + q * 256;
        float y = (hr[c] + xr[c] * inv * (1.f + w1[c])) * sc;
        ys[q] = y; hr[c] = y; ss2 += y * y;
    }
    ss2 = blockReduceSum256(ss2);
    float inv2 = rsqrtf(ss2 / (float)cols + EPSF);
    #pragma unroll
    for (int q = 0; q < 8; q++) {
        int c = threadIdx.x + q * 256;
        float z = ys[q] * inv2 * (1.f + w2[c]);
        fp16 h, l; split2h(z, h, l);
        size_t o = (size_t)row * cols + c;
        dst[o] = h; dst[elts + o] = l;
    }
}

__global__ void qkv_norm_kernel(const float* __restrict__ x,
                                const float* __restrict__ qw, const float* __restrict__ kw,
                                const float* __restrict__ cost, const float* __restrict__ sint,
                                float* __restrict__ Kout, float* __restrict__ Vout,
                                fp16* __restrict__ qt, fp16* __restrict__ kt,
                                fp16* __restrict__ vt) {
    int n = blockIdx.x, g = blockIdx.y, d = threadIdx.x;
    __shared__ float sx[HDIM];
    if (g < 10) {
        const int isq = (g < 8);
        const int h = isq ? g : (g - 8);
        const float* w = isq ? qw : kw;
        const int off = isq ? (h * HDIM) : (2048 + h * HDIM);
        float v = x[(size_t)n * 3072 + off + d];
        float ss = blockReduceSum256(v * v);
        float inv = rsqrtf(ss / (float)HDIM + EPSF);
        float xn = v * inv * (1.f + w[d]);
        sx[d] = xn;
        __syncthreads();
        float rh = (d < HDIM / 2) ? -sx[d + HDIM / 2] : sx[d - HDIM / 2];
        float y = xn * cost[(size_t)n * HDIM + d] + rh * sint[(size_t)n * HDIM + d];
        size_t idx = ((size_t)h * N_TOK + n) * HDIM + d;
        fp16 bh, bl; split2h(y, bh, bl);
        if (isq) {
            qt[idx] = bh; qt[E_QT + idx] = bl;
        } else {
            Kout[idx] = y;
            kt[idx] = bh; kt[E_KT + idx] = bl;
        }
    } else {
        const int h = g - 10;
        float v = x[(size_t)n * 3072 + 2560 + h * HDIM + d];
        float ss = blockReduceSum256(v * v);
        float y = v * rsqrtf(ss / (float)HDIM + EPSF);
        Vout[((size_t)h * N_TOK + n) * HDIM + d] = y;
        fp16 bh, bl; split2h(y, bh, bl);
        size_t tidx = ((size_t)h * HDIM + d) * N_TOK + n;
        vt[tidx] = bh; vt[E_KT + tidx] = bl;
    }
}

__global__ void softmax_causal_split_kernel(const float* __restrict__ p,
                                            fp16* __restrict__ dst, size_t elts) {
    const float* row = p + (size_t)blockIdx.x * N_TOK;
    const int r = blockIdx.x & (N_TOK - 1);
    int base = threadIdx.x * 4;
    float4 r4 = *(const float4*)(row + base);
    float v[4] = {r4.x, r4.y, r4.z, r4.w};
    float m = -INFINITY;
    #pragma unroll
    for (int i = 0; i < 4; i++) if (base + i <= r) m = fmaxf(m, v[i]);
    m = blockReduceMax256(m);
    float e[4];
    #pragma unroll
    for (int i = 0; i < 4; i++) e[i] = (base + i <= r) ? expf(v[i] - m) : 0.f;
    float s = blockReduceSum256(e[0] + e[1] + e[2] + e[3]);
    float invs = 1.f / s;
    union { fp16 b[4]; uint2 u2; } H, L;
    #pragma unroll
    for (int i = 0; i < 4; i++) split2h(e[i] * invs, H.b[i], L.b[i]);
    size_t o = (size_t)blockIdx.x * N_TOK + base;
    *(uint2*)(dst + o) = H.u2;
    *(uint2*)(dst + elts + o) = L.u2;
}

// ======================= fp16x2 mma machinery =======================
__device__ __forceinline__ uint32_t smem_u32(const void* p) {
    uint32_t a;
    asm("{ .reg .u64 t; cvta.to.shared.u64 t, %1; cvt.u32.u64 %0, t; }" : "=r"(a) : "l"(p));
    return a;
}
__device__ __forceinline__ void cp16(uint32_t dst, const void* src) {
    asm volatile("cp.async.cg.shared.global [%0], [%1], 16;" :: "r"(dst), "l"(src) : "memory");
}
__device__ __forceinline__ void ldsm4(uint32_t* r, uint32_t addr) {
    asm volatile("ldmatrix.sync.aligned.m8n8.x4.shared.b16 {%0,%1,%2,%3}, [%4];"
                 : "=r"(r[0]), "=r"(r[1]), "=r"(r[2]), "=r"(r[3]) : "r"(addr));
}
__device__ __forceinline__ void mma_f16(float* d, const uint32_t* a, const uint32_t* b) {
    asm volatile(
        "mma.sync.aligned.m16n8k16.row.col.f32.f16.f16.f32 "
        "{%0,%1,%2,%3}, {%4,%5,%6,%7}, {%8,%9}, {%0,%1,%2,%3};"
        : "+f"(d[0]), "+f"(d[1]), "+f"(d[2]), "+f"(d[3])
        : "r"(a[0]), "r"(a[1]), "r"(a[2]), "r"(a[3]), "r"(b[0]), "r"(b[1]));
}

#define TROWB 80
#define TILEA (128 * TROWB)            // A tile bytes (always 128 rows)

// C[z] tile (128 rows x NT cols) = A[z](rows x K) @ B[z>>bshift](M x K)^T
// fp16 2-plane scaled split; dual accumulators; 3-stage cp.async pipeline.
template <int NT, bool CAUSAL, bool SPLIT>
__global__ void __launch_bounds__(256, 1)
mma_gemm(const fp16* __restrict__ A3, const fp16* __restrict__ B3,
         long long eA, long long eB,
         float* __restrict__ Cf, fp16* __restrict__ C3, long long eC,
         int K, int ldc,
         long long sA, long long sB, long long sC, int bshift) {
    constexpr int TILEB = NT * TROWB;
    constexpr int STG = 2 * TILEA + 2 * TILEB;
    constexpr int NJ = NT / 32;
    if (CAUSAL && (int)blockIdx.x * NT > (int)blockIdx.y * 128 + 127) return;
    extern __shared__ char smem[];
    const uint32_t sb = smem_u32(smem);
    const int tid = threadIdx.x;
    const int bz = blockIdx.z;
    const int row0 = blockIdx.y * 128;
    const int col0 = blockIdx.x * NT;

    const fp16* srcs[4];
    #pragma unroll
    for (int p = 0; p < 2; p++) {
        srcs[p]     = A3 + (size_t)p * eA + (size_t)bz * sA + (size_t)row0 * K;
        srcs[2 + p] = B3 + (size_t)p * eB + (size_t)(bz >> bshift) * sB + (size_t)col0 * K;
    }

    const int lane = tid & 31, wid = tid >> 5;
    const int wm = wid & 3, wn = wid >> 2;
    const int ld_r = tid >> 2;
    const int ld_c = tid & 3;

    uint32_t aoff[2], boff[NJ];
    #pragma unroll
    for (int m = 0; m < 2; m++)
        aoff[m] = (uint32_t)((wm * 32 + m * 16 + (lane & 15)) * TROWB + ((lane >> 4) << 4));
    #pragma unroll
    for (int j = 0; j < NJ; j++)
        boff[j] = (uint32_t)((wn * (NT / 2) + j * 16 + (lane & 7) + ((lane >> 4) << 3)) * TROWB
                             + (((lane >> 3) & 1) << 4));

    float accM[2][2 * NJ][4], accC[2][2 * NJ][4];
    #pragma unroll
    for (int m = 0; m < 2; m++)
        #pragma unroll
        for (int t = 0; t < 2 * NJ; t++)
            #pragma unroll
            for (int u = 0; u < 4; u++) { accM[m][t][u] = 0.f; accC[m][t][u] = 0.f; }

    const int nch = K >> 5;

    auto issue = [&](int c, uint32_t dstb) {
        const int kb = c << 5;
        #pragma unroll
        for (int q = 0; q < 4; q++) {   // A planes: 2 row-batches each
            const int r = (q & 1) * 64 + ld_r;
            const char* gsrc = (const char*)(srcs[q >> 1] + (size_t)r * K + kb) + ld_c * 16;
            cp16(dstb + (uint32_t)((q >> 1) * TILEA + r * TROWB + ld_c * 16), gsrc);
        }
        #pragma unroll
        for (int p = 0; p < 2; p++)     // B planes: NT/64 row-batches each
            #pragma unroll
            for (int qq = 0; qq < NT / 64; qq++) {
                const int r = qq * 64 + ld_r;
                const char* gsrc = (const char*)(srcs[2 + p] + (size_t)r * K + kb) + ld_c * 16;
                cp16(dstb + (uint32_t)(2 * TILEA + p * TILEB + r * TROWB + ld_c * 16), gsrc);
            }
        asm volatile("cp.async.commit_group;" ::: "memory");
    };

    issue(0, sb);
    if (nch > 1) issue(1, sb + STG);
    if (nch > 2) issue(2, sb + 2 * STG);

    int stage = 0;
    for (int c = 0; c < nch; ++c) {
        const int rem = nch - 1 - c;
        if (rem >= 2)      asm volatile("cp.async.wait_group 2;" ::: "memory");
        else if (rem == 1) asm volatile("cp.async.wait_group 1;" ::: "memory");
        else               asm volatile("cp.async.wait_group 0;" ::: "memory");
        __syncthreads();

        const uint32_t base = sb + (uint32_t)stage * STG;

        #pragma unroll
        for (int kk = 0; kk < 2; kk++) {
            const uint32_t kb = kk * 32;
            uint32_t ah[2][4], al[2][4];
            #pragma unroll
            for (int m = 0; m < 2; m++) {
                ldsm4(ah[m], base + 0 * TILEA + aoff[m] + kb);
                ldsm4(al[m], base + 1 * TILEA + aoff[m] + kb);
            }
            #pragma unroll
            for (int j = 0; j < NJ; j++) {
                uint32_t bh[4], bl[4];
                ldsm4(bh, base + 2 * TILEA + 0 * TILEB + boff[j] + kb);
                ldsm4(bl, base + 2 * TILEA + 1 * TILEB + boff[j] + kb);
                #pragma unroll
                for (int m = 0; m < 2; m++) {
                    #pragma unroll
                    for (int h = 0; h < 2; h++) {
                        float* dM = accM[m][j * 2 + h];
                        float* dC = accC[m][j * 2 + h];
                        mma_f16(dM, ah[m], &bh[h * 2]);   // hh -> main
                        mma_f16(dC, ah[m], &bl[h * 2]);   // corrections (x2048) -> corr
                        mma_f16(dC, al[m], &bh[h * 2]);
                    }
                }
            }
        }
        __syncthreads();
        if (c + 3 < nch) issue(c + 3, base);
        stage = (stage == 2) ? 0 : stage + 1;
    }

    const int grp = lane >> 2, qd = lane & 3;
    #pragma unroll
    for (int m = 0; m < 2; m++) {
        #pragma unroll
        for (int t = 0; t < 2 * NJ; t++) {
            const int col = col0 + wn * (NT / 2) + t * 8 + qd * 2;
            #pragma unroll
            for (int half = 0; half < 2; half++) {
                const int row = row0 + wm * 32 + m * 16 + grp + half * 8;
                float v0 = accM[m][t][half * 2 + 0] + accC[m][t][half * 2 + 0] * SPLIT_INV;
                float v1 = accM[m][t][half * 2 + 1] + accC[m][t][half * 2 + 1] * SPLIT_INV;
                const size_t o = (size_t)bz * sC + (size_t)row * ldc + col;
                if (SPLIT) {
                    union { fp16 b[2]; uint32_t u; } H, L;
                    split2h(v0, H.b[0], L.b[0]); split2h(v1, H.b[1], L.b[1]);
                    *(uint32_t*)(C3 + o) = H.u;
                    *(uint32_t*)(C3 + (size_t)eC + o) = L.u;
                } else {
                    float2 o2; o2.x = v0; o2.y = v1;
                    *(float2*)(Cf + o) = o2;
                }
            }
        }
    }
}

#define GSMEM128 (3 * (2 * TILEA + 2 * 128 * TROWB))  // 122880
#define GSMEM64  (3 * (2 * TILEA + 2 * 64 * TROWB))   //  92160

// ======================= split producers =======================
// grid-stride, 4-wide ILP fp32 -> 2-plane fp16
__global__ void wsplit_kernel(const float* __restrict__ x, fp16* __restrict__ dst,
                              size_t plane, size_t n4) {
    const size_t s = (size_t)gridDim.x * 256;
    for (size_t i = (size_t)blockIdx.x * 256 + threadIdx.x; i < n4; i += 4 * s) {
        float4 v[4];
        size_t idx[4];
        #pragma unroll
        for (int q = 0; q < 4; q++) {
            idx[q] = i + q * s;
            v[q] = (idx[q] < n4) ? ((const float4*)x)[idx[q]] : make_float4(0, 0, 0, 0);
        }
        #pragma unroll
        for (int q = 0; q < 4; q++) {
            if (idx[q] >= n4) break;
            union { fp16 b[4]; uint2 u2; } H, L;
            split2h(v[q].x, H.b[0], L.b[0]); split2h(v[q].y, H.b[1], L.b[1]);
            split2h(v[q].z, H.b[2], L.b[2]); split2h(v[q].w, H.b[3], L.b[3]);
            ((uint2*)dst)[idx[q]] = H.u2;
            ((uint2*)(dst + plane))[idx[q]] = L.u2;
        }
    }
}

__global__ void rmsnorm_split_kernel(const float* __restrict__ x, const float* __restrict__ w,
                                     fp16* __restrict__ dst, size_t elts, int cols) {
    int row = blockIdx.x;
    const float* xr = x + (size_t)row * cols;
    float ss = 0.f;
    for (int c = threadIdx.x; c < cols; c += 256) { float v = xr[c]; ss += v * v; }
    ss = blockReduceSum256(ss);
    float inv = rsqrtf(ss / (float)cols + EPSF);
    for (int c = threadIdx.x; c < cols; c += 256) {
        float y = xr[c] * inv * (1.f + w[c]);
        fp16 h, l; split2h(y, h, l);
        size_t o = (size_t)row * cols + c;
        dst[o] = h; dst[elts + o] = l;
    }
}

__global__ void gelu_mul_split_kernel(const float* __restrict__ gu,
                                      fp16* __restrict__ dst, size_t elts, int n) {
    int i = blockIdx.x * 256 + threadIdx.x;
    if (i < n) {
        int row = i >> 12, j = i & 4095;
        float g = gu[(size_t)row * 8192 + j];
        float u = gu[(size_t)row * 8192 + 4096 + j];
        float y = gelu_tanh(g) * u;
        fp16 h, l; split2h(y, h, l);
        dst[i] = h; dst[elts + i] = l;
    }
}

__global__ void gelu_sl_split_kernel(const float* __restrict__ g, const float* __restrict__ plc,
                                     int li, fp16* __restrict__ dst, size_t elts) {
    int i = blockIdx.x * 256 + threadIdx.x;
    if (i < N_TOK * HPL) {
        int n = i >> 8, j = i & 255;
        float y = gelu_tanh(g[i]) * plc[(size_t)n * (TOTAL_LAYERS * HPL) + (size_t)li * HPL + j];
        fp16 h, l; split2h(y, h, l);
        dst[i] = h; dst[elts + i] = l;
    }
}

// ======================= driver =======================
extern "C" void kernel_launch(void* const* d_in, const int* in_sizes, int n_in,
                              void* d_out, int out_size) {
    const float* hidden = (const float*)d_in[0];
    const float* plc    = (const float*)d_in[1];
    const float* cos_s  = (const float*)d_in[3];
    const float* sin_s  = (const float*)d_in[4];
    const float* cos_f  = (const float*)d_in[5];
    const float* sin_f  = (const float*)d_in[6];
    const float* Wq     = (const float*)d_in[7];
    const float* Wk     = (const float*)d_in[8];
    const float* Wv     = (const float*)d_in[9];
    const float* Wo     = (const float*)d_in[10];
    const float* Wg     = (const float*)d_in[11];
    const float* Wu     = (const float*)d_in[12];
    const float* Wd     = (const float*)d_in[13];
    const float* Wplg   = (const float*)d_in[14];
    const float* Wplp   = (const float*)d_in[15];
    const float* ln_in  = (const float*)d_in[16];
    const float* ln_pa  = (const float*)d_in[17];
    const float* ln_pf  = (const float*)d_in[18];
    const float* ln_ff  = (const float*)d_in[19];
    const float* ln_pl  = (const float*)d_in[20];
    const float* qn_w   = (const float*)d_in[21];
    const float* kn_w   = (const float*)d_in[22];
    const float* lscale = (const float*)d_in[23];

    cudaFuncSetAttribute(mma_gemm<128, false, false>, cudaFuncAttributeMaxDynamicSharedMemorySize, GSMEM128);
    cudaFuncSetAttribute(mma_gemm<128, true,  false>, cudaFuncAttributeMaxDynamicSharedMemorySize, GSMEM128);
    cudaFuncSetAttribute(mma_gemm<128, false, true>,  cudaFuncAttributeMaxDynamicSharedMemorySize, GSMEM128);
    cudaFuncSetAttribute(mma_gemm<64,  false, false>, cudaFuncAttributeMaxDynamicSharedMemorySize, GSMEM64);

    char* scr = nullptr;
    cudaGetSymbolAddress((void**)&scr, g_scr);

    fp16* wqkv3 = (fp16*)(scr + OFF_WQKV);
    fp16* wo3   = (fp16*)(scr + OFF_WO3);
    fp16* wgu3  = (fp16*)(scr + OFF_WGU);
    fp16* wd3   = (fp16*)(scr + OFF_WD3);
    fp16* wplg3 = (fp16*)(scr + OFF_WPLG3);
    fp16* wplp3 = (fp16*)(scr + OFF_WPLP3);

    float* hs     = (float*)(scr + OFF_HS);
    float* qkvraw = (float*)(scr + OFF_QKVRAW);
    float* scores = (float*)(scr + OFF_SC);
    float* tmp    = (float*)(scr + OFF_TMP);
    float* gu     = (float*)(scr + OFF_GU);
    float* plbuf  = (float*)(scr + OFF_PLB);
    fp16*  h2     = (fp16*)(scr + OFF_H2);
    fp16*  qt3    = (fp16*)(scr + OFF_QT3);
    fp16*  kt3    = (fp16*)(scr + OFF_KT3);
    fp16*  vt3    = (fp16*)(scr + OFF_VT3);
    fp16*  p3     = (fp16*)(scr + OFF_P3);
    fp16*  ao3    = (fp16*)(scr + OFF_AO3);
    fp16*  m2     = (fp16*)(scr + OFF_M2);
    fp16*  hs3    = (fp16*)(scr + OFF_HS3);
    fp16*  pl3    = (fp16*)(scr + OFF_PL3);

    float* out = (float*)d_out;

    // ---- split weights into fused 2-plane layouts (grid-stride, 4-wide) ----
    auto wsplit = [&](const float* src, fp16* dst, size_t plane, size_t count) {
        size_t n4 = count / 4;
        unsigned blocks = (unsigned)((n4 + 1023) / 1024);
        if (blocks > 2048) blocks = 2048;
        wsplit_kernel<<<blocks, 256>>>(src, dst, plane, n4);
    };
    for (int i = 0; i < NLAYER; i++) {
        const size_t lq = (size_t)i * 2048 * 2048;
        const size_t lk = (size_t)i * 512 * 2048;
        fp16* dst = wqkv3 + (size_t)i * 3072 * 2048;
        wsplit(Wq + lq, dst,               E_QKV, (size_t)2048 * 2048);
        wsplit(Wk + lk, dst + 2048 * 2048, E_QKV, (size_t)512 * 2048);
        wsplit(Wv + lk, dst + 2560 * 2048, E_QKV, (size_t)512 * 2048);

        const size_t lg = (size_t)i * 4096 * 2048;
        fp16* dgu = wgu3 + (size_t)i * 8192 * 2048;
        wsplit(Wg + lg, dgu,               E_GU, (size_t)4096 * 2048);
        wsplit(Wu + lg, dgu + 4096 * 2048, E_GU, (size_t)4096 * 2048);
    }
    wsplit(Wo,   wo3,   E_WO,  E_WO);
    wsplit(Wd,   wd3,   E_WD,  E_WD);
    wsplit(Wplg, wplg3, E_WPL, E_WPL);
    wsplit(Wplp, wplp3, E_WPL, E_WPL);

    cudaMemcpyAsync(hs, hidden, (size_t)N_TOK * DMODEL * sizeof(float), cudaMemcpyDeviceToDevice, 0);

    // initial pre-attention norm (layer 0)
    rmsnorm_split_kernel<<<N_TOK, 256>>>(hs, ln_in, h2, E_H2, DMODEL);

    for (int i = 0; i < NLAYER; i++) {
        const int li = STARTL + i;
        const bool full = ((li + 1) % 5) == 0;
        const float* cost = full ? cos_f : cos_s;
        const float* sint = full ? sin_f : sin_s;
        float* Kout = out + (size_t)N_TOK * DMODEL + (size_t)i * 2 * NKV * N_TOK * HDIM;
        float* Vout = Kout + (size_t)NKV * N_TOK * HDIM;

        // ---- fused QKV (mma, 64-col tiles) + fused norms ----
        mma_gemm<64, false, false><<<dim3(3072 / 64, 8), 256, GSMEM64>>>(
            h2, wqkv3 + (size_t)i * 3072 * 2048, (long long)E_H2, (long long)E_QKV,
            qkvraw, nullptr, 0, DMODEL, 3072, 0, 0, 0, 0);
        qkv_norm_kernel<<<dim3(N_TOK, 12), 256>>>(
            qkvraw, qn_w + (size_t)i * HDIM, kn_w + (size_t)i * HDIM, cost, sint,
            Kout, Vout, qt3, kt3, vt3);

        // ---- attention: causal scores, softmax, PV (split epilogue) ----
        mma_gemm<128, true, false><<<dim3(N_TOK / 128, N_TOK / 128, NH), 256, GSMEM128>>>(
            qt3, kt3, (long long)E_QT, (long long)E_KT, scores, nullptr, 0, HDIM, N_TOK,
            (long long)N_TOK * HDIM, (long long)N_TOK * HDIM, (long long)N_TOK * N_TOK, 2);
        softmax_causal_split_kernel<<<NH * N_TOK, 256>>>(scores, p3, E_P3);
        mma_gemm<128, false, true><<<dim3(HDIM / 128, N_TOK / 128, NH), 256, GSMEM128>>>(
            p3, vt3, (long long)E_P3, (long long)E_KT, nullptr, ao3, (long long)E_AO,
            N_TOK, NH * HDIM,
            (long long)N_TOK * N_TOK, (long long)HDIM * N_TOK, (long long)HDIM, 2);

        // ---- Wo (mma) + fused residual + pre-FFN norm ----
        mma_gemm<128, false, false><<<dim3(DMODEL / 128, 8), 256, GSMEM128>>>(
            ao3, wo3 + (size_t)i * 2048 * 2048, (long long)E_AO, (long long)E_WO,
            tmp, nullptr, 0, NH * HDIM, DMODEL, 0, 0, 0, 0);
        add_rms_norm_kernel<<<N_TOK, 256>>>(hs, tmp, ln_pa + (size_t)i * DMODEL, nullptr,
                                            ln_pf + (size_t)i * DMODEL, h2, E_H2);

        // ---- FFN: fused G+U (64-col tiles), gelu*u, Wd (mma) + residual ----
        mma_gemm<64, false, false><<<dim3(8192 / 64, 8), 256, GSMEM64>>>(
            h2, wgu3 + (size_t)i * 8192 * 2048, (long long)E_H2, (long long)E_GU,
            gu, nullptr, 0, DMODEL, 8192, 0, 0, 0, 0);
        gelu_mul_split_kernel<<<(N_TOK * FFDIM + 255) / 256, 256>>>(gu, m2, E_M2, N_TOK * FFDIM);
        mma_gemm<128, false, false><<<dim3(DMODEL / 128, 8), 256, GSMEM128>>>(
            m2, wd3 + (size_t)i * 2048 * 4096, (long long)E_M2, (long long)E_WD,
            tmp, nullptr, 0, FFDIM, DMODEL, 0, 0, 0, 0);
        add_rms_kernel<<<N_TOK, 256>>>(hs, tmp, ln_ff + (size_t)i * DMODEL, nullptr,
                                       hs3, E_H2, DMODEL);

        // ---- per-layer gating (WPLG on 64-col tiles) + fused residual + next norm ----
        mma_gemm<64, false, false><<<dim3(HPL / 64, 8), 256, GSMEM64>>>(
            hs3, wplg3 + (size_t)i * HPL * 2048, (long long)E_H2, (long long)E_WPL,
            plbuf, nullptr, 0, DMODEL, HPL, 0, 0, 0, 0);
        gelu_sl_split_kernel<<<(N_TOK * HPL + 255) / 256, 256>>>(plbuf, plc, li, pl3, E_PL);
        mma_gemm<128, false, false><<<dim3(DMODEL / 128, 8), 256, GSMEM128>>>(
            pl3, wplp3 + (size_t)i * 2048 * HPL, (long long)E_PL, (long long)E_WPL,
            tmp, nullptr, 0, HPL, DMODEL, 0, 0, 0, 0);
        if (i + 1 < NLAYER) {
            add_rms_norm_kernel<<<N_TOK, 256>>>(hs, tmp, ln_pl + (size_t)i * DMODEL, lscale + i,
                                                ln_in + (size_t)(i + 1) * DMODEL, h2, E_H2);
        } else {
            add_rms_kernel<<<N_TOK, 256>>>(hs, tmp, ln_pl + (size_t)i * DMODEL, lscale + i,
                                           nullptr, 0, DMODEL);
        }
    }

    cudaMemcpyAsync(out, hs, (size_t)N_TOK * DMODEL * sizeof(float), cudaMemcpyDeviceToDevice, 0);
}

// round 14
// speedup vs baseline: 3.4139x; 1.0021x over previous
#include <cuda_runtime.h>
#include <cuda_fp16.h>
#include <math.h>
#include <stdint.h>

#define N_TOK 1024
#define DMODEL 2048
#define NH 8
#define NKV 2
#define HDIM 256
#define FFDIM 4096
#define HPL 256
#define NLAYER 7
#define STARTL 8
#define TOTAL_LAYERS 30
#define EPSF 1e-6f
#define SPLIT_SCALE 2048.f
#define SPLIT_INV   (1.f / 2048.f)

typedef __half fp16;

// ======================= plane sizes (elements) =======================
#define E_QKV ((size_t)NLAYER * 3072 * DMODEL)
#define E_WO  ((size_t)NLAYER * DMODEL * (NH * HDIM))
#define E_GU  ((size_t)NLAYER * 8192 * DMODEL)
#define E_WD  ((size_t)NLAYER * DMODEL * FFDIM)
#define E_WPL ((size_t)NLAYER * HPL * DMODEL)
#define E_H2  ((size_t)N_TOK * DMODEL)
#define E_QT  ((size_t)N_TOK * NH * HDIM)
#define E_KT  ((size_t)N_TOK * NKV * HDIM)
#define E_P3  ((size_t)NH * N_TOK * N_TOK)
#define E_AO  ((size_t)N_TOK * NH * HDIM)
#define E_M2  ((size_t)N_TOK * FFDIM)
#define E_PL  ((size_t)N_TOK * HPL)

// ======================= scratch layout (bytes) =======================
#define OFF_WQKV  ((size_t)0)
#define OFF_WO3   (OFF_WQKV + 4 * E_QKV)
#define OFF_WGU   (OFF_WO3  + 4 * E_WO)
#define OFF_WD3   (OFF_WGU  + 4 * E_GU)
#define OFF_WPLG3 (OFF_WD3  + 4 * E_WD)
#define OFF_WPLP3 (OFF_WPLG3 + 4 * E_WPL)
// fp32 activations
#define OFF_HS     (OFF_WPLP3 + 4 * E_WPL)
#define OFF_QKVRAW (OFF_HS     + 4ull * N_TOK * DMODEL)
#define OFF_SC     (OFF_QKVRAW + 4ull * N_TOK * 3072)
#define OFF_TMP    (OFF_SC     + 4ull * E_P3)
#define OFF_GU     (OFF_TMP    + 4ull * N_TOK * DMODEL)
#define OFF_PLB    (OFF_GU     + 4ull * N_TOK * 8192)
// fp16 2-plane activations
#define OFF_H2     (OFF_PLB + 4ull * E_PL)
#define OFF_QT3    (OFF_H2  + 4ull * E_H2)
#define OFF_KT3    (OFF_QT3 + 4ull * E_QT)
#define OFF_VT3    (OFF_KT3 + 4ull * E_KT)
#define OFF_P3     (OFF_VT3 + 4ull * E_KT)
#define OFF_AO3    (OFF_P3  + 4ull * E_P3)
#define OFF_M2     (OFF_AO3 + 4ull * E_AO)
#define OFF_HS3    (OFF_M2  + 4ull * E_M2)
#define OFF_PL3    (OFF_HS3 + 4ull * E_H2)
#define TOTAL_SCR  (OFF_PL3 + 4ull * E_PL)

__device__ __align__(1024) char g_scr[TOTAL_SCR];

// ======================= block reductions =======================
__device__ __forceinline__ float blockReduceSum256(float v) {
    __shared__ float sh[8]; __shared__ float res;
    int lane = threadIdx.x & 31, wid = threadIdx.x >> 5;
    #pragma unroll
    for (int o = 16; o > 0; o >>= 1) v += __shfl_xor_sync(0xffffffffu, v, o);
    if (lane == 0) sh[wid] = v;
    __syncthreads();
    if (wid == 0) {
        float x = (lane < 8) ? sh[lane] : 0.f;
        #pragma unroll
        for (int o = 4; o > 0; o >>= 1) x += __shfl_xor_sync(0xffffffffu, x, o);
        if (lane == 0) res = x;
    }
    __syncthreads();
    return res;
}
__device__ __forceinline__ float blockReduceMax256(float v) {
    __shared__ float sh[8]; __shared__ float res;
    int lane = threadIdx.x & 31, wid = threadIdx.x >> 5;
    #pragma unroll
    for (int o = 16; o > 0; o >>= 1) v = fmaxf(v, __shfl_xor_sync(0xffffffffu, v, o));
    if (lane == 0) sh[wid] = v;
    __syncthreads();
    if (wid == 0) {
        float x = (lane < 8) ? sh[lane] : -INFINITY;
        #pragma unroll
        for (int o = 4; o > 0; o >>= 1) x = fmaxf(x, __shfl_xor_sync(0xffffffffu, x, o));
        if (lane == 0) res = x;
    }
    __syncthreads();
    return res;
}
__device__ __forceinline__ float gelu_tanh(float x) {
    float t = tanhf(0.7978845608028654f * (x + 0.044715f * x * x * x));
    return 0.5f * x * (1.f + t);
}
__device__ __forceinline__ void split2h(float v, fp16& h, fp16& l) {
    h = __float2half_rn(v);
    l = __float2half_rn((v - __half2float(h)) * SPLIT_SCALE);
}

// ======================= norm / elementwise kernels =======================
__global__ void add_rms_kernel(float* __restrict__ hs, const float* __restrict__ x,
                               const float* __restrict__ w,
                               const float* __restrict__ scale_ptr,
                               fp16* __restrict__ dst, size_t elts, int cols) {
    int row = blockIdx.x;
    const float* xr = x + (size_t)row * cols;
    float ss = 0.f;
    for (int c = threadIdx.x; c < cols; c += 256) { float v = xr[c]; ss += v * v; }
    ss = blockReduceSum256(ss);
    float inv = rsqrtf(ss / (float)cols + EPSF);
    float sc = scale_ptr ? *scale_ptr : 1.f;
    float* hr = hs + (size_t)row * cols;
    for (int c = threadIdx.x; c < cols; c += 256) {
        float y = (hr[c] + xr[c] * inv * (1.f + w[c])) * sc;
        hr[c] = y;
        if (dst) {
            fp16 h, l; split2h(y, h, l);
            size_t o = (size_t)row * cols + c;
            dst[o] = h; dst[elts + o] = l;
        }
    }
}

__global__ void add_rms_norm_kernel(float* __restrict__ hs, const float* __restrict__ x,
                                    const float* __restrict__ w1,
                                    const float* __restrict__ scale_ptr,
                                    const float* __restrict__ w2,
                                    fp16* __restrict__ dst, size_t elts) {
    const int cols = DMODEL;
    int row = blockIdx.x;
    const float* xr = x + (size_t)row * cols;
    float* hr = hs + (size_t)row * cols;
    float ss = 0.f;
    #pragma unroll
    for (int q = 0; q < 8; q++) { float v = xr[threadIdx.x + q * 256]; ss += v * v; }
    ss = blockReduceSum256(ss);
    float inv = rsqrtf(ss / (float)cols + EPSF);
    float sc = scale_ptr ? *scale_ptr : 1.f;
    float ys[8];
    float ss2 = 0.f;
    #pragma unroll
    for (int q = 0; q < 8; q++) {
        int c = threadIdx.x + q * 256;
        float y = (hr[c] + xr[c] * inv * (1.f + w1[c])) * sc;
        ys[q] = y; hr[c] = y; ss2 += y * y;
    }
    ss2 = blockReduceSum256(ss2);
    float inv2 = rsqrtf(ss2 / (float)cols + EPSF);
    #pragma unroll
    for (int q = 0; q < 8; q++) {
        int c = threadIdx.x + q * 256;
        float z = ys[q] * inv2 * (1.f + w2[c]);
        fp16 h, l; split2h(z, h, l);
        size_t o = (size_t)row * cols + c;
        dst[o] = h; dst[elts + o] = l;
    }
}

__global__ void qkv_norm_kernel(const float* __restrict__ x,
                                const float* __restrict__ qw, const float* __restrict__ kw,
                                const float* __restrict__ cost, const float* __restrict__ sint,
                                float* __restrict__ Kout, float* __restrict__ Vout,
                                fp16* __restrict__ qt, fp16* __restrict__ kt,
                                fp16* __restrict__ vt) {
    int n = blockIdx.x, g = blockIdx.y, d = threadIdx.x;
    __shared__ float sx[HDIM];
    if (g < 10) {
        const int isq = (g < 8);
        const int h = isq ? g : (g - 8);
        const float* w = isq ? qw : kw;
        const int off = isq ? (h * HDIM) : (2048 + h * HDIM);
        float v = x[(size_t)n * 3072 + off + d];
        float ss = blockReduceSum256(v * v);
        float inv = rsqrtf(ss / (float)HDIM + EPSF);
        float xn = v * inv * (1.f + w[d]);
        sx[d] = xn;
        __syncthreads();
        float rh = (d < HDIM / 2) ? -sx[d + HDIM / 2] : sx[d - HDIM / 2];
        float y = xn * cost[(size_t)n * HDIM + d] + rh * sint[(size_t)n * HDIM + d];
        size_t idx = ((size_t)h * N_TOK + n) * HDIM + d;
        fp16 bh, bl; split2h(y, bh, bl);
        if (isq) {
            qt[idx] = bh; qt[E_QT + idx] = bl;
        } else {
            Kout[idx] = y;
            kt[idx] = bh; kt[E_KT + idx] = bl;
        }
    } else {
        const int h = g - 10;
        float v = x[(size_t)n * 3072 + 2560 + h * HDIM + d];
        float ss = blockReduceSum256(v * v);
        float y = v * rsqrtf(ss / (float)HDIM + EPSF);
        Vout[((size_t)h * N_TOK + n) * HDIM + d] = y;
        fp16 bh, bl; split2h(y, bh, bl);
        size_t tidx = ((size_t)h * HDIM + d) * N_TOK + n;
        vt[tidx] = bh; vt[E_KT + tidx] = bl;
    }
}

__global__ void softmax_causal_split_kernel(const float* __restrict__ p,
                                            fp16* __restrict__ dst, size_t elts) {
    const float* row = p + (size_t)blockIdx.x * N_TOK;
    const int r = blockIdx.x & (N_TOK - 1);
    int base = threadIdx.x * 4;
    float4 r4 = *(const float4*)(row + base);
    float v[4] = {r4.x, r4.y, r4.z, r4.w};
    float m = -INFINITY;
    #pragma unroll
    for (int i = 0; i < 4; i++) if (base + i <= r) m = fmaxf(m, v[i]);
    m = blockReduceMax256(m);
    float e[4];
    #pragma unroll
    for (int i = 0; i < 4; i++) e[i] = (base + i <= r) ? expf(v[i] - m) : 0.f;
    float s = blockReduceSum256(e[0] + e[1] + e[2] + e[3]);
    float invs = 1.f / s;
    union { fp16 b[4]; uint2 u2; } H, L;
    #pragma unroll
    for (int i = 0; i < 4; i++) split2h(e[i] * invs, H.b[i], L.b[i]);
    size_t o = (size_t)blockIdx.x * N_TOK + base;
    *(uint2*)(dst + o) = H.u2;
    *(uint2*)(dst + elts + o) = L.u2;
}

// ======================= fp16x2 mma machinery =======================
__device__ __forceinline__ uint32_t smem_u32(const void* p) {
    uint32_t a;
    asm("{ .reg .u64 t; cvta.to.shared.u64 t, %1; cvt.u32.u64 %0, t; }" : "=r"(a) : "l"(p));
    return a;
}
__device__ __forceinline__ void cp16(uint32_t dst, const void* src) {
    asm volatile("cp.async.cg.shared.global [%0], [%1], 16;" :: "r"(dst), "l"(src) : "memory");
}
__device__ __forceinline__ void ldsm4(uint32_t* r, uint32_t addr) {
    asm volatile("ldmatrix.sync.aligned.m8n8.x4.shared.b16 {%0,%1,%2,%3}, [%4];"
                 : "=r"(r[0]), "=r"(r[1]), "=r"(r[2]), "=r"(r[3]) : "r"(addr));
}
__device__ __forceinline__ void mma_f16(float* d, const uint32_t* a, const uint32_t* b) {
    asm volatile(
        "mma.sync.aligned.m16n8k16.row.col.f32.f16.f16.f32 "
        "{%0,%1,%2,%3}, {%4,%5,%6,%7}, {%8,%9}, {%0,%1,%2,%3};"
        : "+f"(d[0]), "+f"(d[1]), "+f"(d[2]), "+f"(d[3])
        : "r"(a[0]), "r"(a[1]), "r"(a[2]), "r"(a[3]), "r"(b[0]), "r"(b[1]));
}

#define TROWB 80
#define TILEA (128 * TROWB)

// C[z] tile (128 rows x NT cols) = A[z](rows x K) @ B[z>>bshift](M x K)^T
// fp16 2-plane scaled split; dual accumulators; 3-stage cp.async pipeline.
// kcap4: if >0, limit K-chunks to (blockIdx.y+1)*kcap4 (exact for causal-zero P rows).
template <int NT, bool CAUSAL, bool SPLIT>
__global__ void __launch_bounds__(256, 1)
mma_gemm(const fp16* __restrict__ A3, const fp16* __restrict__ B3,
         long long eA, long long eB,
         float* __restrict__ Cf, fp16* __restrict__ C3, long long eC,
         int K, int ldc,
         long long sA, long long sB, long long sC, int bshift, int kcap4) {
    constexpr int TILEB = NT * TROWB;
    constexpr int STG = 2 * TILEA + 2 * TILEB;
    constexpr int NJ = NT / 32;
    if (CAUSAL && (int)blockIdx.x * NT > (int)blockIdx.y * 128 + 127) return;
    extern __shared__ char smem[];
    const uint32_t sb = smem_u32(smem);
    const int tid = threadIdx.x;
    const int bz = blockIdx.z;
    const int row0 = blockIdx.y * 128;
    const int col0 = blockIdx.x * NT;

    const fp16* srcs[4];
    #pragma unroll
    for (int p = 0; p < 2; p++) {
        srcs[p]     = A3 + (size_t)p * eA + (size_t)bz * sA + (size_t)row0 * K;
        srcs[2 + p] = B3 + (size_t)p * eB + (size_t)(bz >> bshift) * sB + (size_t)col0 * K;
    }

    const int lane = tid & 31, wid = tid >> 5;
    const int wm = wid & 3, wn = wid >> 2;
    const int ld_r = tid >> 2;
    const int ld_c = tid & 3;

    uint32_t aoff[2], boff[NJ];
    #pragma unroll
    for (int m = 0; m < 2; m++)
        aoff[m] = (uint32_t)((wm * 32 + m * 16 + (lane & 15)) * TROWB + ((lane >> 4) << 4));
    #pragma unroll
    for (int j = 0; j < NJ; j++)
        boff[j] = (uint32_t)((wn * (NT / 2) + j * 16 + (lane & 7) + ((lane >> 4) << 3)) * TROWB
                             + (((lane >> 3) & 1) << 4));

    float accM[2][2 * NJ][4], accC[2][2 * NJ][4];
    #pragma unroll
    for (int m = 0; m < 2; m++)
        #pragma unroll
        for (int t = 0; t < 2 * NJ; t++)
            #pragma unroll
            for (int u = 0; u < 4; u++) { accM[m][t][u] = 0.f; accC[m][t][u] = 0.f; }

    int nch = K >> 5;
    if (kcap4) { int cap = ((int)blockIdx.y + 1) * kcap4; if (cap < nch) nch = cap; }

    auto issue = [&](int c, uint32_t dstb) {
        const int kb = c << 5;
        #pragma unroll
        for (int q = 0; q < 4; q++) {
            const int r = (q & 1) * 64 + ld_r;
            const char* gsrc = (const char*)(srcs[q >> 1] + (size_t)r * K + kb) + ld_c * 16;
            cp16(dstb + (uint32_t)((q >> 1) * TILEA + r * TROWB + ld_c * 16), gsrc);
        }
        #pragma unroll
        for (int p = 0; p < 2; p++)
            #pragma unroll
            for (int qq = 0; qq < NT / 64; qq++) {
                const int r = qq * 64 + ld_r;
                const char* gsrc = (const char*)(srcs[2 + p] + (size_t)r * K + kb) + ld_c * 16;
                cp16(dstb + (uint32_t)(2 * TILEA + p * TILEB + r * TROWB + ld_c * 16), gsrc);
            }
        asm volatile("cp.async.commit_group;" ::: "memory");
    };

    issue(0, sb);
    if (nch > 1) issue(1, sb + STG);
    if (nch > 2) issue(2, sb + 2 * STG);

    int stage = 0;
    for (int c = 0; c < nch; ++c) {
        const int rem = nch - 1 - c;
        if (rem >= 2)      asm volatile("cp.async.wait_group 2;" ::: "memory");
        else if (rem == 1) asm volatile("cp.async.wait_group 1;" ::: "memory");
        else               asm volatile("cp.async.wait_group 0;" ::: "memory");
        __syncthreads();

        const uint32_t base = sb + (uint32_t)stage * STG;

        #pragma unroll
        for (int kk = 0; kk < 2; kk++) {
            const uint32_t kb = kk * 32;
            uint32_t ah[2][4], al[2][4];
            #pragma unroll
            for (int m = 0; m < 2; m++) {
                ldsm4(ah[m], base + 0 * TILEA + aoff[m] + kb);
                ldsm4(al[m], base + 1 * TILEA + aoff[m] + kb);
            }
            #pragma unroll
            for (int j = 0; j < NJ; j++) {
                uint32_t bh[4], bl[4];
                ldsm4(bh, base + 2 * TILEA + 0 * TILEB + boff[j] + kb);
                ldsm4(bl, base + 2 * TILEA + 1 * TILEB + boff[j] + kb);
                #pragma unroll
                for (int m = 0; m < 2; m++) {
                    #pragma unroll
                    for (int h = 0; h < 2; h++) {
                        float* dM = accM[m][j * 2 + h];
                        float* dC = accC[m][j * 2 + h];
                        mma_f16(dM, ah[m], &bh[h * 2]);   // hh -> main
                        mma_f16(dC, ah[m], &bl[h * 2]);   // corrections (x2048)
                        mma_f16(dC, al[m], &bh[h * 2]);
                    }
                }
            }
        }
        __syncthreads();
        if (c + 3 < nch) issue(c + 3, base);
        stage = (stage == 2) ? 0 : stage + 1;
    }

    const int grp = lane >> 2, qd = lane & 3;
    #pragma unroll
    for (int m = 0; m < 2; m++) {
        #pragma unroll
        for (int t = 0; t < 2 * NJ; t++) {
            const int col = col0 + wn * (NT / 2) + t * 8 + qd * 2;
            #pragma unroll
            for (int half = 0; half < 2; half++) {
                const int row = row0 + wm * 32 + m * 16 + grp + half * 8;
                float v0 = accM[m][t][half * 2 + 0] + accC[m][t][half * 2 + 0] * SPLIT_INV;
                float v1 = accM[m][t][half * 2 + 1] + accC[m][t][half * 2 + 1] * SPLIT_INV;
                const size_t o = (size_t)bz * sC + (size_t)row * ldc + col;
                if (SPLIT) {
                    union { fp16 b[2]; uint32_t u; } H, L;
                    split2h(v0, H.b[0], L.b[0]); split2h(v1, H.b[1], L.b[1]);
                    *(uint32_t*)(C3 + o) = H.u;
                    *(uint32_t*)(C3 + (size_t)eC + o) = L.u;
                } else {
                    float2 o2; o2.x = v0; o2.y = v1;
                    *(float2*)(Cf + o) = o2;
                }
            }
        }
    }
}

#define GSMEM128 (3 * (2 * TILEA + 2 * 128 * TROWB))  // 122880
#define GSMEM64  (3 * (2 * TILEA + 2 * 64 * TROWB))   //  92160

// ======================= split producers =======================
// simple one-float4-per-thread (round-8 form: measured 71% DRAM at full grid)
__global__ void wsplit_kernel(const float* __restrict__ x, fp16* __restrict__ dst,
                              size_t plane, size_t n4) {
    size_t i = (size_t)blockIdx.x * 256 + threadIdx.x;
    if (i >= n4) return;
    float4 v = ((const float4*)x)[i];
    union { fp16 b[4]; uint2 u2; } H, L;
    split2h(v.x, H.b[0], L.b[0]); split2h(v.y, H.b[1], L.b[1]);
    split2h(v.z, H.b[2], L.b[2]); split2h(v.w, H.b[3], L.b[3]);
    ((uint2*)dst)[i] = H.u2;
    ((uint2*)(dst + plane))[i] = L.u2;
}

__global__ void rmsnorm_split_kernel(const float* __restrict__ x, const float* __restrict__ w,
                                     fp16* __restrict__ dst, size_t elts, int cols) {
    int row = blockIdx.x;
    const float* xr = x + (size_t)row * cols;
    float ss = 0.f;
    for (int c = threadIdx.x; c < cols; c += 256) { float v = xr[c]; ss += v * v; }
    ss = blockReduceSum256(ss);
    float inv = rsqrtf(ss / (float)cols + EPSF);
    for (int c = threadIdx.x; c < cols; c += 256) {
        float y = xr[c] * inv * (1.f + w[c]);
        fp16 h, l; split2h(y, h, l);
        size_t o = (size_t)row * cols + c;
        dst[o] = h; dst[elts + o] = l;
    }
}

__global__ void gelu_mul_split_kernel(const float* __restrict__ gu,
                                      fp16* __restrict__ dst, size_t elts, int n) {
    int i = blockIdx.x * 256 + threadIdx.x;
    if (i < n) {
        int row = i >> 12, j = i & 4095;
        float g = gu[(size_t)row * 8192 + j];
        float u = gu[(size_t)row * 8192 + 4096 + j];
        float y = gelu_tanh(g) * u;
        fp16 h, l; split2h(y, h, l);
        dst[i] = h; dst[elts + i] = l;
    }
}

__global__ void gelu_sl_split_kernel(const float* __restrict__ g, const float* __restrict__ plc,
                                     int li, fp16* __restrict__ dst, size_t elts) {
    int i = blockIdx.x * 256 + threadIdx.x;
    if (i < N_TOK * HPL) {
        int n = i >> 8, j = i & 255;
        float y = gelu_tanh(g[i]) * plc[(size_t)n * (TOTAL_LAYERS * HPL) + (size_t)li * HPL + j];
        fp16 h, l; split2h(y, h, l);
        dst[i] = h; dst[elts + i] = l;
    }
}

// ======================= driver =======================
extern "C" void kernel_launch(void* const* d_in, const int* in_sizes, int n_in,
                              void* d_out, int out_size) {
    const float* hidden = (const float*)d_in[0];
    const float* plc    = (const float*)d_in[1];
    const float* cos_s  = (const float*)d_in[3];
    const float* sin_s  = (const float*)d_in[4];
    const float* cos_f  = (const float*)d_in[5];
    const float* sin_f  = (const float*)d_in[6];
    const float* Wq     = (const float*)d_in[7];
    const float* Wk     = (const float*)d_in[8];
    const float* Wv     = (const float*)d_in[9];
    const float* Wo     = (const float*)d_in[10];
    const float* Wg     = (const float*)d_in[11];
    const float* Wu     = (const float*)d_in[12];
    const float* Wd     = (const float*)d_in[13];
    const float* Wplg   = (const float*)d_in[14];
    const float* Wplp   = (const float*)d_in[15];
    const float* ln_in  = (const float*)d_in[16];
    const float* ln_pa  = (const float*)d_in[17];
    const float* ln_pf  = (const float*)d_in[18];
    const float* ln_ff  = (const float*)d_in[19];
    const float* ln_pl  = (const float*)d_in[20];
    const float* qn_w   = (const float*)d_in[21];
    const float* kn_w   = (const float*)d_in[22];
    const float* lscale = (const float*)d_in[23];

    cudaFuncSetAttribute(mma_gemm<128, false, false>, cudaFuncAttributeMaxDynamicSharedMemorySize, GSMEM128);
    cudaFuncSetAttribute(mma_gemm<128, true,  false>, cudaFuncAttributeMaxDynamicSharedMemorySize, GSMEM128);
    cudaFuncSetAttribute(mma_gemm<128, false, true>,  cudaFuncAttributeMaxDynamicSharedMemorySize, GSMEM128);
    cudaFuncSetAttribute(mma_gemm<64,  false, false>, cudaFuncAttributeMaxDynamicSharedMemorySize, GSMEM64);

    char* scr = nullptr;
    cudaGetSymbolAddress((void**)&scr, g_scr);

    fp16* wqkv3 = (fp16*)(scr + OFF_WQKV);
    fp16* wo3   = (fp16*)(scr + OFF_WO3);
    fp16* wgu3  = (fp16*)(scr + OFF_WGU);
    fp16* wd3   = (fp16*)(scr + OFF_WD3);
    fp16* wplg3 = (fp16*)(scr + OFF_WPLG3);
    fp16* wplp3 = (fp16*)(scr + OFF_WPLP3);

    float* hs     = (float*)(scr + OFF_HS);
    float* qkvraw = (float*)(scr + OFF_QKVRAW);
    float* scores = (float*)(scr + OFF_SC);
    float* tmp    = (float*)(scr + OFF_TMP);
    float* gu     = (float*)(scr + OFF_GU);
    float* plbuf  = (float*)(scr + OFF_PLB);
    fp16*  h2     = (fp16*)(scr + OFF_H2);
    fp16*  qt3    = (fp16*)(scr + OFF_QT3);
    fp16*  kt3    = (fp16*)(scr + OFF_KT3);
    fp16*  vt3    = (fp16*)(scr + OFF_VT3);
    fp16*  p3     = (fp16*)(scr + OFF_P3);
    fp16*  ao3    = (fp16*)(scr + OFF_AO3);
    fp16*  m2     = (fp16*)(scr + OFF_M2);
    fp16*  hs3    = (fp16*)(scr + OFF_HS3);
    fp16*  pl3    = (fp16*)(scr + OFF_PL3);

    float* out = (float*)d_out;

    // ---- split weights into fused 2-plane layouts (simple full-grid) ----
    auto wsplit = [&](const float* src, fp16* dst, size_t plane, size_t count) {
        size_t n4 = count / 4;
        wsplit_kernel<<<(unsigned)((n4 + 255) / 256), 256>>>(src, dst, plane, n4);
    };
    for (int i = 0; i < NLAYER; i++) {
        const size_t lq = (size_t)i * 2048 * 2048;
        const size_t lk = (size_t)i * 512 * 2048;
        fp16* dst = wqkv3 + (size_t)i * 3072 * 2048;
        wsplit(Wq + lq, dst,               E_QKV, (size_t)2048 * 2048);
        wsplit(Wk + lk, dst + 2048 * 2048, E_QKV, (size_t)512 * 2048);
        wsplit(Wv + lk, dst + 2560 * 2048, E_QKV, (size_t)512 * 2048);

        const size_t lg = (size_t)i * 4096 * 2048;
        fp16* dgu = wgu3 + (size_t)i * 8192 * 2048;
        wsplit(Wg + lg, dgu,               E_GU, (size_t)4096 * 2048);
        wsplit(Wu + lg, dgu + 4096 * 2048, E_GU, (size_t)4096 * 2048);
    }
    wsplit(Wo,   wo3,   E_WO,  E_WO);
    wsplit(Wd,   wd3,   E_WD,  E_WD);
    wsplit(Wplg, wplg3, E_WPL, E_WPL);
    wsplit(Wplp, wplp3, E_WPL, E_WPL);

    cudaMemcpyAsync(hs, hidden, (size_t)N_TOK * DMODEL * sizeof(float), cudaMemcpyDeviceToDevice, 0);

    // initial pre-attention norm (layer 0)
    rmsnorm_split_kernel<<<N_TOK, 256>>>(hs, ln_in, h2, E_H2, DMODEL);

    for (int i = 0; i < NLAYER; i++) {
        const int li = STARTL + i;
        const bool full = ((li + 1) % 5) == 0;
        const float* cost = full ? cos_f : cos_s;
        const float* sint = full ? sin_f : sin_s;
        float* Kout = out + (size_t)N_TOK * DMODEL + (size_t)i * 2 * NKV * N_TOK * HDIM;
        float* Vout = Kout + (size_t)NKV * N_TOK * HDIM;

        // ---- fused QKV (mma, 64-col tiles) + fused norms ----
        mma_gemm<64, false, false><<<dim3(3072 / 64, 8), 256, GSMEM64>>>(
            h2, wqkv3 + (size_t)i * 3072 * 2048, (long long)E_H2, (long long)E_QKV,
            qkvraw, nullptr, 0, DMODEL, 3072, 0, 0, 0, 0, 0);
        qkv_norm_kernel<<<dim3(N_TOK, 12), 256>>>(
            qkvraw, qn_w + (size_t)i * HDIM, kn_w + (size_t)i * HDIM, cost, sint,
            Kout, Vout, qt3, kt3, vt3);

        // ---- attention: causal scores, softmax, PV (split epilogue + k-cap) ----
        mma_gemm<128, true, false><<<dim3(N_TOK / 128, N_TOK / 128, NH), 256, GSMEM128>>>(
            qt3, kt3, (long long)E_QT, (long long)E_KT, scores, nullptr, 0, HDIM, N_TOK,
            (long long)N_TOK * HDIM, (long long)N_TOK * HDIM, (long long)N_TOK * N_TOK, 2, 0);
        softmax_causal_split_kernel<<<NH * N_TOK, 256>>>(scores, p3, E_P3);
        mma_gemm<128, false, true><<<dim3(HDIM / 128, N_TOK / 128, NH), 256, GSMEM128>>>(
            p3, vt3, (long long)E_P3, (long long)E_KT, nullptr, ao3, (long long)E_AO,
            N_TOK, NH * HDIM,
            (long long)N_TOK * N_TOK, (long long)HDIM * N_TOK, (long long)HDIM, 2, 4);

        // ---- Wo (mma) + fused residual + pre-FFN norm ----
        mma_gemm<128, false, false><<<dim3(DMODEL / 128, 8), 256, GSMEM128>>>(
            ao3, wo3 + (size_t)i * 2048 * 2048, (long long)E_AO, (long long)E_WO,
            tmp, nullptr, 0, NH * HDIM, DMODEL, 0, 0, 0, 0, 0);
        add_rms_norm_kernel<<<N_TOK, 256>>>(hs, tmp, ln_pa + (size_t)i * DMODEL, nullptr,
                                            ln_pf + (size_t)i * DMODEL, h2, E_H2);

        // ---- FFN: fused G+U (64-col tiles), gelu*u, Wd (mma) + residual ----
        mma_gemm<64, false, false><<<dim3(8192 / 64, 8), 256, GSMEM64>>>(
            h2, wgu3 + (size_t)i * 8192 * 2048, (long long)E_H2, (long long)E_GU,
            gu, nullptr, 0, DMODEL, 8192, 0, 0, 0, 0, 0);
        gelu_mul_split_kernel<<<(N_TOK * FFDIM + 255) / 256, 256>>>(gu, m2, E_M2, N_TOK * FFDIM);
        mma_gemm<128, false, false><<<dim3(DMODEL / 128, 8), 256, GSMEM128>>>(
            m2, wd3 + (size_t)i * 2048 * 4096, (long long)E_M2, (long long)E_WD,
            tmp, nullptr, 0, FFDIM, DMODEL, 0, 0, 0, 0, 0);
        add_rms_kernel<<<N_TOK, 256>>>(hs, tmp, ln_ff + (size_t)i * DMODEL, nullptr,
                                       hs3, E_H2, DMODEL);

        // ---- per-layer gating (WPLG on 64-col tiles) + fused residual + next norm ----
        mma_gemm<64, false, false><<<dim3(HPL / 64, 8), 256, GSMEM64>>>(
            hs3, wplg3 + (size_t)i * HPL * 2048, (long long)E_H2, (long long)E_WPL,
            plbuf, nullptr, 0, DMODEL, HPL, 0, 0, 0, 0, 0);
        gelu_sl_split_kernel<<<(N_TOK * HPL + 255) / 256, 256>>>(plbuf, plc, li, pl3, E_PL);
        mma_gemm<128, false, false><<<dim3(DMODEL / 128, 8), 256, GSMEM128>>>(
            pl3, wplp3 + (size_t)i * 2048 * HPL, (long long)E_PL, (long long)E_WPL,
            tmp, nullptr, 0, HPL, DMODEL, 0, 0, 0, 0, 0);
        if (i + 1 < NLAYER) {
            add_rms_norm_kernel<<<N_TOK, 256>>>(hs, tmp, ln_pl + (size_t)i * DMODEL, lscale + i,
                                                ln_in + (size_t)(i + 1) * DMODEL, h2, E_H2);
        } else {
            add_rms_kernel<<<N_TOK, 256>>>(hs, tmp, ln_pl + (size_t)i * DMODEL, lscale + i,
                                           nullptr, 0, DMODEL);
        }
    }

    cudaMemcpyAsync(out, hs, (size_t)N_TOK * DMODEL * sizeof(float), cudaMemcpyDeviceToDevice, 0);
}

// round 15
// speedup vs baseline: 3.7226x; 1.0904x over previous
#include <cuda_runtime.h>
#include <cuda_fp16.h>
#include <math.h>
#include <stdint.h>

#define N_TOK 1024
#define DMODEL 2048
#define NH 8
#define NKV 2
#define HDIM 256
#define FFDIM 4096
#define HPL 256
#define NLAYER 7
#define STARTL 8
#define TOTAL_LAYERS 30
#define EPSF 1e-6f
#define SPLIT_SCALE 2048.f
#define SPLIT_INV   (1.f / 2048.f)

typedef __half fp16;

// ======================= plane sizes (elements) =======================
#define E_QKV ((size_t)NLAYER * 3072 * DMODEL)
#define E_WO  ((size_t)NLAYER * DMODEL * (NH * HDIM))
#define E_GU  ((size_t)NLAYER * 8192 * DMODEL)
#define E_WD  ((size_t)NLAYER * DMODEL * FFDIM)
#define E_WPL ((size_t)NLAYER * HPL * DMODEL)
#define E_H2  ((size_t)N_TOK * DMODEL)
#define E_QT  ((size_t)N_TOK * NH * HDIM)
#define E_KT  ((size_t)N_TOK * NKV * HDIM)
#define E_P3  ((size_t)NH * N_TOK * N_TOK)
#define E_AO  ((size_t)N_TOK * NH * HDIM)
#define E_M2  ((size_t)N_TOK * FFDIM)
#define E_PL  ((size_t)N_TOK * HPL)

// ======================= scratch layout (bytes) =======================
#define OFF_WQKV  ((size_t)0)
#define OFF_WO3   (OFF_WQKV + 4 * E_QKV)
#define OFF_WGU   (OFF_WO3  + 4 * E_WO)
#define OFF_WD3   (OFF_WGU  + 4 * E_GU)
#define OFF_WPLG3 (OFF_WD3  + 4 * E_WD)
#define OFF_WPLP3 (OFF_WPLG3 + 4 * E_WPL)
// fp32 activations
#define OFF_HS     (OFF_WPLP3 + 4 * E_WPL)
#define OFF_QKVRAW (OFF_HS     + 4ull * N_TOK * DMODEL)
#define OFF_SC     (OFF_QKVRAW + 4ull * N_TOK * 3072)
#define OFF_TMP    (OFF_SC     + 4ull * E_P3)
#define OFF_GU     (OFF_TMP    + 4ull * N_TOK * DMODEL)
#define OFF_PLB    (OFF_GU     + 4ull * N_TOK * 8192)
// fp16 2-plane activations
#define OFF_H2     (OFF_PLB + 4ull * E_PL)
#define OFF_QT3    (OFF_H2  + 4ull * E_H2)
#define OFF_KT3    (OFF_QT3 + 4ull * E_QT)
#define OFF_VT3    (OFF_KT3 + 4ull * E_KT)
#define OFF_P3     (OFF_VT3 + 4ull * E_KT)
#define OFF_AO3    (OFF_P3  + 4ull * E_P3)
#define OFF_M2     (OFF_AO3 + 4ull * E_AO)
#define OFF_HS3    (OFF_M2  + 4ull * E_M2)
#define OFF_PL3    (OFF_HS3 + 4ull * E_H2)
#define TOTAL_SCR  (OFF_PL3 + 4ull * E_PL)

__device__ __align__(1024) char g_scr[TOTAL_SCR];

// ======================= block reductions =======================
__device__ __forceinline__ float blockReduceSum256(float v) {
    __shared__ float sh[8]; __shared__ float res;
    int lane = threadIdx.x & 31, wid = threadIdx.x >> 5;
    #pragma unroll
    for (int o = 16; o > 0; o >>= 1) v += __shfl_xor_sync(0xffffffffu, v, o);
    if (lane == 0) sh[wid] = v;
    __syncthreads();
    if (wid == 0) {
        float x = (lane < 8) ? sh[lane] : 0.f;
        #pragma unroll
        for (int o = 4; o > 0; o >>= 1) x += __shfl_xor_sync(0xffffffffu, x, o);
        if (lane == 0) res = x;
    }
    __syncthreads();
    return res;
}
__device__ __forceinline__ float blockReduceMax256(float v) {
    __shared__ float sh[8]; __shared__ float res;
    int lane = threadIdx.x & 31, wid = threadIdx.x >> 5;
    #pragma unroll
    for (int o = 16; o > 0; o >>= 1) v = fmaxf(v, __shfl_xor_sync(0xffffffffu, v, o));
    if (lane == 0) sh[wid] = v;
    __syncthreads();
    if (wid == 0) {
        float x = (lane < 8) ? sh[lane] : -INFINITY;
        #pragma unroll
        for (int o = 4; o > 0; o >>= 1) x = fmaxf(x, __shfl_xor_sync(0xffffffffu, x, o));
        if (lane == 0) res = x;
    }
    __syncthreads();
    return res;
}
__device__ __forceinline__ float gelu_tanh(float x) {
    float t = tanhf(0.7978845608028654f * (x + 0.044715f * x * x * x));
    return 0.5f * x * (1.f + t);
}
__device__ __forceinline__ void split2h(float v, fp16& h, fp16& l) {
    h = __float2half_rn(v);
    l = __float2half_rn((v - __half2float(h)) * SPLIT_SCALE);
}

// ======================= norm / elementwise kernels =======================
__global__ void add_rms_kernel(float* __restrict__ hs, const float* __restrict__ x,
                               const float* __restrict__ w,
                               const float* __restrict__ scale_ptr,
                               fp16* __restrict__ dst, size_t elts, int cols) {
    int row = blockIdx.x;
    const float* xr = x + (size_t)row * cols;
    float ss = 0.f;
    for (int c = threadIdx.x; c < cols; c += 256) { float v = xr[c]; ss += v * v; }
    ss = blockReduceSum256(ss);
    float inv = rsqrtf(ss / (float)cols + EPSF);
    float sc = scale_ptr ? *scale_ptr : 1.f;
    float* hr = hs + (size_t)row * cols;
    for (int c = threadIdx.x; c < cols; c += 256) {
        float y = (hr[c] + xr[c] * inv * (1.f + w[c])) * sc;
        hr[c] = y;
        if (dst) {
            fp16 h, l; split2h(y, h, l);
            size_t o = (size_t)row * cols + c;
            dst[o] = h; dst[elts + o] = l;
        }
    }
}

__global__ void add_rms_norm_kernel(float* __restrict__ hs, const float* __restrict__ x,
                                    const float* __restrict__ w1,
                                    const float* __restrict__ scale_ptr,
                                    const float* __restrict__ w2,
                                    fp16* __restrict__ dst, size_t elts) {
    const int cols = DMODEL;
    int row = blockIdx.x;
    const float* xr = x + (size_t)row * cols;
    float* hr = hs + (size_t)row * cols;
    float ss = 0.f;
    #pragma unroll
    for (int q = 0; q < 8; q++) { float v = xr[threadIdx.x + q * 256]; ss += v * v; }
    ss = blockReduceSum256(ss);
    float inv = rsqrtf(ss / (float)cols + EPSF);
    float sc = scale_ptr ? *scale_ptr : 1.f;
    float ys[8];
    float ss2 = 0.f;
    #pragma unroll
    for (int q = 0; q < 8; q++) {
        int c = threadIdx.x + q * 256;
        float y = (hr[c] + xr[c] * inv * (1.f + w1[c])) * sc;
        ys[q] = y; hr[c] = y; ss2 += y * y;
    }
    ss2 = blockReduceSum256(ss2);
    float inv2 = rsqrtf(ss2 / (float)cols + EPSF);
    #pragma unroll
    for (int q = 0; q < 8; q++) {
        int c = threadIdx.x + q * 256;
        float z = ys[q] * inv2 * (1.f + w2[c]);
        fp16 h, l; split2h(z, h, l);
        size_t o = (size_t)row * cols + c;
        dst[o] = h; dst[elts + o] = l;
    }
}

__global__ void qkv_norm_kernel(const float* __restrict__ x,
                                const float* __restrict__ qw, const float* __restrict__ kw,
                                const float* __restrict__ cost, const float* __restrict__ sint,
                                float* __restrict__ Kout, float* __restrict__ Vout,
                                fp16* __restrict__ qt, fp16* __restrict__ kt,
                                fp16* __restrict__ vt) {
    int n = blockIdx.x, g = blockIdx.y, d = threadIdx.x;
    __shared__ float sx[HDIM];
    if (g < 10) {
        const int isq = (g < 8);
        const int h = isq ? g : (g - 8);
        const float* w = isq ? qw : kw;
        const int off = isq ? (h * HDIM) : (2048 + h * HDIM);
        float v = x[(size_t)n * 3072 + off + d];
        float ss = blockReduceSum256(v * v);
        float inv = rsqrtf(ss / (float)HDIM + EPSF);
        float xn = v * inv * (1.f + w[d]);
        sx[d] = xn;
        __syncthreads();
        float rh = (d < HDIM / 2) ? -sx[d + HDIM / 2] : sx[d - HDIM / 2];
        float y = xn * cost[(size_t)n * HDIM + d] + rh * sint[(size_t)n * HDIM + d];
        size_t idx = ((size_t)h * N_TOK + n) * HDIM + d;
        fp16 bh, bl; split2h(y, bh, bl);
        if (isq) {
            qt[idx] = bh; qt[E_QT + idx] = bl;
        } else {
            Kout[idx] = y;
            kt[idx] = bh; kt[E_KT + idx] = bl;
        }
    } else {
        const int h = g - 10;
        float v = x[(size_t)n * 3072 + 2560 + h * HDIM + d];
        float ss = blockReduceSum256(v * v);
        float y = v * rsqrtf(ss / (float)HDIM + EPSF);
        Vout[((size_t)h * N_TOK + n) * HDIM + d] = y;
        fp16 bh, bl; split2h(y, bh, bl);
        size_t tidx = ((size_t)h * HDIM + d) * N_TOK + n;
        vt[tidx] = bh; vt[E_KT + tidx] = bl;
    }
}

__global__ void softmax_causal_split_kernel(const float* __restrict__ p,
                                            fp16* __restrict__ dst, size_t elts) {
    const float* row = p + (size_t)blockIdx.x * N_TOK;
    const int r = blockIdx.x & (N_TOK - 1);
    int base = threadIdx.x * 4;
    float4 r4 = *(const float4*)(row + base);
    float v[4] = {r4.x, r4.y, r4.z, r4.w};
    float m = -INFINITY;
    #pragma unroll
    for (int i = 0; i < 4; i++) if (base + i <= r) m = fmaxf(m, v[i]);
    m = blockReduceMax256(m);
    float e[4];
    #pragma unroll
    for (int i = 0; i < 4; i++) e[i] = (base + i <= r) ? expf(v[i] - m) : 0.f;
    float s = blockReduceSum256(e[0] + e[1] + e[2] + e[3]);
    float invs = 1.f / s;
    union { fp16 b[4]; uint2 u2; } H, L;
    #pragma unroll
    for (int i = 0; i < 4; i++) split2h(e[i] * invs, H.b[i], L.b[i]);
    size_t o = (size_t)blockIdx.x * N_TOK + base;
    *(uint2*)(dst + o) = H.u2;
    *(uint2*)(dst + elts + o) = L.u2;
}

// ======================= fp16x2 mma machinery =======================
__device__ __forceinline__ uint32_t smem_u32(const void* p) {
    uint32_t a;
    asm("{ .reg .u64 t; cvta.to.shared.u64 t, %1; cvt.u32.u64 %0, t; }" : "=r"(a) : "l"(p));
    return a;
}
__device__ __forceinline__ void cp16(uint32_t dst, const void* src) {
    asm volatile("cp.async.cg.shared.global [%0], [%1], 16;" :: "r"(dst), "l"(src) : "memory");
}
__device__ __forceinline__ void ldsm4(uint32_t* r, uint32_t addr) {
    asm volatile("ldmatrix.sync.aligned.m8n8.x4.shared.b16 {%0,%1,%2,%3}, [%4];"
                 : "=r"(r[0]), "=r"(r[1]), "=r"(r[2]), "=r"(r[3]) : "r"(addr));
}
__device__ __forceinline__ void mma_f16(float* d, const uint32_t* a, const uint32_t* b) {
    asm volatile(
        "mma.sync.aligned.m16n8k16.row.col.f32.f16.f16.f32 "
        "{%0,%1,%2,%3}, {%4,%5,%6,%7}, {%8,%9}, {%0,%1,%2,%3};"
        : "+f"(d[0]), "+f"(d[1]), "+f"(d[2]), "+f"(d[3])
        : "r"(a[0]), "r"(a[1]), "r"(a[2]), "r"(a[3]), "r"(b[0]), "r"(b[1]));
}

#define TROWB 80
#define TILEA (128 * TROWB)

// C[z] tile (128 rows x NT cols) = A[z](rows x K) @ B[z>>bshift](M x K)^T
// fp16 2-plane scaled split; dual accumulators; 3-stage cp.async pipeline.
// NT=64 kernels request 2 CTAs/SM (regs<=128) for cross-CTA stall hiding.
// kcap4: if >0, limit K-chunks to (blockIdx.y+1)*kcap4 (exact for causal-zero P rows).
template <int NT, bool CAUSAL, bool SPLIT>
__global__ void __launch_bounds__(256, NT == 64 ? 2 : 1)
mma_gemm(const fp16* __restrict__ A3, const fp16* __restrict__ B3,
         long long eA, long long eB,
         float* __restrict__ Cf, fp16* __restrict__ C3, long long eC,
         int K, int ldc,
         long long sA, long long sB, long long sC, int bshift, int kcap4) {
    constexpr int TILEB = NT * TROWB;
    constexpr int STG = 2 * TILEA + 2 * TILEB;
    constexpr int NJ = NT / 32;
    if (CAUSAL && (int)blockIdx.x * NT > (int)blockIdx.y * 128 + 127) return;
    extern __shared__ char smem[];
    const uint32_t sb = smem_u32(smem);
    const int tid = threadIdx.x;
    const int bz = blockIdx.z;
    const int row0 = blockIdx.y * 128;
    const int col0 = blockIdx.x * NT;

    const fp16* srcs[4];
    #pragma unroll
    for (int p = 0; p < 2; p++) {
        srcs[p]     = A3 + (size_t)p * eA + (size_t)bz * sA + (size_t)row0 * K;
        srcs[2 + p] = B3 + (size_t)p * eB + (size_t)(bz >> bshift) * sB + (size_t)col0 * K;
    }

    const int lane = tid & 31, wid = tid >> 5;
    const int wm = wid & 3, wn = wid >> 2;
    const int ld_r = tid >> 2;
    const int ld_c = tid & 3;

    uint32_t aoff[2], boff[NJ];
    #pragma unroll
    for (int m = 0; m < 2; m++)
        aoff[m] = (uint32_t)((wm * 32 + m * 16 + (lane & 15)) * TROWB + ((lane >> 4) << 4));
    #pragma unroll
    for (int j = 0; j < NJ; j++)
        boff[j] = (uint32_t)((wn * (NT / 2) + j * 16 + (lane & 7) + ((lane >> 4) << 3)) * TROWB
                             + (((lane >> 3) & 1) << 4));

    float accM[2][2 * NJ][4], accC[2][2 * NJ][4];
    #pragma unroll
    for (int m = 0; m < 2; m++)
        #pragma unroll
        for (int t = 0; t < 2 * NJ; t++)
            #pragma unroll
            for (int u = 0; u < 4; u++) { accM[m][t][u] = 0.f; accC[m][t][u] = 0.f; }

    int nch = K >> 5;
    if (kcap4) { int cap = ((int)blockIdx.y + 1) * kcap4; if (cap < nch) nch = cap; }

    auto issue = [&](int c, uint32_t dstb) {
        const int kb = c << 5;
        #pragma unroll
        for (int q = 0; q < 4; q++) {
            const int r = (q & 1) * 64 + ld_r;
            const char* gsrc = (const char*)(srcs[q >> 1] + (size_t)r * K + kb) + ld_c * 16;
            cp16(dstb + (uint32_t)((q >> 1) * TILEA + r * TROWB + ld_c * 16), gsrc);
        }
        #pragma unroll
        for (int p = 0; p < 2; p++)
            #pragma unroll
            for (int qq = 0; qq < NT / 64; qq++) {
                const int r = qq * 64 + ld_r;
                const char* gsrc = (const char*)(srcs[2 + p] + (size_t)r * K + kb) + ld_c * 16;
                cp16(dstb + (uint32_t)(2 * TILEA + p * TILEB + r * TROWB + ld_c * 16), gsrc);
            }
        asm volatile("cp.async.commit_group;" ::: "memory");
    };

    issue(0, sb);
    if (nch > 1) issue(1, sb + STG);
    if (nch > 2) issue(2, sb + 2 * STG);

    int stage = 0;
    for (int c = 0; c < nch; ++c) {
        const int rem = nch - 1 - c;
        if (rem >= 2)      asm volatile("cp.async.wait_group 2;" ::: "memory");
        else if (rem == 1) asm volatile("cp.async.wait_group 1;" ::: "memory");
        else               asm volatile("cp.async.wait_group 0;" ::: "memory");
        __syncthreads();

        const uint32_t base = sb + (uint32_t)stage * STG;

        #pragma unroll
        for (int kk = 0; kk < 2; kk++) {
            const uint32_t kb = kk * 32;
            uint32_t ah[2][4], al[2][4];
            #pragma unroll
            for (int m = 0; m < 2; m++) {
                ldsm4(ah[m], base + 0 * TILEA + aoff[m] + kb);
                ldsm4(al[m], base + 1 * TILEA + aoff[m] + kb);
            }
            #pragma unroll
            for (int j = 0; j < NJ; j++) {
                uint32_t bh[4], bl[4];
                ldsm4(bh, base + 2 * TILEA + 0 * TILEB + boff[j] + kb);
                ldsm4(bl, base + 2 * TILEA + 1 * TILEB + boff[j] + kb);
                #pragma unroll
                for (int m = 0; m < 2; m++) {
                    #pragma unroll
                    for (int h = 0; h < 2; h++) {
                        float* dM = accM[m][j * 2 + h];
                        float* dC = accC[m][j * 2 + h];
                        mma_f16(dM, ah[m], &bh[h * 2]);   // hh -> main
                        mma_f16(dC, ah[m], &bl[h * 2]);   // corrections (x2048)
                        mma_f16(dC, al[m], &bh[h * 2]);
                    }
                }
            }
        }
        __syncthreads();
        if (c + 3 < nch) issue(c + 3, base);
        stage = (stage == 2) ? 0 : stage + 1;
    }

    const int grp = lane >> 2, qd = lane & 3;
    #pragma unroll
    for (int m = 0; m < 2; m++) {
        #pragma unroll
        for (int t = 0; t < 2 * NJ; t++) {
            const int col = col0 + wn * (NT / 2) + t * 8 + qd * 2;
            #pragma unroll
            for (int half = 0; half < 2; half++) {
                const int row = row0 + wm * 32 + m * 16 + grp + half * 8;
                float v0 = accM[m][t][half * 2 + 0] + accC[m][t][half * 2 + 0] * SPLIT_INV;
                float v1 = accM[m][t][half * 2 + 1] + accC[m][t][half * 2 + 1] * SPLIT_INV;
                const size_t o = (size_t)bz * sC + (size_t)row * ldc + col;
                if (SPLIT) {
                    union { fp16 b[2]; uint32_t u; } H, L;
                    split2h(v0, H.b[0], L.b[0]); split2h(v1, H.b[1], L.b[1]);
                    *(uint32_t*)(C3 + o) = H.u;
                    *(uint32_t*)(C3 + (size_t)eC + o) = L.u;
                } else {
                    float2 o2; o2.x = v0; o2.y = v1;
                    *(float2*)(Cf + o) = o2;
                }
            }
        }
    }
}

#define GSMEM128 (3 * (2 * TILEA + 2 * 128 * TROWB))  // 122880
#define GSMEM64  (3 * (2 * TILEA + 2 * 64 * TROWB))   //  92160

// ======================= split producers =======================
__global__ void wsplit_kernel(const float* __restrict__ x, fp16* __restrict__ dst,
                              size_t plane, size_t n4) {
    size_t i = (size_t)blockIdx.x * 256 + threadIdx.x;
    if (i >= n4) return;
    float4 v = ((const float4*)x)[i];
    union { fp16 b[4]; uint2 u2; } H, L;
    split2h(v.x, H.b[0], L.b[0]); split2h(v.y, H.b[1], L.b[1]);
    split2h(v.z, H.b[2], L.b[2]); split2h(v.w, H.b[3], L.b[3]);
    ((uint2*)dst)[i] = H.u2;
    ((uint2*)(dst + plane))[i] = L.u2;
}

__global__ void rmsnorm_split_kernel(const float* __restrict__ x, const float* __restrict__ w,
                                     fp16* __restrict__ dst, size_t elts, int cols) {
    int row = blockIdx.x;
    const float* xr = x + (size_t)row * cols;
    float ss = 0.f;
    for (int c = threadIdx.x; c < cols; c += 256) { float v = xr[c]; ss += v * v; }
    ss = blockReduceSum256(ss);
    float inv = rsqrtf(ss / (float)cols + EPSF);
    for (int c = threadIdx.x; c < cols; c += 256) {
        float y = xr[c] * inv * (1.f + w[c]);
        fp16 h, l; split2h(y, h, l);
        size_t o = (size_t)row * cols + c;
        dst[o] = h; dst[elts + o] = l;
    }
}

__global__ void gelu_mul_split_kernel(const float* __restrict__ gu,
                                      fp16* __restrict__ dst, size_t elts, int n) {
    int i = blockIdx.x * 256 + threadIdx.x;
    if (i < n) {
        int row = i >> 12, j = i & 4095;
        float g = gu[(size_t)row * 8192 + j];
        float u = gu[(size_t)row * 8192 + 4096 + j];
        float y = gelu_tanh(g) * u;
        fp16 h, l; split2h(y, h, l);
        dst[i] = h; dst[elts + i] = l;
    }
}

__global__ void gelu_sl_split_kernel(const float* __restrict__ g, const float* __restrict__ plc,
                                     int li, fp16* __restrict__ dst, size_t elts) {
    int i = blockIdx.x * 256 + threadIdx.x;
    if (i < N_TOK * HPL) {
        int n = i >> 8, j = i & 255;
        float y = gelu_tanh(g[i]) * plc[(size_t)n * (TOTAL_LAYERS * HPL) + (size_t)li * HPL + j];
        fp16 h, l; split2h(y, h, l);
        dst[i] = h; dst[elts + i] = l;
    }
}

// ======================= driver =======================
extern "C" void kernel_launch(void* const* d_in, const int* in_sizes, int n_in,
                              void* d_out, int out_size) {
    const float* hidden = (const float*)d_in[0];
    const float* plc    = (const float*)d_in[1];
    const float* cos_s  = (const float*)d_in[3];
    const float* sin_s  = (const float*)d_in[4];
    const float* cos_f  = (const float*)d_in[5];
    const float* sin_f  = (const float*)d_in[6];
    const float* Wq     = (const float*)d_in[7];
    const float* Wk     = (const float*)d_in[8];
    const float* Wv     = (const float*)d_in[9];
    const float* Wo     = (const float*)d_in[10];
    const float* Wg     = (const float*)d_in[11];
    const float* Wu     = (const float*)d_in[12];
    const float* Wd     = (const float*)d_in[13];
    const float* Wplg   = (const float*)d_in[14];
    const float* Wplp   = (const float*)d_in[15];
    const float* ln_in  = (const float*)d_in[16];
    const float* ln_pa  = (const float*)d_in[17];
    const float* ln_pf  = (const float*)d_in[18];
    const float* ln_ff  = (const float*)d_in[19];
    const float* ln_pl  = (const float*)d_in[20];
    const float* qn_w   = (const float*)d_in[21];
    const float* kn_w   = (const float*)d_in[22];
    const float* lscale = (const float*)d_in[23];

    cudaFuncSetAttribute(mma_gemm<128, false, false>, cudaFuncAttributeMaxDynamicSharedMemorySize, GSMEM128);
    cudaFuncSetAttribute(mma_gemm<64,  true,  false>, cudaFuncAttributeMaxDynamicSharedMemorySize, GSMEM64);
    cudaFuncSetAttribute(mma_gemm<64,  false, true>,  cudaFuncAttributeMaxDynamicSharedMemorySize, GSMEM64);
    cudaFuncSetAttribute(mma_gemm<64,  false, false>, cudaFuncAttributeMaxDynamicSharedMemorySize, GSMEM64);

    char* scr = nullptr;
    cudaGetSymbolAddress((void**)&scr, g_scr);

    fp16* wqkv3 = (fp16*)(scr + OFF_WQKV);
    fp16* wo3   = (fp16*)(scr + OFF_WO3);
    fp16* wgu3  = (fp16*)(scr + OFF_WGU);
    fp16* wd3   = (fp16*)(scr + OFF_WD3);
    fp16* wplg3 = (fp16*)(scr + OFF_WPLG3);
    fp16* wplp3 = (fp16*)(scr + OFF_WPLP3);

    float* hs     = (float*)(scr + OFF_HS);
    float* qkvraw = (float*)(scr + OFF_QKVRAW);
    float* scores = (float*)(scr + OFF_SC);
    float* tmp    = (float*)(scr + OFF_TMP);
    float* gu     = (float*)(scr + OFF_GU);
    float* plbuf  = (float*)(scr + OFF_PLB);
    fp16*  h2     = (fp16*)(scr + OFF_H2);
    fp16*  qt3    = (fp16*)(scr + OFF_QT3);
    fp16*  kt3    = (fp16*)(scr + OFF_KT3);
    fp16*  vt3    = (fp16*)(scr + OFF_VT3);
    fp16*  p3     = (fp16*)(scr + OFF_P3);
    fp16*  ao3    = (fp16*)(scr + OFF_AO3);
    fp16*  m2     = (fp16*)(scr + OFF_M2);
    fp16*  hs3    = (fp16*)(scr + OFF_HS3);
    fp16*  pl3    = (fp16*)(scr + OFF_PL3);

    float* out = (float*)d_out;

    // ---- split weights into fused 2-plane layouts ----
    auto wsplit = [&](const float* src, fp16* dst, size_t plane, size_t count) {
        size_t n4 = count / 4;
        wsplit_kernel<<<(unsigned)((n4 + 255) / 256), 256>>>(src, dst, plane, n4);
    };
    for (int i = 0; i < NLAYER; i++) {
        const size_t lq = (size_t)i * 2048 * 2048;
        const size_t lk = (size_t)i * 512 * 2048;
        fp16* dst = wqkv3 + (size_t)i * 3072 * 2048;
        wsplit(Wq + lq, dst,               E_QKV, (size_t)2048 * 2048);
        wsplit(Wk + lk, dst + 2048 * 2048, E_QKV, (size_t)512 * 2048);
        wsplit(Wv + lk, dst + 2560 * 2048, E_QKV, (size_t)512 * 2048);

        const size_t lg = (size_t)i * 4096 * 2048;
        fp16* dgu = wgu3 + (size_t)i * 8192 * 2048;
        wsplit(Wg + lg, dgu,               E_GU, (size_t)4096 * 2048);
        wsplit(Wu + lg, dgu + 4096 * 2048, E_GU, (size_t)4096 * 2048);
    }
    wsplit(Wo,   wo3,   E_WO,  E_WO);
    wsplit(Wd,   wd3,   E_WD,  E_WD);
    wsplit(Wplg, wplg3, E_WPL, E_WPL);
    wsplit(Wplp, wplp3, E_WPL, E_WPL);

    cudaMemcpyAsync(hs, hidden, (size_t)N_TOK * DMODEL * sizeof(float), cudaMemcpyDeviceToDevice, 0);

    // initial pre-attention norm (layer 0)
    rmsnorm_split_kernel<<<N_TOK, 256>>>(hs, ln_in, h2, E_H2, DMODEL);

    for (int i = 0; i < NLAYER; i++) {
        const int li = STARTL + i;
        const bool full = ((li + 1) % 5) == 0;
        const float* cost = full ? cos_f : cos_s;
        const float* sint = full ? sin_f : sin_s;
        float* Kout = out + (size_t)N_TOK * DMODEL + (size_t)i * 2 * NKV * N_TOK * HDIM;
        float* Vout = Kout + (size_t)NKV * N_TOK * HDIM;

        // ---- fused QKV (mma, 64-col tiles, 2 CTA/SM) + fused norms ----
        mma_gemm<64, false, false><<<dim3(3072 / 64, 8), 256, GSMEM64>>>(
            h2, wqkv3 + (size_t)i * 3072 * 2048, (long long)E_H2, (long long)E_QKV,
            qkvraw, nullptr, 0, DMODEL, 3072, 0, 0, 0, 0, 0);
        qkv_norm_kernel<<<dim3(N_TOK, 12), 256>>>(
            qkvraw, qn_w + (size_t)i * HDIM, kn_w + (size_t)i * HDIM, cost, sint,
            Kout, Vout, qt3, kt3, vt3);

        // ---- attention: causal scores (64-col), softmax, PV (64-col + k-cap) ----
        mma_gemm<64, true, false><<<dim3(N_TOK / 64, N_TOK / 128, NH), 256, GSMEM64>>>(
            qt3, kt3, (long long)E_QT, (long long)E_KT, scores, nullptr, 0, HDIM, N_TOK,
            (long long)N_TOK * HDIM, (long long)N_TOK * HDIM, (long long)N_TOK * N_TOK, 2, 0);
        softmax_causal_split_kernel<<<NH * N_TOK, 256>>>(scores, p3, E_P3);
        mma_gemm<64, false, true><<<dim3(HDIM / 64, N_TOK / 128, NH), 256, GSMEM64>>>(
            p3, vt3, (long long)E_P3, (long long)E_KT, nullptr, ao3, (long long)E_AO,
            N_TOK, NH * HDIM,
            (long long)N_TOK * N_TOK, (long long)HDIM * N_TOK, (long long)HDIM, 2, 4);

        // ---- Wo (mma) + fused residual + pre-FFN norm ----
        mma_gemm<128, false, false><<<dim3(DMODEL / 128, 8), 256, GSMEM128>>>(
            ao3, wo3 + (size_t)i * 2048 * 2048, (long long)E_AO, (long long)E_WO,
            tmp, nullptr, 0, NH * HDIM, DMODEL, 0, 0, 0, 0, 0);
        add_rms_norm_kernel<<<N_TOK, 256>>>(hs, tmp, ln_pa + (size_t)i * DMODEL, nullptr,
                                            ln_pf + (size_t)i * DMODEL, h2, E_H2);

        // ---- FFN: fused G+U (64-col, 2 CTA/SM), gelu*u, Wd (mma) + residual ----
        mma_gemm<64, false, false><<<dim3(8192 / 64, 8), 256, GSMEM64>>>(
            h2, wgu3 + (size_t)i * 8192 * 2048, (long long)E_H2, (long long)E_GU,
            gu, nullptr, 0, DMODEL, 8192, 0, 0, 0, 0, 0);
        gelu_mul_split_kernel<<<(N_TOK * FFDIM + 255) / 256, 256>>>(gu, m2, E_M2, N_TOK * FFDIM);
        mma_gemm<128, false, false><<<dim3(DMODEL / 128, 8), 256, GSMEM128>>>(
            m2, wd3 + (size_t)i * 2048 * 4096, (long long)E_M2, (long long)E_WD,
            tmp, nullptr, 0, FFDIM, DMODEL, 0, 0, 0, 0, 0);
        add_rms_kernel<<<N_TOK, 256>>>(hs, tmp, ln_ff + (size_t)i * DMODEL, nullptr,
                                       hs3, E_H2, DMODEL);

        // ---- per-layer gating (64-col) + fused residual + next norm ----
        mma_gemm<64, false, false><<<dim3(HPL / 64, 8), 256, GSMEM64>>>(
            hs3, wplg3 + (size_t)i * HPL * 2048, (long long)E_H2, (long long)E_WPL,
            plbuf, nullptr, 0, DMODEL, HPL, 0, 0, 0, 0, 0);
        gelu_sl_split_kernel<<<(N_TOK * HPL + 255) / 256, 256>>>(plbuf, plc, li, pl3, E_PL);
        mma_gemm<128, false, false><<<dim3(DMODEL / 128, 8), 256, GSMEM128>>>(
            pl3, wplp3 + (size_t)i * 2048 * HPL, (long long)E_PL, (long long)E_WPL,
            tmp, nullptr, 0, HPL, DMODEL, 0, 0, 0, 0, 0);
        if (i + 1 < NLAYER) {
            add_rms_norm_kernel<<<N_TOK, 256>>>(hs, tmp, ln_pl + (size_t)i * DMODEL, lscale + i,
                                                ln_in + (size_t)(i + 1) * DMODEL, h2, E_H2);
        } else {
            add_rms_kernel<<<N_TOK, 256>>>(hs, tmp, ln_pl + (size_t)i * DMODEL, lscale + i,
                                           nullptr, 0, DMODEL);
        }
    }

    cudaMemcpyAsync(out, hs, (size_t)N_TOK * DMODEL * sizeof(float), cudaMemcpyDeviceToDevice, 0);
}

// round 16
// speedup vs baseline: 3.7402x; 1.0047x over previous
#include <cuda_runtime.h>
#include <cuda_fp16.h>
#include <math.h>
#include <stdint.h>

#define N_TOK 1024
#define DMODEL 2048
#define NH 8
#define NKV 2
#define HDIM 256
#define FFDIM 4096
#define HPL 256
#define NLAYER 7
#define STARTL 8
#define TOTAL_LAYERS 30
#define EPSF 1e-6f
#define SPLIT_SCALE 2048.f
#define SPLIT_INV   (1.f / 2048.f)

typedef __half fp16;

// ======================= plane sizes (elements) =======================
#define E_QKV ((size_t)NLAYER * 3072 * DMODEL)
#define E_WO  ((size_t)NLAYER * DMODEL * (NH * HDIM))
#define E_GU  ((size_t)NLAYER * 8192 * DMODEL)
#define E_WD  ((size_t)NLAYER * DMODEL * FFDIM)
#define E_WPL ((size_t)NLAYER * HPL * DMODEL)
#define E_H2  ((size_t)N_TOK * DMODEL)
#define E_QT  ((size_t)N_TOK * NH * HDIM)
#define E_KT  ((size_t)N_TOK * NKV * HDIM)
#define E_P3  ((size_t)NH * N_TOK * N_TOK)
#define E_AO  ((size_t)N_TOK * NH * HDIM)
#define E_M2  ((size_t)N_TOK * FFDIM)
#define E_PL  ((size_t)N_TOK * HPL)

// ======================= scratch layout (bytes) =======================
#define OFF_WQKV  ((size_t)0)
#define OFF_WO3   (OFF_WQKV + 4 * E_QKV)
#define OFF_WGU   (OFF_WO3  + 4 * E_WO)
#define OFF_WD3   (OFF_WGU  + 4 * E_GU)
#define OFF_WPLG3 (OFF_WD3  + 4 * E_WD)
#define OFF_WPLP3 (OFF_WPLG3 + 4 * E_WPL)
// fp32 activations
#define OFF_HS     (OFF_WPLP3 + 4 * E_WPL)
#define OFF_QKVRAW (OFF_HS     + 4ull * N_TOK * DMODEL)
#define OFF_SC     (OFF_QKVRAW + 4ull * N_TOK * 3072)
#define OFF_TMP    (OFF_SC     + 4ull * E_P3)
#define OFF_GU     (OFF_TMP    + 4ull * N_TOK * DMODEL)
#define OFF_PLB    (OFF_GU     + 4ull * N_TOK * 8192)
// fp16 2-plane activations
#define OFF_H2     (OFF_PLB + 4ull * E_PL)
#define OFF_QT3    (OFF_H2  + 4ull * E_H2)
#define OFF_KT3    (OFF_QT3 + 4ull * E_QT)
#define OFF_VT3    (OFF_KT3 + 4ull * E_KT)
#define OFF_P3     (OFF_VT3 + 4ull * E_KT)
#define OFF_AO3    (OFF_P3  + 4ull * E_P3)
#define OFF_M2     (OFF_AO3 + 4ull * E_AO)
#define OFF_HS3    (OFF_M2  + 4ull * E_M2)
#define OFF_PL3    (OFF_HS3 + 4ull * E_H2)
#define TOTAL_SCR  (OFF_PL3 + 4ull * E_PL)

__device__ __align__(1024) char g_scr[TOTAL_SCR];

// ======================= block reductions =======================
__device__ __forceinline__ float blockReduceSum256(float v) {
    __shared__ float sh[8]; __shared__ float res;
    int lane = threadIdx.x & 31, wid = threadIdx.x >> 5;
    #pragma unroll
    for (int o = 16; o > 0; o >>= 1) v += __shfl_xor_sync(0xffffffffu, v, o);
    if (lane == 0) sh[wid] = v;
    __syncthreads();
    if (wid == 0) {
        float x = (lane < 8) ? sh[lane] : 0.f;
        #pragma unroll
        for (int o = 4; o > 0; o >>= 1) x += __shfl_xor_sync(0xffffffffu, x, o);
        if (lane == 0) res = x;
    }
    __syncthreads();
    return res;
}
__device__ __forceinline__ float blockReduceMax256(float v) {
    __shared__ float sh[8]; __shared__ float res;
    int lane = threadIdx.x & 31, wid = threadIdx.x >> 5;
    #pragma unroll
    for (int o = 16; o > 0; o >>= 1) v = fmaxf(v, __shfl_xor_sync(0xffffffffu, v, o));
    if (lane == 0) sh[wid] = v;
    __syncthreads();
    if (wid == 0) {
        float x = (lane < 8) ? sh[lane] : -INFINITY;
        #pragma unroll
        for (int o = 4; o > 0; o >>= 1) x = fmaxf(x, __shfl_xor_sync(0xffffffffu, x, o));
        if (lane == 0) res = x;
    }
    __syncthreads();
    return res;
}
__device__ __forceinline__ float gelu_tanh(float x) {
    float t = tanhf(0.7978845608028654f * (x + 0.044715f * x * x * x));
    return 0.5f * x * (1.f + t);
}
__device__ __forceinline__ void split2h(float v, fp16& h, fp16& l) {
    h = __float2half_rn(v);
    l = __float2half_rn((v - __half2float(h)) * SPLIT_SCALE);
}

// ======================= norm / elementwise kernels =======================
__global__ void add_rms_kernel(float* __restrict__ hs, const float* __restrict__ x,
                               const float* __restrict__ w,
                               const float* __restrict__ scale_ptr,
                               fp16* __restrict__ dst, size_t elts, int cols) {
    int row = blockIdx.x;
    const float* xr = x + (size_t)row * cols;
    float ss = 0.f;
    for (int c = threadIdx.x; c < cols; c += 256) { float v = xr[c]; ss += v * v; }
    ss = blockReduceSum256(ss);
    float inv = rsqrtf(ss / (float)cols + EPSF);
    float sc = scale_ptr ? *scale_ptr : 1.f;
    float* hr = hs + (size_t)row * cols;
    for (int c = threadIdx.x; c < cols; c += 256) {
        float y = (hr[c] + xr[c] * inv * (1.f + w[c])) * sc;
        hr[c] = y;
        if (dst) {
            fp16 h, l; split2h(y, h, l);
            size_t o = (size_t)row * cols + c;
            dst[o] = h; dst[elts + o] = l;
        }
    }
}

__global__ void add_rms_norm_kernel(float* __restrict__ hs, const float* __restrict__ x,
                                    const float* __restrict__ w1,
                                    const float* __restrict__ scale_ptr,
                                    const float* __restrict__ w2,
                                    fp16* __restrict__ dst, size_t elts) {
    const int cols = DMODEL;
    int row = blockIdx.x;
    const float* xr = x + (size_t)row * cols;
    float* hr = hs + (size_t)row * cols;
    float ss = 0.f;
    #pragma unroll
    for (int q = 0; q < 8; q++) { float v = xr[threadIdx.x + q * 256]; ss += v * v; }
    ss = blockReduceSum256(ss);
    float inv = rsqrtf(ss / (float)cols + EPSF);
    float sc = scale_ptr ? *scale_ptr : 1.f;
    float ys[8];
    float ss2 = 0.f;
    #pragma unroll
    for (int q = 0; q < 8; q++) {
        int c = threadIdx.x + q * 256;
        float y = (hr[c] + xr[c] * inv * (1.f + w1[c])) * sc;
        ys[q] = y; hr[c] = y; ss2 += y * y;
    }
    ss2 = blockReduceSum256(ss2);
    float inv2 = rsqrtf(ss2 / (float)cols + EPSF);
    #pragma unroll
    for (int q = 0; q < 8; q++) {
        int c = threadIdx.x + q * 256;
        float z = ys[q] * inv2 * (1.f + w2[c]);
        fp16 h, l; split2h(z, h, l);
        size_t o = (size_t)row * cols + c;
        dst[o] = h; dst[elts + o] = l;
    }
}

__global__ void qkv_norm_kernel(const float* __restrict__ x,
                                const float* __restrict__ qw, const float* __restrict__ kw,
                                const float* __restrict__ cost, const float* __restrict__ sint,
                                float* __restrict__ Kout, float* __restrict__ Vout,
                                fp16* __restrict__ qt, fp16* __restrict__ kt,
                                fp16* __restrict__ vt) {
    int n = blockIdx.x, g = blockIdx.y, d = threadIdx.x;
    __shared__ float sx[HDIM];
    if (g < 10) {
        const int isq = (g < 8);
        const int h = isq ? g : (g - 8);
        const float* w = isq ? qw : kw;
        const int off = isq ? (h * HDIM) : (2048 + h * HDIM);
        float v = x[(size_t)n * 3072 + off + d];
        float ss = blockReduceSum256(v * v);
        float inv = rsqrtf(ss / (float)HDIM + EPSF);
        float xn = v * inv * (1.f + w[d]);
        sx[d] = xn;
        __syncthreads();
        float rh = (d < HDIM / 2) ? -sx[d + HDIM / 2] : sx[d - HDIM / 2];
        float y = xn * cost[(size_t)n * HDIM + d] + rh * sint[(size_t)n * HDIM + d];
        size_t idx = ((size_t)h * N_TOK + n) * HDIM + d;
        fp16 bh, bl; split2h(y, bh, bl);
        if (isq) {
            qt[idx] = bh; qt[E_QT + idx] = bl;
        } else {
            Kout[idx] = y;
            kt[idx] = bh; kt[E_KT + idx] = bl;
        }
    } else {
        const int h = g - 10;
        float v = x[(size_t)n * 3072 + 2560 + h * HDIM + d];
        float ss = blockReduceSum256(v * v);
        float y = v * rsqrtf(ss / (float)HDIM + EPSF);
        Vout[((size_t)h * N_TOK + n) * HDIM + d] = y;
        fp16 bh, bl; split2h(y, bh, bl);
        size_t tidx = ((size_t)h * HDIM + d) * N_TOK + n;
        vt[tidx] = bh; vt[E_KT + tidx] = bl;
    }
}

__global__ void softmax_causal_split_kernel(const float* __restrict__ p,
                                            fp16* __restrict__ dst, size_t elts) {
    const float* row = p + (size_t)blockIdx.x * N_TOK;
    const int r = blockIdx.x & (N_TOK - 1);
    int base = threadIdx.x * 4;
    float4 r4 = *(const float4*)(row + base);
    float v[4] = {r4.x, r4.y, r4.z, r4.w};
    float m = -INFINITY;
    #pragma unroll
    for (int i = 0; i < 4; i++) if (base + i <= r) m = fmaxf(m, v[i]);
    m = blockReduceMax256(m);
    float e[4];
    #pragma unroll
    for (int i = 0; i < 4; i++) e[i] = (base + i <= r) ? expf(v[i] - m) : 0.f;
    float s = blockReduceSum256(e[0] + e[1] + e[2] + e[3]);
    float invs = 1.f / s;
    union { fp16 b[4]; uint2 u2; } H, L;
    #pragma unroll
    for (int i = 0; i < 4; i++) split2h(e[i] * invs, H.b[i], L.b[i]);
    size_t o = (size_t)blockIdx.x * N_TOK + base;
    *(uint2*)(dst + o) = H.u2;
    *(uint2*)(dst + elts + o) = L.u2;
}

// ======================= fp16x2 mma machinery =======================
__device__ __forceinline__ uint32_t smem_u32(const void* p) {
    uint32_t a;
    asm("{ .reg .u64 t; cvta.to.shared.u64 t, %1; cvt.u32.u64 %0, t; }" : "=r"(a) : "l"(p));
    return a;
}
__device__ __forceinline__ void cp16(uint32_t dst, const void* src) {
    asm volatile("cp.async.cg.shared.global [%0], [%1], 16;" :: "r"(dst), "l"(src) : "memory");
}
__device__ __forceinline__ void ldsm4(uint32_t* r, uint32_t addr) {
    asm volatile("ldmatrix.sync.aligned.m8n8.x4.shared.b16 {%0,%1,%2,%3}, [%4];"
                 : "=r"(r[0]), "=r"(r[1]), "=r"(r[2]), "=r"(r[3]) : "r"(addr));
}
__device__ __forceinline__ void mma_f16(float* d, const uint32_t* a, const uint32_t* b) {
    asm volatile(
        "mma.sync.aligned.m16n8k16.row.col.f32.f16.f16.f32 "
        "{%0,%1,%2,%3}, {%4,%5,%6,%7}, {%8,%9}, {%0,%1,%2,%3};"
        : "+f"(d[0]), "+f"(d[1]), "+f"(d[2]), "+f"(d[3])
        : "r"(a[0]), "r"(a[1]), "r"(a[2]), "r"(a[3]), "r"(b[0]), "r"(b[1]));
}

#define TROWB 80
#define TILEA (128 * TROWB)

// C[z] tile (128 rows x 64 cols) = A[z](rows x K) @ B[z>>bshift](M x K)^T
// fp16 2-plane scaled split; dual accumulators; 3-stage cp.async; 2 CTAs/SM.
// kcap4: if >0, limit K-chunks to (blockIdx.y+1)*kcap4 (exact for causal-zero P rows).
template <bool CAUSAL, bool SPLIT>
__global__ void __launch_bounds__(256, 2)
mma_gemm(const fp16* __restrict__ A3, const fp16* __restrict__ B3,
         long long eA, long long eB,
         float* __restrict__ Cf, fp16* __restrict__ C3, long long eC,
         int K, int ldc,
         long long sA, long long sB, long long sC, int bshift, int kcap4) {
    constexpr int NT = 64;
    constexpr int TILEB = NT * TROWB;
    constexpr int STG = 2 * TILEA + 2 * TILEB;
    constexpr int NJ = NT / 32;
    if (CAUSAL && (int)blockIdx.x * NT > (int)blockIdx.y * 128 + 127) return;
    extern __shared__ char smem[];
    const uint32_t sb = smem_u32(smem);
    const int tid = threadIdx.x;
    const int bz = blockIdx.z;
    const int row0 = blockIdx.y * 128;
    const int col0 = blockIdx.x * NT;

    const fp16* srcs[4];
    #pragma unroll
    for (int p = 0; p < 2; p++) {
        srcs[p]     = A3 + (size_t)p * eA + (size_t)bz * sA + (size_t)row0 * K;
        srcs[2 + p] = B3 + (size_t)p * eB + (size_t)(bz >> bshift) * sB + (size_t)col0 * K;
    }

    const int lane = tid & 31, wid = tid >> 5;
    const int wm = wid & 3, wn = wid >> 2;
    const int ld_r = tid >> 2;
    const int ld_c = tid & 3;

    uint32_t aoff[2], boff[NJ];
    #pragma unroll
    for (int m = 0; m < 2; m++)
        aoff[m] = (uint32_t)((wm * 32 + m * 16 + (lane & 15)) * TROWB + ((lane >> 4) << 4));
    #pragma unroll
    for (int j = 0; j < NJ; j++)
        boff[j] = (uint32_t)((wn * (NT / 2) + j * 16 + (lane & 7) + ((lane >> 4) << 3)) * TROWB
                             + (((lane >> 3) & 1) << 4));

    float accM[2][2 * NJ][4], accC[2][2 * NJ][4];
    #pragma unroll
    for (int m = 0; m < 2; m++)
        #pragma unroll
        for (int t = 0; t < 2 * NJ; t++)
            #pragma unroll
            for (int u = 0; u < 4; u++) { accM[m][t][u] = 0.f; accC[m][t][u] = 0.f; }

    int nch = K >> 5;
    if (kcap4) { int cap = ((int)blockIdx.y + 1) * kcap4; if (cap < nch) nch = cap; }

    auto issue = [&](int c, uint32_t dstb) {
        const int kb = c << 5;
        #pragma unroll
        for (int q = 0; q < 4; q++) {
            const int r = (q & 1) * 64 + ld_r;
            const char* gsrc = (const char*)(srcs[q >> 1] + (size_t)r * K + kb) + ld_c * 16;
            cp16(dstb + (uint32_t)((q >> 1) * TILEA + r * TROWB + ld_c * 16), gsrc);
        }
        #pragma unroll
        for (int p = 0; p < 2; p++) {
            const char* gsrc = (const char*)(srcs[2 + p] + (size_t)ld_r * K + kb) + ld_c * 16;
            cp16(dstb + (uint32_t)(2 * TILEA + p * TILEB + ld_r * TROWB + ld_c * 16), gsrc);
        }
        asm volatile("cp.async.commit_group;" ::: "memory");
    };

    issue(0, sb);
    if (nch > 1) issue(1, sb + STG);
    if (nch > 2) issue(2, sb + 2 * STG);

    int stage = 0;
    for (int c = 0; c < nch; ++c) {
        const int rem = nch - 1 - c;
        if (rem >= 2)      asm volatile("cp.async.wait_group 2;" ::: "memory");
        else if (rem == 1) asm volatile("cp.async.wait_group 1;" ::: "memory");
        else               asm volatile("cp.async.wait_group 0;" ::: "memory");
        __syncthreads();

        const uint32_t base = sb + (uint32_t)stage * STG;

        #pragma unroll
        for (int kk = 0; kk < 2; kk++) {
            const uint32_t kb = kk * 32;
            uint32_t ah[2][4], al[2][4];
            #pragma unroll
            for (int m = 0; m < 2; m++) {
                ldsm4(ah[m], base + 0 * TILEA + aoff[m] + kb);
                ldsm4(al[m], base + 1 * TILEA + aoff[m] + kb);
            }
            #pragma unroll
            for (int j = 0; j < NJ; j++) {
                uint32_t bh[4], bl[4];
                ldsm4(bh, base + 2 * TILEA + 0 * TILEB + boff[j] + kb);
                ldsm4(bl, base + 2 * TILEA + 1 * TILEB + boff[j] + kb);
                #pragma unroll
                for (int m = 0; m < 2; m++) {
                    #pragma unroll
                    for (int h = 0; h < 2; h++) {
                        float* dM = accM[m][j * 2 + h];
                        float* dC = accC[m][j * 2 + h];
                        mma_f16(dM, ah[m], &bh[h * 2]);   // hh -> main
                        mma_f16(dC, ah[m], &bl[h * 2]);   // corrections (x2048)
                        mma_f16(dC, al[m], &bh[h * 2]);
                    }
                }
            }
        }
        __syncthreads();
        if (c + 3 < nch) issue(c + 3, base);
        stage = (stage == 2) ? 0 : stage + 1;
    }

    const int grp = lane >> 2, qd = lane & 3;
    #pragma unroll
    for (int m = 0; m < 2; m++) {
        #pragma unroll
        for (int t = 0; t < 2 * NJ; t++) {
            const int col = col0 + wn * (NT / 2) + t * 8 + qd * 2;
            #pragma unroll
            for (int half = 0; half < 2; half++) {
                const int row = row0 + wm * 32 + m * 16 + grp + half * 8;
                float v0 = accM[m][t][half * 2 + 0] + accC[m][t][half * 2 + 0] * SPLIT_INV;
                float v1 = accM[m][t][half * 2 + 1] + accC[m][t][half * 2 + 1] * SPLIT_INV;
                const size_t o = (size_t)bz * sC + (size_t)row * ldc + col;
                if (SPLIT) {
                    union { fp16 b[2]; uint32_t u; } H, L;
                    split2h(v0, H.b[0], L.b[0]); split2h(v1, H.b[1], L.b[1]);
                    *(uint32_t*)(C3 + o) = H.u;
                    *(uint32_t*)(C3 + (size_t)eC + o) = L.u;
                } else {
                    float2 o2; o2.x = v0; o2.y = v1;
                    *(float2*)(Cf + o) = o2;
                }
            }
        }
    }
}

#define GSMEM64 (3 * (2 * TILEA + 2 * 64 * TROWB))   // 92160

// ======================= split producers =======================
__global__ void wsplit_kernel(const float* __restrict__ x, fp16* __restrict__ dst,
                              size_t plane, size_t n4) {
    size_t i = (size_t)blockIdx.x * 256 + threadIdx.x;
    if (i >= n4) return;
    float4 v = ((const float4*)x)[i];
    union { fp16 b[4]; uint2 u2; } H, L;
    split2h(v.x, H.b[0], L.b[0]); split2h(v.y, H.b[1], L.b[1]);
    split2h(v.z, H.b[2], L.b[2]); split2h(v.w, H.b[3], L.b[3]);
    ((uint2*)dst)[i] = H.u2;
    ((uint2*)(dst + plane))[i] = L.u2;
}

__global__ void rmsnorm_split_kernel(const float* __restrict__ x, const float* __restrict__ w,
                                     fp16* __restrict__ dst, size_t elts, int cols) {
    int row = blockIdx.x;
    const float* xr = x + (size_t)row * cols;
    float ss = 0.f;
    for (int c = threadIdx.x; c < cols; c += 256) { float v = xr[c]; ss += v * v; }
    ss = blockReduceSum256(ss);
    float inv = rsqrtf(ss / (float)cols + EPSF);
    for (int c = threadIdx.x; c < cols; c += 256) {
        float y = xr[c] * inv * (1.f + w[c]);
        fp16 h, l; split2h(y, h, l);
        size_t o = (size_t)row * cols + c;
        dst[o] = h; dst[elts + o] = l;
    }
}

__global__ void gelu_mul_split_kernel(const float* __restrict__ gu,
                                      fp16* __restrict__ dst, size_t elts, int n) {
    int i = blockIdx.x * 256 + threadIdx.x;
    if (i < n) {
        int row = i >> 12, j = i & 4095;
        float g = gu[(size_t)row * 8192 + j];
        float u = gu[(size_t)row * 8192 + 4096 + j];
        float y = gelu_tanh(g) * u;
        fp16 h, l; split2h(y, h, l);
        dst[i] = h; dst[elts + i] = l;
    }
}

__global__ void gelu_sl_split_kernel(const float* __restrict__ g, const float* __restrict__ plc,
                                     int li, fp16* __restrict__ dst, size_t elts) {
    int i = blockIdx.x * 256 + threadIdx.x;
    if (i < N_TOK * HPL) {
        int n = i >> 8, j = i & 255;
        float y = gelu_tanh(g[i]) * plc[(size_t)n * (TOTAL_LAYERS * HPL) + (size_t)li * HPL + j];
        fp16 h, l; split2h(y, h, l);
        dst[i] = h; dst[elts + i] = l;
    }
}

// ======================= driver =======================
extern "C" void kernel_launch(void* const* d_in, const int* in_sizes, int n_in,
                              void* d_out, int out_size) {
    const float* hidden = (const float*)d_in[0];
    const float* plc    = (const float*)d_in[1];
    const float* cos_s  = (const float*)d_in[3];
    const float* sin_s  = (const float*)d_in[4];
    const float* cos_f  = (const float*)d_in[5];
    const float* sin_f  = (const float*)d_in[6];
    const float* Wq     = (const float*)d_in[7];
    const float* Wk     = (const float*)d_in[8];
    const float* Wv     = (const float*)d_in[9];
    const float* Wo     = (const float*)d_in[10];
    const float* Wg     = (const float*)d_in[11];
    const float* Wu     = (const float*)d_in[12];
    const float* Wd     = (const float*)d_in[13];
    const float* Wplg   = (const float*)d_in[14];
    const float* Wplp   = (const float*)d_in[15];
    const float* ln_in  = (const float*)d_in[16];
    const float* ln_pa  = (const float*)d_in[17];
    const float* ln_pf  = (const float*)d_in[18];
    const float* ln_ff  = (const float*)d_in[19];
    const float* ln_pl  = (const float*)d_in[20];
    const float* qn_w   = (const float*)d_in[21];
    const float* kn_w   = (const float*)d_in[22];
    const float* lscale = (const float*)d_in[23];

    cudaFuncSetAttribute(mma_gemm<true,  false>, cudaFuncAttributeMaxDynamicSharedMemorySize, GSMEM64);
    cudaFuncSetAttribute(mma_gemm<false, true>,  cudaFuncAttributeMaxDynamicSharedMemorySize, GSMEM64);
    cudaFuncSetAttribute(mma_gemm<false, false>, cudaFuncAttributeMaxDynamicSharedMemorySize, GSMEM64);

    char* scr = nullptr;
    cudaGetSymbolAddress((void**)&scr, g_scr);

    fp16* wqkv3 = (fp16*)(scr + OFF_WQKV);
    fp16* wo3   = (fp16*)(scr + OFF_WO3);
    fp16* wgu3  = (fp16*)(scr + OFF_WGU);
    fp16* wd3   = (fp16*)(scr + OFF_WD3);
    fp16* wplg3 = (fp16*)(scr + OFF_WPLG3);
    fp16* wplp3 = (fp16*)(scr + OFF_WPLP3);

    float* hs     = (float*)(scr + OFF_HS);
    float* qkvraw = (float*)(scr + OFF_QKVRAW);
    float* scores = (float*)(scr + OFF_SC);
    float* tmp    = (float*)(scr + OFF_TMP);
    float* gu     = (float*)(scr + OFF_GU);
    float* plbuf  = (float*)(scr + OFF_PLB);
    fp16*  h2     = (fp16*)(scr + OFF_H2);
    fp16*  qt3    = (fp16*)(scr + OFF_QT3);
    fp16*  kt3    = (fp16*)(scr + OFF_KT3);
    fp16*  vt3    = (fp16*)(scr + OFF_VT3);
    fp16*  p3     = (fp16*)(scr + OFF_P3);
    fp16*  ao3    = (fp16*)(scr + OFF_AO3);
    fp16*  m2     = (fp16*)(scr + OFF_M2);
    fp16*  hs3    = (fp16*)(scr + OFF_HS3);
    fp16*  pl3    = (fp16*)(scr + OFF_PL3);

    float* out = (float*)d_out;

    // ---- split weights into fused 2-plane layouts ----
    auto wsplit = [&](const float* src, fp16* dst, size_t plane, size_t count) {
        size_t n4 = count / 4;
        wsplit_kernel<<<(unsigned)((n4 + 255) / 256), 256>>>(src, dst, plane, n4);
    };
    for (int i = 0; i < NLAYER; i++) {
        const size_t lq = (size_t)i * 2048 * 2048;
        const size_t lk = (size_t)i * 512 * 2048;
        fp16* dst = wqkv3 + (size_t)i * 3072 * 2048;
        wsplit(Wq + lq, dst,               E_QKV, (size_t)2048 * 2048);
        wsplit(Wk + lk, dst + 2048 * 2048, E_QKV, (size_t)512 * 2048);
        wsplit(Wv + lk, dst + 2560 * 2048, E_QKV, (size_t)512 * 2048);

        const size_t lg = (size_t)i * 4096 * 2048;
        fp16* dgu = wgu3 + (size_t)i * 8192 * 2048;
        wsplit(Wg + lg, dgu,               E_GU, (size_t)4096 * 2048);
        wsplit(Wu + lg, dgu + 4096 * 2048, E_GU, (size_t)4096 * 2048);
    }
    wsplit(Wo,   wo3,   E_WO,  E_WO);
    wsplit(Wd,   wd3,   E_WD,  E_WD);
    wsplit(Wplg, wplg3, E_WPL, E_WPL);
    wsplit(Wplp, wplp3, E_WPL, E_WPL);

    cudaMemcpyAsync(hs, hidden, (size_t)N_TOK * DMODEL * sizeof(float), cudaMemcpyDeviceToDevice, 0);

    // initial pre-attention norm (layer 0)
    rmsnorm_split_kernel<<<N_TOK, 256>>>(hs, ln_in, h2, E_H2, DMODEL);

    for (int i = 0; i < NLAYER; i++) {
        const int li = STARTL + i;
        const bool full = ((li + 1) % 5) == 0;
        const float* cost = full ? cos_f : cos_s;
        const float* sint = full ? sin_f : sin_s;
        float* Kout = out + (size_t)N_TOK * DMODEL + (size_t)i * 2 * NKV * N_TOK * HDIM;
        float* Vout = Kout + (size_t)NKV * N_TOK * HDIM;

        // ---- fused QKV + fused norms ----
        mma_gemm<false, false><<<dim3(3072 / 64, 8), 256, GSMEM64>>>(
            h2, wqkv3 + (size_t)i * 3072 * 2048, (long long)E_H2, (long long)E_QKV,
            qkvraw, nullptr, 0, DMODEL, 3072, 0, 0, 0, 0, 0);
        qkv_norm_kernel<<<dim3(N_TOK, 12), 256>>>(
            qkvraw, qn_w + (size_t)i * HDIM, kn_w + (size_t)i * HDIM, cost, sint,
            Kout, Vout, qt3, kt3, vt3);

        // ---- attention: causal scores, softmax, PV (split epilogue + k-cap) ----
        mma_gemm<true, false><<<dim3(N_TOK / 64, N_TOK / 128, NH), 256, GSMEM64>>>(
            qt3, kt3, (long long)E_QT, (long long)E_KT, scores, nullptr, 0, HDIM, N_TOK,
            (long long)N_TOK * HDIM, (long long)N_TOK * HDIM, (long long)N_TOK * N_TOK, 2, 0);
        softmax_causal_split_kernel<<<NH * N_TOK, 256>>>(scores, p3, E_P3);
        mma_gemm<false, true><<<dim3(HDIM / 64, N_TOK / 128, NH), 256, GSMEM64>>>(
            p3, vt3, (long long)E_P3, (long long)E_KT, nullptr, ao3, (long long)E_AO,
            N_TOK, NH * HDIM,
            (long long)N_TOK * N_TOK, (long long)HDIM * N_TOK, (long long)HDIM, 2, 4);

        // ---- Wo + fused residual + pre-FFN norm ----
        mma_gemm<false, false><<<dim3(DMODEL / 64, 8), 256, GSMEM64>>>(
            ao3, wo3 + (size_t)i * 2048 * 2048, (long long)E_AO, (long long)E_WO,
            tmp, nullptr, 0, NH * HDIM, DMODEL, 0, 0, 0, 0, 0);
        add_rms_norm_kernel<<<N_TOK, 256>>>(hs, tmp, ln_pa + (size_t)i * DMODEL, nullptr,
                                            ln_pf + (size_t)i * DMODEL, h2, E_H2);

        // ---- FFN: fused G+U, gelu*u, Wd + residual ----
        mma_gemm<false, false><<<dim3(8192 / 64, 8), 256, GSMEM64>>>(
            h2, wgu3 + (size_t)i * 8192 * 2048, (long long)E_H2, (long long)E_GU,
            gu, nullptr, 0, DMODEL, 8192, 0, 0, 0, 0, 0);
        gelu_mul_split_kernel<<<(N_TOK * FFDIM + 255) / 256, 256>>>(gu, m2, E_M2, N_TOK * FFDIM);
        mma_gemm<false, false><<<dim3(DMODEL / 64, 8), 256, GSMEM64>>>(
            m2, wd3 + (size_t)i * 2048 * 4096, (long long)E_M2, (long long)E_WD,
            tmp, nullptr, 0, FFDIM, DMODEL, 0, 0, 0, 0, 0);
        add_rms_kernel<<<N_TOK, 256>>>(hs, tmp, ln_ff + (size_t)i * DMODEL, nullptr,
                                       hs3, E_H2, DMODEL);

        // ---- per-layer gating + fused residual + next norm ----
        mma_gemm<false, false><<<dim3(HPL / 64, 8), 256, GSMEM64>>>(
            hs3, wplg3 + (size_t)i * HPL * 2048, (long long)E_H2, (long long)E_WPL,
            plbuf, nullptr, 0, DMODEL, HPL, 0, 0, 0, 0, 0);
        gelu_sl_split_kernel<<<(N_TOK * HPL + 255) / 256, 256>>>(plbuf, plc, li, pl3, E_PL);
        mma_gemm<false, false><<<dim3(DMODEL / 64, 8), 256, GSMEM64>>>(
            pl3, wplp3 + (size_t)i * 2048 * HPL, (long long)E_PL, (long long)E_WPL,
            tmp, nullptr, 0, HPL, DMODEL, 0, 0, 0, 0, 0);
        if (i + 1 < NLAYER) {
            add_rms_norm_kernel<<<N_TOK, 256>>>(hs, tmp, ln_pl + (size_t)i * DMODEL, lscale + i,
                                                ln_in + (size_t)(i + 1) * DMODEL, h2, E_H2);
        } else {
            add_rms_kernel<<<N_TOK, 256>>>(hs, tmp, ln_pl + (size_t)i * DMODEL, lscale + i,
                                           nullptr, 0, DMODEL);
        }
    }

    cudaMemcpyAsync(out, hs, (size_t)N_TOK * DMODEL * sizeof(float), cudaMemcpyDeviceToDevice, 0);
}

// round 17
// speedup vs baseline: 3.7558x; 1.0042x over previous
#include <cuda_runtime.h>
#include <cuda_fp16.h>
#include <math.h>
#include <stdint.h>

#define N_TOK 1024
#define DMODEL 2048
#define NH 8
#define NKV 2
#define HDIM 256
#define FFDIM 4096
#define HPL 256
#define NLAYER 7
#define STARTL 8
#define TOTAL_LAYERS 30
#define EPSF 1e-6f
#define SPLIT_SCALE 2048.f
#define SPLIT_INV   (1.f / 2048.f)

typedef __half fp16;

// ======================= plane sizes (elements) =======================
#define E_QKV ((size_t)NLAYER * 3072 * DMODEL)
#define E_WO  ((size_t)NLAYER * DMODEL * (NH * HDIM))
#define E_GU  ((size_t)NLAYER * 8192 * DMODEL)
#define E_WD  ((size_t)NLAYER * DMODEL * FFDIM)
#define E_WPL ((size_t)NLAYER * HPL * DMODEL)
#define E_H2  ((size_t)N_TOK * DMODEL)
#define E_QT  ((size_t)N_TOK * NH * HDIM)
#define E_KT  ((size_t)N_TOK * NKV * HDIM)
#define E_P3  ((size_t)NH * N_TOK * N_TOK)
#define E_AO  ((size_t)N_TOK * NH * HDIM)
#define E_M2  ((size_t)N_TOK * FFDIM)
#define E_PL  ((size_t)N_TOK * HPL)

// ======================= scratch layout (bytes) =======================
#define OFF_WQKV  ((size_t)0)
#define OFF_WO3   (OFF_WQKV + 4 * E_QKV)
#define OFF_WGU   (OFF_WO3  + 4 * E_WO)
#define OFF_WD3   (OFF_WGU  + 4 * E_GU)
#define OFF_WPLG3 (OFF_WD3  + 4 * E_WD)
#define OFF_WPLP3 (OFF_WPLG3 + 4 * E_WPL)
// fp32 activations
#define OFF_HS     (OFF_WPLP3 + 4 * E_WPL)
#define OFF_QKVRAW (OFF_HS     + 4ull * N_TOK * DMODEL)
#define OFF_SC     (OFF_QKVRAW + 4ull * N_TOK * 3072)
#define OFF_TMP    (OFF_SC     + 4ull * E_P3)
#define OFF_PLB    (OFF_TMP    + 4ull * N_TOK * DMODEL)
// fp16 2-plane activations
#define OFF_H2     (OFF_PLB + 4ull * E_PL)
#define OFF_QT3    (OFF_H2  + 4ull * E_H2)
#define OFF_KT3    (OFF_QT3 + 4ull * E_QT)
#define OFF_VT3    (OFF_KT3 + 4ull * E_KT)
#define OFF_P3     (OFF_VT3 + 4ull * E_KT)
#define OFF_AO3    (OFF_P3  + 4ull * E_P3)
#define OFF_M2     (OFF_AO3 + 4ull * E_AO)
#define OFF_HS3    (OFF_M2  + 4ull * E_M2)
#define OFF_PL3    (OFF_HS3 + 4ull * E_H2)
#define TOTAL_SCR  (OFF_PL3 + 4ull * E_PL)

__device__ __align__(1024) char g_scr[TOTAL_SCR];

// ======================= block reductions =======================
__device__ __forceinline__ float blockReduceSum256(float v) {
    __shared__ float sh[8]; __shared__ float res;
    int lane = threadIdx.x & 31, wid = threadIdx.x >> 5;
    #pragma unroll
    for (int o = 16; o > 0; o >>= 1) v += __shfl_xor_sync(0xffffffffu, v, o);
    if (lane == 0) sh[wid] = v;
    __syncthreads();
    if (wid == 0) {
        float x = (lane < 8) ? sh[lane] : 0.f;
        #pragma unroll
        for (int o = 4; o > 0; o >>= 1) x += __shfl_xor_sync(0xffffffffu, x, o);
        if (lane == 0) res = x;
    }
    __syncthreads();
    return res;
}
__device__ __forceinline__ float blockReduceMax256(float v) {
    __shared__ float sh[8]; __shared__ float res;
    int lane = threadIdx.x & 31, wid = threadIdx.x >> 5;
    #pragma unroll
    for (int o = 16; o > 0; o >>= 1) v = fmaxf(v, __shfl_xor_sync(0xffffffffu, v, o));
    if (lane == 0) sh[wid] = v;
    __syncthreads();
    if (wid == 0) {
        float x = (lane < 8) ? sh[lane] : -INFINITY;
        #pragma unroll
        for (int o = 4; o > 0; o >>= 1) x = fmaxf(x, __shfl_xor_sync(0xffffffffu, x, o));
        if (lane == 0) res = x;
    }
    __syncthreads();
    return res;
}
__device__ __forceinline__ float gelu_tanh(float x) {
    float t = tanhf(0.7978845608028654f * (x + 0.044715f * x * x * x));
    return 0.5f * x * (1.f + t);
}
__device__ __forceinline__ void split2h(float v, fp16& h, fp16& l) {
    h = __float2half_rn(v);
    l = __float2half_rn((v - __half2float(h)) * SPLIT_SCALE);
}

// ======================= norm / elementwise kernels =======================
__global__ void add_rms_kernel(float* __restrict__ hs, const float* __restrict__ x,
                               const float* __restrict__ w,
                               const float* __restrict__ scale_ptr,
                               fp16* __restrict__ dst, size_t elts, int cols) {
    int row = blockIdx.x;
    const float* xr = x + (size_t)row * cols;
    float ss = 0.f;
    for (int c = threadIdx.x; c < cols; c += 256) { float v = xr[c]; ss += v * v; }
    ss = blockReduceSum256(ss);
    float inv = rsqrtf(ss / (float)cols + EPSF);
    float sc = scale_ptr ? *scale_ptr : 1.f;
    float* hr = hs + (size_t)row * cols;
    for (int c = threadIdx.x; c < cols; c += 256) {
        float y = (hr[c] + xr[c] * inv * (1.f + w[c])) * sc;
        hr[c] = y;
        if (dst) {
            fp16 h, l; split2h(y, h, l);
            size_t o = (size_t)row * cols + c;
            dst[o] = h; dst[elts + o] = l;
        }
    }
}

__global__ void add_rms_norm_kernel(float* __restrict__ hs, const float* __restrict__ x,
                                    const float* __restrict__ w1,
                                    const float* __restrict__ scale_ptr,
                                    const float* __restrict__ w2,
                                    fp16* __restrict__ dst, size_t elts) {
    const int cols = DMODEL;
    int row = blockIdx.x;
    const float* xr = x + (size_t)row * cols;
    float* hr = hs + (size_t)row * cols;
    float ss = 0.f;
    #pragma unroll
    for (int q = 0; q < 8; q++) { float v = xr[threadIdx.x + q * 256]; ss += v * v; }
    ss = blockReduceSum256(ss);
    float inv = rsqrtf(ss / (float)cols + EPSF);
    float sc = scale_ptr ? *scale_ptr : 1.f;
    float ys[8];
    float ss2 = 0.f;
    #pragma unroll
    for (int q = 0; q < 8; q++) {
        int c = threadIdx.x + q * 256;
        float y = (hr[c] + xr[c] * inv * (1.f + w1[c])) * sc;
        ys[q] = y; hr[c] = y; ss2 += y * y;
    }
    ss2 = blockReduceSum256(ss2);
    float inv2 = rsqrtf(ss2 / (float)cols + EPSF);
    #pragma unroll
    for (int q = 0; q < 8; q++) {
        int c = threadIdx.x + q * 256;
        float z = ys[q] * inv2 * (1.f + w2[c]);
        fp16 h, l; split2h(z, h, l);
        size_t o = (size_t)row * cols + c;
        dst[o] = h; dst[elts + o] = l;
    }
}

__global__ void qkv_norm_kernel(const float* __restrict__ x,
                                const float* __restrict__ qw, const float* __restrict__ kw,
                                const float* __restrict__ cost, const float* __restrict__ sint,
                                float* __restrict__ Kout, float* __restrict__ Vout,
                                fp16* __restrict__ qt, fp16* __restrict__ kt,
                                fp16* __restrict__ vt) {
    int n = blockIdx.x, g = blockIdx.y, d = threadIdx.x;
    __shared__ float sx[HDIM];
    if (g < 10) {
        const int isq = (g < 8);
        const int h = isq ? g : (g - 8);
        const float* w = isq ? qw : kw;
        const int off = isq ? (h * HDIM) : (2048 + h * HDIM);
        float v = x[(size_t)n * 3072 + off + d];
        float ss = blockReduceSum256(v * v);
        float inv = rsqrtf(ss / (float)HDIM + EPSF);
        float xn = v * inv * (1.f + w[d]);
        sx[d] = xn;
        __syncthreads();
        float rh = (d < HDIM / 2) ? -sx[d + HDIM / 2] : sx[d - HDIM / 2];
        float y = xn * cost[(size_t)n * HDIM + d] + rh * sint[(size_t)n * HDIM + d];
        size_t idx = ((size_t)h * N_TOK + n) * HDIM + d;
        fp16 bh, bl; split2h(y, bh, bl);
        if (isq) {
            qt[idx] = bh; qt[E_QT + idx] = bl;
        } else {
            Kout[idx] = y;
            kt[idx] = bh; kt[E_KT + idx] = bl;
        }
    } else {
        const int h = g - 10;
        float v = x[(size_t)n * 3072 + 2560 + h * HDIM + d];
        float ss = blockReduceSum256(v * v);
        float y = v * rsqrtf(ss / (float)HDIM + EPSF);
        Vout[((size_t)h * N_TOK + n) * HDIM + d] = y;
        fp16 bh, bl; split2h(y, bh, bl);
        size_t tidx = ((size_t)h * HDIM + d) * N_TOK + n;
        vt[tidx] = bh; vt[E_KT + tidx] = bl;
    }
}

__global__ void softmax_causal_split_kernel(const float* __restrict__ p,
                                            fp16* __restrict__ dst, size_t elts) {
    const float* row = p + (size_t)blockIdx.x * N_TOK;
    const int r = blockIdx.x & (N_TOK - 1);
    int base = threadIdx.x * 4;
    float4 r4 = *(const float4*)(row + base);
    float v[4] = {r4.x, r4.y, r4.z, r4.w};
    float m = -INFINITY;
    #pragma unroll
    for (int i = 0; i < 4; i++) if (base + i <= r) m = fmaxf(m, v[i]);
    m = blockReduceMax256(m);
    float e[4];
    #pragma unroll
    for (int i = 0; i < 4; i++) e[i] = (base + i <= r) ? expf(v[i] - m) : 0.f;
    float s = blockReduceSum256(e[0] + e[1] + e[2] + e[3]);
    float invs = 1.f / s;
    union { fp16 b[4]; uint2 u2; } H, L;
    #pragma unroll
    for (int i = 0; i < 4; i++) split2h(e[i] * invs, H.b[i], L.b[i]);
    size_t o = (size_t)blockIdx.x * N_TOK + base;
    *(uint2*)(dst + o) = H.u2;
    *(uint2*)(dst + elts + o) = L.u2;
}

// ======================= fp16x2 mma machinery =======================
__device__ __forceinline__ uint32_t smem_u32(const void* p) {
    uint32_t a;
    asm("{ .reg .u64 t; cvta.to.shared.u64 t, %1; cvt.u32.u64 %0, t; }" : "=r"(a) : "l"(p));
    return a;
}
__device__ __forceinline__ void cp16(uint32_t dst, const void* src) {
    asm volatile("cp.async.cg.shared.global [%0], [%1], 16;" :: "r"(dst), "l"(src) : "memory");
}
__device__ __forceinline__ void ldsm4(uint32_t* r, uint32_t addr) {
    asm volatile("ldmatrix.sync.aligned.m8n8.x4.shared.b16 {%0,%1,%2,%3}, [%4];"
                 : "=r"(r[0]), "=r"(r[1]), "=r"(r[2]), "=r"(r[3]) : "r"(addr));
}
__device__ __forceinline__ void mma_f16(float* d, const uint32_t* a, const uint32_t* b) {
    asm volatile(
        "mma.sync.aligned.m16n8k16.row.col.f32.f16.f16.f32 "
        "{%0,%1,%2,%3}, {%4,%5,%6,%7}, {%8,%9}, {%0,%1,%2,%3};"
        : "+f"(d[0]), "+f"(d[1]), "+f"(d[2]), "+f"(d[3])
        : "r"(a[0]), "r"(a[1]), "r"(a[2]), "r"(a[3]), "r"(b[0]), "r"(b[1]));
}

#define TROWB 80
#define TILEA (128 * TROWB)

// Epilogue modes
#define EPI_F32   0
#define EPI_SPLIT 1
#define EPI_GELU  2   // interleaved (g,u) columns: write split(gelu(g)*u) at col/2

// C[z] tile (128 rows x 64 cols) = A[z](rows x K) @ B[z>>bshift](M x K)^T
// fp16 2-plane scaled split; dual accumulators; 3-stage cp.async; 2 CTAs/SM.
// kcap4: if >0, limit K-chunks to (blockIdx.y+1)*kcap4 (exact for causal-zero P rows).
template <bool CAUSAL, int EPI>
__global__ void __launch_bounds__(256, 2)
mma_gemm(const fp16* __restrict__ A3, const fp16* __restrict__ B3,
         long long eA, long long eB,
         float* __restrict__ Cf, fp16* __restrict__ C3, long long eC,
         int K, int ldc,
         long long sA, long long sB, long long sC, int bshift, int kcap4) {
    constexpr int NT = 64;
    constexpr int TILEB = NT * TROWB;
    constexpr int STG = 2 * TILEA + 2 * TILEB;
    constexpr int NJ = NT / 32;
    if (CAUSAL && (int)blockIdx.x * NT > (int)blockIdx.y * 128 + 127) return;
    extern __shared__ char smem[];
    const uint32_t sb = smem_u32(smem);
    const int tid = threadIdx.x;
    const int bz = blockIdx.z;
    const int row0 = blockIdx.y * 128;
    const int col0 = blockIdx.x * NT;

    const fp16* srcs[4];
    #pragma unroll
    for (int p = 0; p < 2; p++) {
        srcs[p]     = A3 + (size_t)p * eA + (size_t)bz * sA + (size_t)row0 * K;
        srcs[2 + p] = B3 + (size_t)p * eB + (size_t)(bz >> bshift) * sB + (size_t)col0 * K;
    }

    const int lane = tid & 31, wid = tid >> 5;
    const int wm = wid & 3, wn = wid >> 2;
    const int ld_r = tid >> 2;
    const int ld_c = tid & 3;

    uint32_t aoff[2], boff[NJ];
    #pragma unroll
    for (int m = 0; m < 2; m++)
        aoff[m] = (uint32_t)((wm * 32 + m * 16 + (lane & 15)) * TROWB + ((lane >> 4) << 4));
    #pragma unroll
    for (int j = 0; j < NJ; j++)
        boff[j] = (uint32_t)((wn * (NT / 2) + j * 16 + (lane & 7) + ((lane >> 4) << 3)) * TROWB
                             + (((lane >> 3) & 1) << 4));

    float accM[2][2 * NJ][4], accC[2][2 * NJ][4];
    #pragma unroll
    for (int m = 0; m < 2; m++)
        #pragma unroll
        for (int t = 0; t < 2 * NJ; t++)
            #pragma unroll
            for (int u = 0; u < 4; u++) { accM[m][t][u] = 0.f; accC[m][t][u] = 0.f; }

    int nch = K >> 5;
    if (kcap4) { int cap = ((int)blockIdx.y + 1) * kcap4; if (cap < nch) nch = cap; }

    auto issue = [&](int c, uint32_t dstb) {
        const int kb = c << 5;
        #pragma unroll
        for (int q = 0; q < 4; q++) {
            const int r = (q & 1) * 64 + ld_r;
            const char* gsrc = (const char*)(srcs[q >> 1] + (size_t)r * K + kb) + ld_c * 16;
            cp16(dstb + (uint32_t)((q >> 1) * TILEA + r * TROWB + ld_c * 16), gsrc);
        }
        #pragma unroll
        for (int p = 0; p < 2; p++) {
            const char* gsrc = (const char*)(srcs[2 + p] + (size_t)ld_r * K + kb) + ld_c * 16;
            cp16(dstb + (uint32_t)(2 * TILEA + p * TILEB + ld_r * TROWB + ld_c * 16), gsrc);
        }
        asm volatile("cp.async.commit_group;" ::: "memory");
    };

    issue(0, sb);
    if (nch > 1) issue(1, sb + STG);
    if (nch > 2) issue(2, sb + 2 * STG);

    int stage = 0;
    for (int c = 0; c < nch; ++c) {
        const int rem = nch - 1 - c;
        if (rem >= 2)      asm volatile("cp.async.wait_group 2;" ::: "memory");
        else if (rem == 1) asm volatile("cp.async.wait_group 1;" ::: "memory");
        else               asm volatile("cp.async.wait_group 0;" ::: "memory");
        __syncthreads();

        const uint32_t base = sb + (uint32_t)stage * STG;

        #pragma unroll
        for (int kk = 0; kk < 2; kk++) {
            const uint32_t kb = kk * 32;
            uint32_t ah[2][4], al[2][4];
            #pragma unroll
            for (int m = 0; m < 2; m++) {
                ldsm4(ah[m], base + 0 * TILEA + aoff[m] + kb);
                ldsm4(al[m], base + 1 * TILEA + aoff[m] + kb);
            }
            #pragma unroll
            for (int j = 0; j < NJ; j++) {
                uint32_t bh[4], bl[4];
                ldsm4(bh, base + 2 * TILEA + 0 * TILEB + boff[j] + kb);
                ldsm4(bl, base + 2 * TILEA + 1 * TILEB + boff[j] + kb);
                #pragma unroll
                for (int m = 0; m < 2; m++) {
                    #pragma unroll
                    for (int h = 0; h < 2; h++) {
                        float* dM = accM[m][j * 2 + h];
                        float* dC = accC[m][j * 2 + h];
                        mma_f16(dM, ah[m], &bh[h * 2]);   // hh -> main
                        mma_f16(dC, ah[m], &bl[h * 2]);   // corrections (x2048)
                        mma_f16(dC, al[m], &bh[h * 2]);
                    }
                }
            }
        }
        __syncthreads();
        if (c + 3 < nch) issue(c + 3, base);
        stage = (stage == 2) ? 0 : stage + 1;
    }

    const int grp = lane >> 2, qd = lane & 3;
    #pragma unroll
    for (int m = 0; m < 2; m++) {
        #pragma unroll
        for (int t = 0; t < 2 * NJ; t++) {
            const int col = col0 + wn * (NT / 2) + t * 8 + qd * 2;
            #pragma unroll
            for (int half = 0; half < 2; half++) {
                const int row = row0 + wm * 32 + m * 16 + grp + half * 8;
                float v0 = accM[m][t][half * 2 + 0] + accC[m][t][half * 2 + 0] * SPLIT_INV;
                float v1 = accM[m][t][half * 2 + 1] + accC[m][t][half * 2 + 1] * SPLIT_INV;
                if (EPI == EPI_GELU) {
                    // interleaved weights: v0 = g_j, v1 = u_j, j = col/2
                    float y = gelu_tanh(v0) * v1;
                    fp16 h, l; split2h(y, h, l);
                    const size_t o = (size_t)row * ldc + (col >> 1);
                    C3[o] = h;
                    C3[(size_t)eC + o] = l;
                } else {
                    const size_t o = (size_t)bz * sC + (size_t)row * ldc + col;
                    if (EPI == EPI_SPLIT) {
                        union { fp16 b[2]; uint32_t u; } H, L;
                        split2h(v0, H.b[0], L.b[0]); split2h(v1, H.b[1], L.b[1]);
                        *(uint32_t*)(C3 + o) = H.u;
                        *(uint32_t*)(C3 + (size_t)eC + o) = L.u;
                    } else {
                        float2 o2; o2.x = v0; o2.y = v1;
                        *(float2*)(Cf + o) = o2;
                    }
                }
            }
        }
    }
}

#define GSMEM64 (3 * (2 * TILEA + 2 * 64 * TROWB))   // 92160

// ======================= split producers =======================
__global__ void wsplit_kernel(const float* __restrict__ x, fp16* __restrict__ dst,
                              size_t plane, size_t n4) {
    size_t i = (size_t)blockIdx.x * 256 + threadIdx.x;
    if (i >= n4) return;
    float4 v = ((const float4*)x)[i];
    union { fp16 b[4]; uint2 u2; } H, L;
    split2h(v.x, H.b[0], L.b[0]); split2h(v.y, H.b[1], L.b[1]);
    split2h(v.z, H.b[2], L.b[2]); split2h(v.w, H.b[3], L.b[3]);
    ((uint2*)dst)[i] = H.u2;
    ((uint2*)(dst + plane))[i] = L.u2;
}

// row-interleaving split: src row r (2048 floats) -> dst row 2r+phase
__global__ void wsplit_rows_kernel(const float* __restrict__ x, fp16* __restrict__ dst,
                                   size_t plane, int phase, size_t n4) {
    size_t i = (size_t)blockIdx.x * 256 + threadIdx.x;
    if (i >= n4) return;
    size_t srow = i >> 9;           // 2048 cols = 512 float4 per row
    size_t c4 = i & 511;
    float4 v = ((const float4*)x)[i];
    union { fp16 b[4]; uint2 u2; } H, L;
    split2h(v.x, H.b[0], L.b[0]); split2h(v.y, H.b[1], L.b[1]);
    split2h(v.z, H.b[2], L.b[2]); split2h(v.w, H.b[3], L.b[3]);
    size_t di = ((srow * 2 + (size_t)phase) << 9) + c4;
    ((uint2*)dst)[di] = H.u2;
    ((uint2*)(dst + plane))[di] = L.u2;
}

__global__ void rmsnorm_split_kernel(const float* __restrict__ x, const float* __restrict__ w,
                                     fp16* __restrict__ dst, size_t elts, int cols) {
    int row = blockIdx.x;
    const float* xr = x + (size_t)row * cols;
    float ss = 0.f;
    for (int c = threadIdx.x; c < cols; c += 256) { float v = xr[c]; ss += v * v; }
    ss = blockReduceSum256(ss);
    float inv = rsqrtf(ss / (float)cols + EPSF);
    for (int c = threadIdx.x; c < cols; c += 256) {
        float y = xr[c] * inv * (1.f + w[c]);
        fp16 h, l; split2h(y, h, l);
        size_t o = (size_t)row * cols + c;
        dst[o] = h; dst[elts + o] = l;
    }
}

__global__ void gelu_sl_split_kernel(const float* __restrict__ g, const float* __restrict__ plc,
                                     int li, fp16* __restrict__ dst, size_t elts) {
    int i = blockIdx.x * 256 + threadIdx.x;
    if (i < N_TOK * HPL) {
        int n = i >> 8, j = i & 255;
        float y = gelu_tanh(g[i]) * plc[(size_t)n * (TOTAL_LAYERS * HPL) + (size_t)li * HPL + j];
        fp16 h, l; split2h(y, h, l);
        dst[i] = h; dst[elts + i] = l;
    }
}

// ======================= driver =======================
extern "C" void kernel_launch(void* const* d_in, const int* in_sizes, int n_in,
                              void* d_out, int out_size) {
    const float* hidden = (const float*)d_in[0];
    const float* plc    = (const float*)d_in[1];
    const float* cos_s  = (const float*)d_in[3];
    const float* sin_s  = (const float*)d_in[4];
    const float* cos_f  = (const float*)d_in[5];
    const float* sin_f  = (const float*)d_in[6];
    const float* Wq     = (const float*)d_in[7];
    const float* Wk     = (const float*)d_in[8];
    const float* Wv     = (const float*)d_in[9];
    const float* Wo     = (const float*)d_in[10];
    const float* Wg     = (const float*)d_in[11];
    const float* Wu     = (const float*)d_in[12];
    const float* Wd     = (const float*)d_in[13];
    const float* Wplg   = (const float*)d_in[14];
    const float* Wplp   = (const float*)d_in[15];
    const float* ln_in  = (const float*)d_in[16];
    const float* ln_pa  = (const float*)d_in[17];
    const float* ln_pf  = (const float*)d_in[18];
    const float* ln_ff  = (const float*)d_in[19];
    const float* ln_pl  = (const float*)d_in[20];
    const float* qn_w   = (const float*)d_in[21];
    const float* kn_w   = (const float*)d_in[22];
    const float* lscale = (const float*)d_in[23];

    cudaFuncSetAttribute(mma_gemm<true,  EPI_F32>,   cudaFuncAttributeMaxDynamicSharedMemorySize, GSMEM64);
    cudaFuncSetAttribute(mma_gemm<false, EPI_SPLIT>, cudaFuncAttributeMaxDynamicSharedMemorySize, GSMEM64);
    cudaFuncSetAttribute(mma_gemm<false, EPI_F32>,   cudaFuncAttributeMaxDynamicSharedMemorySize, GSMEM64);
    cudaFuncSetAttribute(mma_gemm<false, EPI_GELU>,  cudaFuncAttributeMaxDynamicSharedMemorySize, GSMEM64);

    char* scr = nullptr;
    cudaGetSymbolAddress((void**)&scr, g_scr);

    fp16* wqkv3 = (fp16*)(scr + OFF_WQKV);
    fp16* wo3   = (fp16*)(scr + OFF_WO3);
    fp16* wgu3  = (fp16*)(scr + OFF_WGU);
    fp16* wd3   = (fp16*)(scr + OFF_WD3);
    fp16* wplg3 = (fp16*)(scr + OFF_WPLG3);
    fp16* wplp3 = (fp16*)(scr + OFF_WPLP3);

    float* hs     = (float*)(scr + OFF_HS);
    float* qkvraw = (float*)(scr + OFF_QKVRAW);
    float* scores = (float*)(scr + OFF_SC);
    float* tmp    = (float*)(scr + OFF_TMP);
    float* plbuf  = (float*)(scr + OFF_PLB);
    fp16*  h2     = (fp16*)(scr + OFF_H2);
    fp16*  qt3    = (fp16*)(scr + OFF_QT3);
    fp16*  kt3    = (fp16*)(scr + OFF_KT3);
    fp16*  vt3    = (fp16*)(scr + OFF_VT3);
    fp16*  p3     = (fp16*)(scr + OFF_P3);
    fp16*  ao3    = (fp16*)(scr + OFF_AO3);
    fp16*  m2     = (fp16*)(scr + OFF_M2);
    fp16*  hs3    = (fp16*)(scr + OFF_HS3);
    fp16*  pl3    = (fp16*)(scr + OFF_PL3);

    float* out = (float*)d_out;

    // ---- split weights into fused 2-plane layouts ----
    auto wsplit = [&](const float* src, fp16* dst, size_t plane, size_t count) {
        size_t n4 = count / 4;
        wsplit_kernel<<<(unsigned)((n4 + 255) / 256), 256>>>(src, dst, plane, n4);
    };
    auto wsplit_rows = [&](const float* src, fp16* dst, size_t plane, int phase, size_t count) {
        size_t n4 = count / 4;
        wsplit_rows_kernel<<<(unsigned)((n4 + 255) / 256), 256>>>(src, dst, plane, phase, n4);
    };
    for (int i = 0; i < NLAYER; i++) {
        const size_t lq = (size_t)i * 2048 * 2048;
        const size_t lk = (size_t)i * 512 * 2048;
        fp16* dst = wqkv3 + (size_t)i * 3072 * 2048;
        wsplit(Wq + lq, dst,               E_QKV, (size_t)2048 * 2048);
        wsplit(Wk + lk, dst + 2048 * 2048, E_QKV, (size_t)512 * 2048);
        wsplit(Wv + lk, dst + 2560 * 2048, E_QKV, (size_t)512 * 2048);

        // GU: interleave rows (even = Wg row j, odd = Wu row j) for fused GELU epilogue
        const size_t lg = (size_t)i * 4096 * 2048;
        fp16* dgu = wgu3 + (size_t)i * 8192 * 2048;
        wsplit_rows(Wg + lg, dgu, E_GU, 0, (size_t)4096 * 2048);
        wsplit_rows(Wu + lg, dgu, E_GU, 1, (size_t)4096 * 2048);
    }
    wsplit(Wo,   wo3,   E_WO,  E_WO);
    wsplit(Wd,   wd3,   E_WD,  E_WD);
    wsplit(Wplg, wplg3, E_WPL, E_WPL);
    wsplit(Wplp, wplp3, E_WPL, E_WPL);

    cudaMemcpyAsync(hs, hidden, (size_t)N_TOK * DMODEL * sizeof(float), cudaMemcpyDeviceToDevice, 0);

    // initial pre-attention norm (layer 0)
    rmsnorm_split_kernel<<<N_TOK, 256>>>(hs, ln_in, h2, E_H2, DMODEL);

    for (int i = 0; i < NLAYER; i++) {
        const int li = STARTL + i;
        const bool full = ((li + 1) % 5) == 0;
        const float* cost = full ? cos_f : cos_s;
        const float* sint = full ? sin_f : sin_s;
        float* Kout = out + (size_t)N_TOK * DMODEL + (size_t)i * 2 * NKV * N_TOK * HDIM;
        float* Vout = Kout + (size_t)NKV * N_TOK * HDIM;

        // ---- fused QKV + fused norms ----
        mma_gemm<false, EPI_F32><<<dim3(3072 / 64, 8), 256, GSMEM64>>>(
            h2, wqkv3 + (size_t)i * 3072 * 2048, (long long)E_H2, (long long)E_QKV,
            qkvraw, nullptr, 0, DMODEL, 3072, 0, 0, 0, 0, 0);
        qkv_norm_kernel<<<dim3(N_TOK, 12), 256>>>(
            qkvraw, qn_w + (size_t)i * HDIM, kn_w + (size_t)i * HDIM, cost, sint,
            Kout, Vout, qt3, kt3, vt3);

        // ---- attention: causal scores, softmax, PV (split epilogue + k-cap) ----
        mma_gemm<true, EPI_F32><<<dim3(N_TOK / 64, N_TOK / 128, NH), 256, GSMEM64>>>(
            qt3, kt3, (long long)E_QT, (long long)E_KT, scores, nullptr, 0, HDIM, N_TOK,
            (long long)N_TOK * HDIM, (long long)N_TOK * HDIM, (long long)N_TOK * N_TOK, 2, 0);
        softmax_causal_split_kernel<<<NH * N_TOK, 256>>>(scores, p3, E_P3);
        mma_gemm<false, EPI_SPLIT><<<dim3(HDIM / 64, N_TOK / 128, NH), 256, GSMEM64>>>(
            p3, vt3, (long long)E_P3, (long long)E_KT, nullptr, ao3, (long long)E_AO,
            N_TOK, NH * HDIM,
            (long long)N_TOK * N_TOK, (long long)HDIM * N_TOK, (long long)HDIM, 2, 4);

        // ---- Wo + fused residual + pre-FFN norm ----
        mma_gemm<false, EPI_F32><<<dim3(DMODEL / 64, 8), 256, GSMEM64>>>(
            ao3, wo3 + (size_t)i * 2048 * 2048, (long long)E_AO, (long long)E_WO,
            tmp, nullptr, 0, NH * HDIM, DMODEL, 0, 0, 0, 0, 0);
        add_rms_norm_kernel<<<N_TOK, 256>>>(hs, tmp, ln_pa + (size_t)i * DMODEL, nullptr,
                                            ln_pf + (size_t)i * DMODEL, h2, E_H2);

        // ---- FFN: fused G+U with GELU epilogue -> m2, then Wd + residual ----
        mma_gemm<false, EPI_GELU><<<dim3(8192 / 64, 8), 256, GSMEM64>>>(
            h2, wgu3 + (size_t)i * 8192 * 2048, (long long)E_H2, (long long)E_GU,
            nullptr, m2, (long long)E_M2, DMODEL, FFDIM, 0, 0, 0, 0, 0);
        mma_gemm<false, EPI_F32><<<dim3(DMODEL / 64, 8), 256, GSMEM64>>>(
            m2, wd3 + (size_t)i * 2048 * 4096, (long long)E_M2, (long long)E_WD,
            tmp, nullptr, 0, FFDIM, DMODEL, 0, 0, 0, 0, 0);
        add_rms_kernel<<<N_TOK, 256>>>(hs, tmp, ln_ff + (size_t)i * DMODEL, nullptr,
                                       hs3, E_H2, DMODEL);

        // ---- per-layer gating + fused residual + next norm ----
        mma_gemm<false, EPI_F32><<<dim3(HPL / 64, 8), 256, GSMEM64>>>(
            hs3, wplg3 + (size_t)i * HPL * 2048, (long long)E_H2, (long long)E_WPL,
            plbuf, nullptr, 0, DMODEL, HPL, 0, 0, 0, 0, 0);
        gelu_sl_split_kernel<<<(N_TOK * HPL + 255) / 256, 256>>>(plbuf, plc, li, pl3, E_PL);
        mma_gemm<false, EPI_F32><<<dim3(DMODEL / 64, 8), 256, GSMEM64>>>(
            pl3, wplp3 + (size_t)i * 2048 * HPL, (long long)E_PL, (long long)E_WPL,
            tmp, nullptr, 0, HPL, DMODEL, 0, 0, 0, 0, 0);
        if (i + 1 < NLAYER) {
            add_rms_norm_kernel<<<N_TOK, 256>>>(hs, tmp, ln_pl + (size_t)i * DMODEL, lscale + i,
                                                ln_in + (size_t)(i + 1) * DMODEL, h2, E_H2);
        } else {
            add_rms_kernel<<<N_TOK, 256>>>(hs, tmp, ln_pl + (size_t)i * DMODEL, lscale + i,
                                           nullptr, 0, DMODEL);
        }
    }

    cudaMemcpyAsync(out, hs, (size_t)N_TOK * DMODEL * sizeof(float), cudaMemcpyDeviceToDevice, 0);
}